// round 5
// baseline (speedup 1.0000x reference)
#include <cuda_runtime.h>
#include <cuda_bf16.h>
#include <math.h>

typedef unsigned int u32;
typedef __nv_bfloat16 bf16;

#define SS 1024
#define HH 16
#define HDD 64
#define NBH 32

// ---------------- scratch (device globals) ----------------
__device__ bf16 g_xhi[2048*1024], g_xlo[2048*1024];
__device__ bf16 g_whi[3*1024*1024], g_wlo[3*1024*1024];
__device__ bf16 g_dehi[2047*64];
__device__ bf16 g_qhi[NBH*SS*HDD], g_qlo[NBH*SS*HDD];
__device__ bf16 g_khi[NBH*SS*HDD], g_klo[NBH*SS*HDD];
__device__ bf16 g_vhi[NBH*SS*HDD], g_vlo[NBH*SS*HDD];
__device__ bf16 g_phi[(size_t)NBH*SS*SS], g_plo[(size_t)NBH*SS*SS];
__device__ float g_sc[(size_t)NBH*SS*SS];

// ---------------- helpers ----------------
__device__ __forceinline__ u32 sptr(const void* p){ return (u32)__cvta_generic_to_shared(p); }
__device__ __forceinline__ void ldsm4(u32& r0,u32& r1,u32& r2,u32& r3,u32 a){
    asm volatile("ldmatrix.sync.aligned.m8n8.x4.shared.b16 {%0,%1,%2,%3},[%4];"
                 :"=r"(r0),"=r"(r1),"=r"(r2),"=r"(r3):"r"(a));
}
__device__ __forceinline__ void ldsm4t(u32& r0,u32& r1,u32& r2,u32& r3,u32 a){
    asm volatile("ldmatrix.sync.aligned.m8n8.x4.trans.shared.b16 {%0,%1,%2,%3},[%4];"
                 :"=r"(r0),"=r"(r1),"=r"(r2),"=r"(r3):"r"(a));
}
__device__ __forceinline__ void mma16816(float (&c)[4], const u32 (&a)[4], u32 b0, u32 b1){
    asm volatile("mma.sync.aligned.m16n8k16.row.col.f32.bf16.bf16.f32 "
                 "{%0,%1,%2,%3},{%4,%5,%6,%7},{%8,%9},{%0,%1,%2,%3};"
                 :"+f"(c[0]),"+f"(c[1]),"+f"(c[2]),"+f"(c[3])
                 :"r"(a[0]),"r"(a[1]),"r"(a[2]),"r"(a[3]),"r"(b0),"r"(b1));
}
__device__ __forceinline__ void split2(float v, bf16& h, bf16& l){
    h = __float2bfloat16_rn(v);
    l = __float2bfloat16_rn(v - __bfloat162float(h));
}
__device__ __forceinline__ u32 pack2hi(float a, float b){
    __nv_bfloat162 t; t.x=__float2bfloat16_rn(a); t.y=__float2bfloat16_rn(b);
    return *(u32*)&t;
}
__device__ __forceinline__ u32 pack2lo(float a, float b){
    float ah = __bfloat162float(__float2bfloat16_rn(a));
    float bh = __bfloat162float(__float2bfloat16_rn(b));
    __nv_bfloat162 t; t.x=__float2bfloat16_rn(a-ah); t.y=__float2bfloat16_rn(b-bh);
    return *(u32*)&t;
}

// ============================================================================
// K0: fp32 -> bf16 (hi,lo) splits, all 5 tensors in ONE launch.
// ranges: X[0,524288) Wq Wk Wv (+262144 each) de[last 32752, hi only]
// ============================================================================
__global__ __launch_bounds__(256)
void cvt_kernel(const float* __restrict__ X, const float* __restrict__ Wq,
                const float* __restrict__ Wk, const float* __restrict__ Wv,
                const float* __restrict__ de)
{
    int i = blockIdx.x * 256 + threadIdx.x;
    const float* src; bf16 *hi, *lo = nullptr; int off;
    if (i < 524288)       { src = X;  hi = g_xhi; lo = g_xlo; off = i; }
    else if (i < 786432)  { src = Wq; hi = g_whi;            lo = g_wlo;            off = i - 524288; }
    else if (i < 1048576) { src = Wk; hi = g_whi + 1048576;  lo = g_wlo + 1048576;  off = i - 786432; }
    else if (i < 1310720) { src = Wv; hi = g_whi + 2097152;  lo = g_wlo + 2097152;  off = i - 1048576; }
    else if (i < 1343472) { src = de; hi = g_dehi;                                   off = i - 1310720; }
    else return;

    float4 v = *(const float4*)(src + (size_t)off * 4);
    float vv[4] = {v.x, v.y, v.z, v.w};
    bf16 h[4], l[4];
#pragma unroll
    for (int j = 0; j < 4; j++) split2(vv[j], h[j], l[j]);
    __nv_bfloat162 h0; h0.x=h[0]; h0.y=h[1];
    __nv_bfloat162 h1; h1.x=h[2]; h1.y=h[3];
    *(uint2*)(hi + (size_t)off*4) = make_uint2(*(u32*)&h0, *(u32*)&h1);
    if (lo) {
        __nv_bfloat162 l0; l0.x=l[0]; l0.y=l[1];
        __nv_bfloat162 l1; l1.x=l[2]; l1.y=l[3];
        *(uint2*)(lo + (size_t)off*4) = make_uint2(*(u32*)&l0, *(u32*)&l1);
    }
}

// ============================================================================
// K1: q/k/v = X @ W^T + b (bf16 x3 mma), hi/lo out in [B,H,S,HD].
// CTA 128m x 128n, BK=32, 8 warps (2m x 4n), warp 64x32.
// ============================================================================
__global__ __launch_bounds__(256)
void qkv_mma(const float* __restrict__ bq, const float* __restrict__ bk,
             const float* __restrict__ bv)
{
    __shared__ __align__(16) bf16 sA[2][128*40];
    __shared__ __align__(16) bf16 sB[2][128*40];

    const int tid = threadIdx.x, wid = tid>>5, lane = tid&31;
    const int warpM = wid>>2, warpN = wid&3;
    const int z = blockIdx.z, n0 = blockIdx.x*128, m0 = blockIdx.y*128;
    const int lr = lane&15, lc8 = (lane>>4)*8, g = lane>>2, t = lane&3;

    const bf16* Bh = g_whi + (size_t)z*1048576;
    const bf16* Bl = g_wlo + (size_t)z*1048576;
    const float* bias = (z==0)?bq:(z==1)?bk:bv;
    bf16* dhi = (z==0)?g_qhi:(z==1)?g_khi:g_vhi;
    bf16* dlo = (z==0)?g_qlo:(z==1)?g_klo:g_vlo;

    float acc[4][4][4];
#pragma unroll
    for (int i=0;i<4;i++)
#pragma unroll
        for (int j=0;j<4;j++)
#pragma unroll
            for (int c=0;c<4;c++) acc[i][j][c]=0.f;

    for (int k0 = 0; k0 < 1024; k0 += 32) {
#pragma unroll
        for (int rep=0;rep<2;rep++){
            int idx = rep*256+tid, r = idx>>2, s = idx&3;
            *(uint4*)&sA[0][r*40+s*8] = *(const uint4*)&g_xhi[(size_t)(m0+r)*1024 + k0 + s*8];
            *(uint4*)&sA[1][r*40+s*8] = *(const uint4*)&g_xlo[(size_t)(m0+r)*1024 + k0 + s*8];
            *(uint4*)&sB[0][r*40+s*8] = *(const uint4*)&Bh[(size_t)(n0+r)*1024 + k0 + s*8];
            *(uint4*)&sB[1][r*40+s*8] = *(const uint4*)&Bl[(size_t)(n0+r)*1024 + k0 + s*8];
        }
        __syncthreads();
#pragma unroll
        for (int kb=0;kb<32;kb+=16){
            u32 ah[4][4], al[4][4], bhr[4][2], blr[4][2];
#pragma unroll
            for (int mt=0;mt<4;mt++){
                ldsm4(ah[mt][0],ah[mt][1],ah[mt][2],ah[mt][3],
                      sptr(&sA[0][(warpM*64+mt*16+lr)*40 + kb + lc8]));
                ldsm4(al[mt][0],al[mt][1],al[mt][2],al[mt][3],
                      sptr(&sA[1][(warpM*64+mt*16+lr)*40 + kb + lc8]));
            }
#pragma unroll
            for (int gg=0;gg<2;gg++){
                u32 r0,r1,r2,r3;
                ldsm4(r0,r1,r2,r3, sptr(&sB[0][(warpN*32+gg*16+lr)*40 + kb + lc8]));
                bhr[2*gg][0]=r0; bhr[2*gg][1]=r2; bhr[2*gg+1][0]=r1; bhr[2*gg+1][1]=r3;
                ldsm4(r0,r1,r2,r3, sptr(&sB[1][(warpN*32+gg*16+lr)*40 + kb + lc8]));
                blr[2*gg][0]=r0; blr[2*gg][1]=r2; blr[2*gg+1][0]=r1; blr[2*gg+1][1]=r3;
            }
#pragma unroll
            for (int mt=0;mt<4;mt++)
#pragma unroll
                for (int nt=0;nt<4;nt++){
                    mma16816(acc[mt][nt], ah[mt], bhr[nt][0], bhr[nt][1]);
                    mma16816(acc[mt][nt], ah[mt], blr[nt][0], blr[nt][1]);
                    mma16816(acc[mt][nt], al[mt], bhr[nt][0], bhr[nt][1]);
                }
        }
        __syncthreads();
    }

#pragma unroll
    for (int mt=0;mt<4;mt++)
#pragma unroll
        for (int nt=0;nt<4;nt++){
            int ncol = n0 + warpN*32 + nt*8 + 2*t;
            float b0 = bias[ncol], b1 = bias[ncol+1];
            int h = ncol>>6, dd = ncol&63;
#pragma unroll
            for (int rr=0;rr<2;rr++){
                int m = m0 + warpM*64 + mt*16 + g + rr*8;
                int b_ = m>>10, l = m&1023;
                float v0 = acc[mt][nt][rr*2+0] + b0;
                float v1 = acc[mt][nt][rr*2+1] + b1;
                size_t o = (((size_t)(b_*HH + h))*SS + l)*HDD + dd;
                *(u32*)&dhi[o] = pack2hi(v0, v1);
                *(u32*)&dlo[o] = pack2lo(v0, v1);
            }
        }
}

// ============================================================================
// K2: scores = (q k^T)[x3] + Toeplitz(Q DE^T)[x1], *0.125 + mask -> f32
// (unchanged, known good)
// ============================================================================
__global__ __launch_bounds__(256)
void scores_mma(const float* __restrict__ mask)
{
    __shared__ __align__(16) char sm[49152];
    bf16*  sQh = (bf16*)sm;
    bf16*  sQl = (bf16*)(sm+10240);
    bf16*  sKh = (bf16*)(sm+20480);
    bf16*  sKl = (bf16*)(sm+30720);
    bf16*  sDE = (bf16*)(sm+10240);
    float* sT  = (float*)(sm+15360);

    const int tid = threadIdx.x, wid = tid>>5, lane = tid&31;
    const int warpM = wid>>2, warpN = wid&3;
    const int bh = blockIdx.z, l0 = blockIdx.y*128, r0 = blockIdx.x*128;
    const int b_ = bh>>4;
    const int jb = l0 - r0 + 896;
    const int lr = lane&15, lc8 = (lane>>4)*8, g = lane>>2, t = lane&3;

    const bf16* qh = g_qhi + (size_t)bh*SS*HDD;
    const bf16* ql = g_qlo + (size_t)bh*SS*HDD;
    const bf16* kh = g_khi + (size_t)bh*SS*HDD;
    const bf16* kl = g_klo + (size_t)bh*SS*HDD;

    float acc[4][4][4];
#pragma unroll
    for (int i=0;i<4;i++)
#pragma unroll
        for (int j=0;j<4;j++)
#pragma unroll
            for (int c=0;c<4;c++) acc[i][j][c]=0.f;

    for (int kc=0;kc<2;kc++){
        int k0 = kc*32;
        __syncthreads();
#pragma unroll
        for (int rep=0;rep<2;rep++){
            int idx = rep*256+tid, r = idx>>2, s = idx&3;
            *(uint4*)&sQh[r*40+s*8] = *(const uint4*)&qh[(size_t)(l0+r)*64 + k0 + s*8];
            *(uint4*)&sQl[r*40+s*8] = *(const uint4*)&ql[(size_t)(l0+r)*64 + k0 + s*8];
            *(uint4*)&sKh[r*40+s*8] = *(const uint4*)&kh[(size_t)(r0+r)*64 + k0 + s*8];
            *(uint4*)&sKl[r*40+s*8] = *(const uint4*)&kl[(size_t)(r0+r)*64 + k0 + s*8];
        }
        __syncthreads();
#pragma unroll
        for (int kb=0;kb<32;kb+=16){
            u32 ah[4][4], al[4][4], bhr[4][2], blr[4][2];
#pragma unroll
            for (int mt=0;mt<4;mt++){
                ldsm4(ah[mt][0],ah[mt][1],ah[mt][2],ah[mt][3],
                      sptr(&sQh[(warpM*64+mt*16+lr)*40 + kb + lc8]));
                ldsm4(al[mt][0],al[mt][1],al[mt][2],al[mt][3],
                      sptr(&sQl[(warpM*64+mt*16+lr)*40 + kb + lc8]));
            }
#pragma unroll
            for (int gg=0;gg<2;gg++){
                u32 r0r,r1r,r2r,r3r;
                ldsm4(r0r,r1r,r2r,r3r, sptr(&sKh[(warpN*32+gg*16+lr)*40 + kb + lc8]));
                bhr[2*gg][0]=r0r; bhr[2*gg][1]=r2r; bhr[2*gg+1][0]=r1r; bhr[2*gg+1][1]=r3r;
                ldsm4(r0r,r1r,r2r,r3r, sptr(&sKl[(warpN*32+gg*16+lr)*40 + kb + lc8]));
                blr[2*gg][0]=r0r; blr[2*gg][1]=r2r; blr[2*gg+1][0]=r1r; blr[2*gg+1][1]=r3r;
            }
#pragma unroll
            for (int mt=0;mt<4;mt++)
#pragma unroll
                for (int nt=0;nt<4;nt++){
                    mma16816(acc[mt][nt], ah[mt], bhr[nt][0], bhr[nt][1]);
                    mma16816(acc[mt][nt], ah[mt], blr[nt][0], blr[nt][1]);
                    mma16816(acc[mt][nt], al[mt], bhr[nt][0], bhr[nt][1]);
                }
        }
    }

    for (int c=0;c<4;c++){
        int t0c = 64*c;
        float Tacc[4][2][4];
#pragma unroll
        for (int i=0;i<4;i++)
#pragma unroll
            for (int j=0;j<2;j++)
#pragma unroll
                for (int q=0;q<4;q++) Tacc[i][j][q]=0.f;
        for (int kc=0;kc<2;kc++){
            int k0 = kc*32;
            __syncthreads();
#pragma unroll
            for (int rep=0;rep<2;rep++){
                int idx = rep*256+tid, r = idx>>2, s = idx&3;
                *(uint4*)&sQh[r*40+s*8] = *(const uint4*)&qh[(size_t)(l0+r)*64 + k0 + s*8];
            }
            { int r = tid>>2, s = tid&3;
              int der = jb + t0c + r; if (der > 2046) der = 2046;
              *(uint4*)&sDE[r*40+s*8] = *(const uint4*)&g_dehi[(size_t)der*64 + k0 + s*8]; }
            __syncthreads();
#pragma unroll
            for (int kb=0;kb<32;kb+=16){
                u32 ah[4][4];
#pragma unroll
                for (int mt=0;mt<4;mt++)
                    ldsm4(ah[mt][0],ah[mt][1],ah[mt][2],ah[mt][3],
                          sptr(&sQh[(warpM*64+mt*16+lr)*40 + kb + lc8]));
                u32 r0r,r1r,r2r,r3r;
                ldsm4(r0r,r1r,r2r,r3r, sptr(&sDE[(warpN*16+lr)*40 + kb + lc8]));
#pragma unroll
                for (int mt=0;mt<4;mt++){
                    mma16816(Tacc[mt][0], ah[mt], r0r, r2r);
                    mma16816(Tacc[mt][1], ah[mt], r1r, r3r);
                }
            }
        }
        __syncthreads();
#pragma unroll
        for (int mt=0;mt<4;mt++)
#pragma unroll
            for (int n2=0;n2<2;n2++){
                int col = warpN*16 + n2*8 + 2*t;
                int rw = warpM*64 + mt*16 + g;
                *(float2*)&sT[rw*66 + col]     = make_float2(Tacc[mt][n2][0], Tacc[mt][n2][1]);
                *(float2*)&sT[(rw+8)*66 + col] = make_float2(Tacc[mt][n2][2], Tacc[mt][n2][3]);
            }
        __syncthreads();
#pragma unroll
        for (int mt=0;mt<4;mt++){
            int ib = warpM*64 + mt*16 + g;
#pragma unroll
            for (int nt=0;nt<4;nt++){
                int jb0 = warpN*32 + nt*8 + 2*t;
#pragma unroll
                for (int cr=0;cr<4;cr++){
                    int i = ib + (cr>>1)*8, j = jb0 + (cr&1);
                    int tt = i - j + 127 - t0c;
                    if ((unsigned)tt < 64u) acc[mt][nt][cr] += sT[i*66 + tt];
                }
            }
        }
        __syncthreads();
    }

    float* outp = g_sc + (size_t)bh*SS*SS;
#pragma unroll
    for (int mt=0;mt<4;mt++){
        int i0 = l0 + warpM*64 + mt*16 + g;
#pragma unroll
        for (int nt=0;nt<4;nt++){
            int jc = r0 + warpN*32 + nt*8 + 2*t;
            float2 mk = *(const float2*)&mask[b_*SS + jc];
            *(float2*)&outp[(size_t)i0*SS + jc] =
                make_float2(fmaf(acc[mt][nt][0],0.125f,mk.x), fmaf(acc[mt][nt][1],0.125f,mk.y));
            *(float2*)&outp[(size_t)(i0+8)*SS + jc] =
                make_float2(fmaf(acc[mt][nt][2],0.125f,mk.x), fmaf(acc[mt][nt][3],0.125f,mk.y));
        }
    }
}

// ============================================================================
// K3: stochastic double softmax, WARP-PER-ROW (no block barriers).
// 8 warps/CTA = 8 rows; 32 elems/lane; 3 shuffle reductions.
// ============================================================================
__global__ __launch_bounds__(256)
void softmax_warp(const float* __restrict__ gum)
{
    const int tid = threadIdx.x, lane = tid & 31, w = tid >> 5;
    const size_t row = (size_t)blockIdx.x * 8 + w;      // 32768 rows
    const float* srow = g_sc + row * SS;
    const float* urow = gum + row * SS;

    float s[32], n[32];
#pragma unroll
    for (int j = 0; j < 8; j++) {
        float4 v = *(const float4*)&srow[(j*32 + lane)*4];
        s[j*4+0]=v.x; s[j*4+1]=v.y; s[j*4+2]=v.z; s[j*4+3]=v.w;
        float4 u = *(const float4*)&urow[(j*32 + lane)*4];
        n[j*4+0] = 1e-10f - logf(u.x + 1e-10f);
        n[j*4+1] = 1e-10f - logf(u.y + 1e-10f);
        n[j*4+2] = 1e-10f - logf(u.z + 1e-10f);
        n[j*4+3] = 1e-10f - logf(u.w + 1e-10f);
    }
    float m = s[0];
#pragma unroll
    for (int i = 1; i < 32; i++) m = fmaxf(m, s[i]);
#pragma unroll
    for (int o = 16; o; o >>= 1) m = fmaxf(m, __shfl_xor_sync(0xffffffffu, m, o));

    float sm1 = 0.f;
#pragma unroll
    for (int i = 0; i < 32; i++) {
        s[i] = __expf(s[i] - m);
        n[i] = __fdividef(s[i], n[i]);
        sm1 += n[i];
    }
#pragma unroll
    for (int o = 16; o; o >>= 1) sm1 += __shfl_xor_sync(0xffffffffu, sm1, o);
    float inv1 = __fdividef(1.0f, sm1);

    float sm2 = 0.f;
#pragma unroll
    for (int i = 0; i < 32; i++) {
        n[i] = s[i] * __expf(fmaf(n[i], inv1, -1.0f));
        sm2 += n[i];
    }
#pragma unroll
    for (int o = 16; o; o >>= 1) sm2 += __shfl_xor_sync(0xffffffffu, sm2, o);
    float inv2 = __fdividef(1.0f, sm2);

#pragma unroll
    for (int j = 0; j < 8; j++) {
        float a = n[j*4+0]*inv2, b = n[j*4+1]*inv2, c = n[j*4+2]*inv2, d = n[j*4+3]*inv2;
        size_t o = row*SS + (j*32 + lane)*4;
        *(uint2*)&g_phi[o] = make_uint2(pack2hi(a,b), pack2hi(c,d));
        *(uint2*)&g_plo[o] = make_uint2(pack2lo(a,b), pack2lo(c,d));
    }
}

// ============================================================================
// K4: out = P @ V (bf16 x3 mma) — unchanged, known good.
// ============================================================================
__global__ __launch_bounds__(256)
void pv_mma(float* __restrict__ out)
{
    __shared__ __align__(16) bf16 sP[2][128*40];
    __shared__ __align__(16) bf16 sV[2][32*72];

    const int tid = threadIdx.x, wid = tid>>5, lane = tid&31;
    const int warpM = wid>>1, warpN = wid&1;
    const int bh = blockIdx.y, l0 = blockIdx.x*128;
    const int b_ = bh>>4, h = bh&15;
    const int lr = lane&15, lc8 = (lane>>4)*8, g = lane>>2, t = lane&3;

    const bf16* Ph = g_phi + (size_t)bh*SS*SS;
    const bf16* Pl = g_plo + (size_t)bh*SS*SS;
    const bf16* Vh = g_vhi + (size_t)bh*SS*HDD;
    const bf16* Vl = g_vlo + (size_t)bh*SS*HDD;

    float acc[2][4][4];
#pragma unroll
    for (int i=0;i<2;i++)
#pragma unroll
        for (int j=0;j<4;j++)
#pragma unroll
            for (int c=0;c<4;c++) acc[i][j][c]=0.f;

    for (int k0 = 0; k0 < 1024; k0 += 32) {
#pragma unroll
        for (int rep=0;rep<2;rep++){
            int idx = rep*256+tid, r = idx>>2, s = idx&3;
            *(uint4*)&sP[0][r*40+s*8] = *(const uint4*)&Ph[(size_t)(l0+r)*1024 + k0 + s*8];
            *(uint4*)&sP[1][r*40+s*8] = *(const uint4*)&Pl[(size_t)(l0+r)*1024 + k0 + s*8];
        }
        { int r = tid>>3, s = tid&7;
          *(uint4*)&sV[0][r*72+s*8] = *(const uint4*)&Vh[(size_t)(k0+r)*64 + s*8];
          *(uint4*)&sV[1][r*72+s*8] = *(const uint4*)&Vl[(size_t)(k0+r)*64 + s*8]; }
        __syncthreads();
#pragma unroll
        for (int kb=0;kb<32;kb+=16){
            u32 ah[2][4], al[2][4], bhr[4][2], blr[4][2];
#pragma unroll
            for (int mt=0;mt<2;mt++){
                ldsm4(ah[mt][0],ah[mt][1],ah[mt][2],ah[mt][3],
                      sptr(&sP[0][(warpM*32+mt*16+lr)*40 + kb + lc8]));
                ldsm4(al[mt][0],al[mt][1],al[mt][2],al[mt][3],
                      sptr(&sP[1][(warpM*32+mt*16+lr)*40 + kb + lc8]));
            }
#pragma unroll
            for (int gg=0;gg<2;gg++){
                u32 r0,r1,r2,r3;
                ldsm4t(r0,r1,r2,r3, sptr(&sV[0][(kb+lr)*72 + warpN*32 + gg*16 + lc8]));
                bhr[2*gg][0]=r0; bhr[2*gg][1]=r1; bhr[2*gg+1][0]=r2; bhr[2*gg+1][1]=r3;
                ldsm4t(r0,r1,r2,r3, sptr(&sV[1][(kb+lr)*72 + warpN*32 + gg*16 + lc8]));
                blr[2*gg][0]=r0; blr[2*gg][1]=r1; blr[2*gg+1][0]=r2; blr[2*gg+1][1]=r3;
            }
#pragma unroll
            for (int mt=0;mt<2;mt++)
#pragma unroll
                for (int nt=0;nt<4;nt++){
                    mma16816(acc[mt][nt], ah[mt], bhr[nt][0], bhr[nt][1]);
                    mma16816(acc[mt][nt], ah[mt], blr[nt][0], blr[nt][1]);
                    mma16816(acc[mt][nt], al[mt], bhr[nt][0], bhr[nt][1]);
                }
        }
        __syncthreads();
    }

#pragma unroll
    for (int mt=0;mt<2;mt++)
#pragma unroll
        for (int nt=0;nt<4;nt++){
            int dcol = warpN*32 + nt*8 + 2*t;
#pragma unroll
            for (int rr=0;rr<2;rr++){
                int l = l0 + warpM*32 + mt*16 + g + rr*8;
                *(float2*)&out[((size_t)(b_*SS)+l)*1024 + h*64 + dcol] =
                    make_float2(acc[mt][nt][rr*2+0], acc[mt][nt][rr*2+1]);
            }
        }
}

// ============================================================================
extern "C" void kernel_launch(void* const* d_in, const int* in_sizes, int n_in,
                              void* d_out, int out_size)
{
    const float* hidden = (const float*)d_in[0];
    const float* mask   = (const float*)d_in[1];
    const float* gum    = (const float*)d_in[2];
    const float* Wq     = (const float*)d_in[3];
    const float* bq     = (const float*)d_in[4];
    const float* Wk     = (const float*)d_in[5];
    const float* bk     = (const float*)d_in[6];
    const float* Wv     = (const float*)d_in[7];
    const float* bv     = (const float*)d_in[8];
    const float* de     = (const float*)d_in[9];
    float* out = (float*)d_out;

    cvt_kernel<<<5249, 256>>>(hidden, Wq, Wk, Wv, de);
    qkv_mma<<<dim3(8, 16, 3), 256>>>(bq, bk, bv);
    scores_mma<<<dim3(8, 8, 32), 256>>>(mask);
    softmax_warp<<<4096, 256>>>(gum);
    pv_mma<<<dim3(8, 32), 256>>>(out);
}

// round 6
// speedup vs baseline: 1.1848x; 1.1848x over previous
#include <cuda_runtime.h>
#include <cuda_bf16.h>
#include <math.h>

typedef unsigned int u32;
typedef __nv_bfloat16 bf16;

#define SS 1024
#define HH 16
#define HDD 64
#define NBH 32

// ---------------- scratch (device globals) ----------------
__device__ bf16 g_xhi[2048*1024], g_xlo[2048*1024];
__device__ bf16 g_whi[3*1024*1024], g_wlo[3*1024*1024];
__device__ bf16 g_dehi[2047*64];
__device__ bf16 g_qhi[NBH*SS*HDD], g_qlo[NBH*SS*HDD];
__device__ bf16 g_khi[NBH*SS*HDD], g_klo[NBH*SS*HDD];
__device__ bf16 g_vhi[NBH*SS*HDD], g_vlo[NBH*SS*HDD];
__device__ bf16 g_phi[(size_t)NBH*SS*SS], g_plo[(size_t)NBH*SS*SS];
__device__ float g_sc[(size_t)NBH*SS*SS];

// ---------------- helpers ----------------
__device__ __forceinline__ u32 sptr(const void* p){ return (u32)__cvta_generic_to_shared(p); }
__device__ __forceinline__ void ldsm4(u32& r0,u32& r1,u32& r2,u32& r3,u32 a){
    asm volatile("ldmatrix.sync.aligned.m8n8.x4.shared.b16 {%0,%1,%2,%3},[%4];"
                 :"=r"(r0),"=r"(r1),"=r"(r2),"=r"(r3):"r"(a));
}
__device__ __forceinline__ void ldsm4t(u32& r0,u32& r1,u32& r2,u32& r3,u32 a){
    asm volatile("ldmatrix.sync.aligned.m8n8.x4.trans.shared.b16 {%0,%1,%2,%3},[%4];"
                 :"=r"(r0),"=r"(r1),"=r"(r2),"=r"(r3):"r"(a));
}
__device__ __forceinline__ void mma16816(float (&c)[4], const u32 (&a)[4], u32 b0, u32 b1){
    asm volatile("mma.sync.aligned.m16n8k16.row.col.f32.bf16.bf16.f32 "
                 "{%0,%1,%2,%3},{%4,%5,%6,%7},{%8,%9},{%0,%1,%2,%3};"
                 :"+f"(c[0]),"+f"(c[1]),"+f"(c[2]),"+f"(c[3])
                 :"r"(a[0]),"r"(a[1]),"r"(a[2]),"r"(a[3]),"r"(b0),"r"(b1));
}
__device__ __forceinline__ void split2(float v, bf16& h, bf16& l){
    h = __float2bfloat16_rn(v);
    l = __float2bfloat16_rn(v - __bfloat162float(h));
}
__device__ __forceinline__ u32 pack2hi(float a, float b){
    __nv_bfloat162 t; t.x=__float2bfloat16_rn(a); t.y=__float2bfloat16_rn(b);
    return *(u32*)&t;
}
__device__ __forceinline__ u32 pack2lo(float a, float b){
    float ah = __bfloat162float(__float2bfloat16_rn(a));
    float bh = __bfloat162float(__float2bfloat16_rn(b));
    __nv_bfloat162 t; t.x=__float2bfloat16_rn(a-ah); t.y=__float2bfloat16_rn(b-bh);
    return *(u32*)&t;
}

#define CP16(dst, src) \
    asm volatile("cp.async.cg.shared.global [%0], [%1], 16;" :: "r"(dst), "l"(src))
#define CP_COMMIT() asm volatile("cp.async.commit_group;" ::: "memory")
#define CP_WAIT(n)  asm volatile("cp.async.wait_group %0;" :: "n"(n) : "memory")

// ============================================================================
// K0: fp32 -> bf16 (hi,lo) splits, all 5 tensors in ONE launch.
// ============================================================================
__global__ __launch_bounds__(256)
void cvt_kernel(const float* __restrict__ X, const float* __restrict__ Wq,
                const float* __restrict__ Wk, const float* __restrict__ Wv,
                const float* __restrict__ de)
{
    int i = blockIdx.x * 256 + threadIdx.x;
    const float* src; bf16 *hi, *lo = nullptr; int off;
    if (i < 524288)       { src = X;  hi = g_xhi; lo = g_xlo; off = i; }
    else if (i < 786432)  { src = Wq; hi = g_whi;            lo = g_wlo;            off = i - 524288; }
    else if (i < 1048576) { src = Wk; hi = g_whi + 1048576;  lo = g_wlo + 1048576;  off = i - 786432; }
    else if (i < 1310720) { src = Wv; hi = g_whi + 2097152;  lo = g_wlo + 2097152;  off = i - 1048576; }
    else if (i < 1343472) { src = de; hi = g_dehi;                                   off = i - 1310720; }
    else return;

    float4 v = *(const float4*)(src + (size_t)off * 4);
    float vv[4] = {v.x, v.y, v.z, v.w};
    bf16 h[4], l[4];
#pragma unroll
    for (int j = 0; j < 4; j++) split2(vv[j], h[j], l[j]);
    __nv_bfloat162 h0; h0.x=h[0]; h0.y=h[1];
    __nv_bfloat162 h1; h1.x=h[2]; h1.y=h[3];
    *(uint2*)(hi + (size_t)off*4) = make_uint2(*(u32*)&h0, *(u32*)&h1);
    if (lo) {
        __nv_bfloat162 l0; l0.x=l[0]; l0.y=l[1];
        __nv_bfloat162 l1; l1.x=l[2]; l1.y=l[3];
        *(uint2*)(lo + (size_t)off*4) = make_uint2(*(u32*)&l0, *(u32*)&l1);
    }
}

// ============================================================================
// K1: q/k/v = X @ W^T + b (bf16 x3 mma), cp.async 2-stage pipeline.
// CTA 128m x 128n, BK=32, 8 warps (2m x 4n).
// stage layout (40960B/stage): Ahi(10240) Alo Bhi Blo, row stride 80B.
// ============================================================================
#define QKV_SMEM (2*40960)
__global__ __launch_bounds__(256)
void qkv_mma(const float* __restrict__ bq, const float* __restrict__ bk,
             const float* __restrict__ bv)
{
    extern __shared__ __align__(16) char smem[];
    const u32 sb = sptr(smem);

    const int tid = threadIdx.x, wid = tid>>5, lane = tid&31;
    const int warpM = wid>>2, warpN = wid&3;
    const int z = blockIdx.z, n0 = blockIdx.x*128, m0 = blockIdx.y*128;
    const int lr = lane&15, lc8 = (lane>>4)*8, g = lane>>2, t = lane&3;

    const bf16* Bh = g_whi + (size_t)z*1048576;
    const bf16* Bl = g_wlo + (size_t)z*1048576;
    const float* bias = (z==0)?bq:(z==1)?bk:bv;
    bf16* dhi = (z==0)?g_qhi:(z==1)?g_khi:g_vhi;
    bf16* dlo = (z==0)?g_qlo:(z==1)?g_klo:g_vlo;

    // per-thread load mapping (8 x cp.async of 16B per stage)
    const int lmat = tid >> 6;           // reuse over rep: idx = rep*256+tid
    float acc[4][4][4];
#pragma unroll
    for (int i=0;i<4;i++)
#pragma unroll
        for (int j=0;j<4;j++)
#pragma unroll
            for (int c=0;c<4;c++) acc[i][j][c]=0.f;
    (void)lmat;

    auto load_stage = [&](int st, int k0){
        const u32 base = sb + st*40960;
#pragma unroll
        for (int rep=0;rep<8;rep++){
            int idx = rep*256 + tid;
            int mat = idx >> 9, rem = idx & 511;
            int row = rem >> 2, s4 = rem & 3;
            u32 dst = base + mat*10240 + row*80 + s4*16;
            const bf16* srcp =
                (mat==0) ? &g_xhi[(size_t)(m0+row)*1024 + k0 + s4*8] :
                (mat==1) ? &g_xlo[(size_t)(m0+row)*1024 + k0 + s4*8] :
                (mat==2) ? &Bh[(size_t)(n0+row)*1024 + k0 + s4*8] :
                           &Bl[(size_t)(n0+row)*1024 + k0 + s4*8];
            CP16(dst, srcp);
        }
    };

    load_stage(0, 0); CP_COMMIT();

    for (int c = 0; c < 32; c++) {
        if (c < 31) { load_stage((c+1)&1, (c+1)*32); CP_COMMIT(); CP_WAIT(1); }
        else        { CP_WAIT(0); }
        __syncthreads();
        const u32 st = sb + (c&1)*40960;
#pragma unroll
        for (int kb=0;kb<32;kb+=16){
            u32 ah[4][4], al[4][4], bhr[4][2], blr[4][2];
#pragma unroll
            for (int mt=0;mt<4;mt++){
                u32 ra = st + ((warpM*64+mt*16+lr)*40 + kb + lc8)*2;
                ldsm4(ah[mt][0],ah[mt][1],ah[mt][2],ah[mt][3], ra);
                ldsm4(al[mt][0],al[mt][1],al[mt][2],al[mt][3], ra + 10240);
            }
#pragma unroll
            for (int gg=0;gg<2;gg++){
                u32 rb = st + 20480 + ((warpN*32+gg*16+lr)*40 + kb + lc8)*2;
                u32 r0,r1,r2,r3;
                ldsm4(r0,r1,r2,r3, rb);
                bhr[2*gg][0]=r0; bhr[2*gg][1]=r2; bhr[2*gg+1][0]=r1; bhr[2*gg+1][1]=r3;
                ldsm4(r0,r1,r2,r3, rb + 10240);
                blr[2*gg][0]=r0; blr[2*gg][1]=r2; blr[2*gg+1][0]=r1; blr[2*gg+1][1]=r3;
            }
#pragma unroll
            for (int mt=0;mt<4;mt++)
#pragma unroll
                for (int nt=0;nt<4;nt++){
                    mma16816(acc[mt][nt], ah[mt], bhr[nt][0], bhr[nt][1]);
                    mma16816(acc[mt][nt], ah[mt], blr[nt][0], blr[nt][1]);
                    mma16816(acc[mt][nt], al[mt], bhr[nt][0], bhr[nt][1]);
                }
        }
        __syncthreads();
    }

#pragma unroll
    for (int mt=0;mt<4;mt++)
#pragma unroll
        for (int nt=0;nt<4;nt++){
            int ncol = n0 + warpN*32 + nt*8 + 2*t;
            float b0 = bias[ncol], b1 = bias[ncol+1];
            int h = ncol>>6, dd = ncol&63;
#pragma unroll
            for (int rr=0;rr<2;rr++){
                int m = m0 + warpM*64 + mt*16 + g + rr*8;
                int b_ = m>>10, l = m&1023;
                float v0 = acc[mt][nt][rr*2+0] + b0;
                float v1 = acc[mt][nt][rr*2+1] + b1;
                size_t o = (((size_t)(b_*HH + h))*SS + l)*HDD + dd;
                *(u32*)&dhi[o] = pack2hi(v0, v1);
                *(u32*)&dlo[o] = pack2lo(v0, v1);
            }
        }
}

// ============================================================================
// K2: scores = (q k^T)[x3] + Toeplitz(Q DE^T)[x1], *0.125 + mask -> f32
// Q/K hi/lo resident for full K=64 (one cp.async wait); DE chunks prefetched.
// smem: sQh(18432) sQl sKh sKl | sDE 9216 | sT 128*66*4 = 116736B dynamic.
// ============================================================================
#define SC_SMEM 116736
#define SC_QH 0
#define SC_QL 18432
#define SC_KH 36864
#define SC_KL 55296
#define SC_DE 73728
#define SC_T  82944
__global__ __launch_bounds__(256)
void scores_mma(const float* __restrict__ mask)
{
    extern __shared__ __align__(16) char smem[];
    const u32 sb = sptr(smem);
    float* sT = (float*)(smem + SC_T);

    const int tid = threadIdx.x, wid = tid>>5, lane = tid&31;
    const int warpM = wid>>2, warpN = wid&3;
    const int bh = blockIdx.z, l0 = blockIdx.y*128, r0 = blockIdx.x*128;
    const int b_ = bh>>4;
    const int jb = l0 - r0 + 896;
    const int lr = lane&15, lc8 = (lane>>4)*8, g = lane>>2, t = lane&3;

    const bf16* qh = g_qhi + (size_t)bh*SS*HDD;
    const bf16* ql = g_qlo + (size_t)bh*SS*HDD;
    const bf16* kh = g_khi + (size_t)bh*SS*HDD;
    const bf16* kl = g_klo + (size_t)bh*SS*HDD;

    auto load_de = [&](int cchunk){
#pragma unroll
        for (int rep=0;rep<2;rep++){
            int idx = rep*256 + tid;
            int row = idx >> 3, s8 = idx & 7;
            int der = jb + cchunk*64 + row; if (der > 2046) der = 2046;
            CP16(sb + SC_DE + row*144 + s8*16, &g_dehi[(size_t)der*64 + s8*8]);
        }
    };

    // group 0: Q/K full K=64 (16 cp.async per thread)
#pragma unroll
    for (int rep=0;rep<16;rep++){
        int idx = rep*256 + tid;
        int mat = idx >> 10, rem = idx & 1023;
        int row = rem >> 3, s8 = rem & 7;
        u32 dst = sb + mat*18432 + row*144 + s8*16;
        const bf16* srcp =
            (mat==0) ? &qh[(size_t)(l0+row)*64 + s8*8] :
            (mat==1) ? &ql[(size_t)(l0+row)*64 + s8*8] :
            (mat==2) ? &kh[(size_t)(r0+row)*64 + s8*8] :
                       &kl[(size_t)(r0+row)*64 + s8*8];
        CP16(dst, srcp);
    }
    CP_COMMIT();
    load_de(0); CP_COMMIT();    // group 1: DE chunk 0

    float acc[4][4][4];
#pragma unroll
    for (int i=0;i<4;i++)
#pragma unroll
        for (int j=0;j<4;j++)
#pragma unroll
            for (int c=0;c<4;c++) acc[i][j][c]=0.f;

    CP_WAIT(1);          // Q/K ready (DE0 may still be in flight)
    __syncthreads();

    // ---- phase 1: qk^T x3, all 4 k-steps behind one barrier ----
#pragma unroll
    for (int kb=0;kb<64;kb+=16){
        u32 ah[4][4], al[4][4], bhr[4][2], blr[4][2];
#pragma unroll
        for (int mt=0;mt<4;mt++){
            u32 ra = sb + ((warpM*64+mt*16+lr)*72 + kb + lc8)*2;
            ldsm4(ah[mt][0],ah[mt][1],ah[mt][2],ah[mt][3], ra + SC_QH);
            ldsm4(al[mt][0],al[mt][1],al[mt][2],al[mt][3], ra + SC_QL);
        }
#pragma unroll
        for (int gg=0;gg<2;gg++){
            u32 rb = sb + ((warpN*32+gg*16+lr)*72 + kb + lc8)*2;
            u32 r0r,r1r,r2r,r3r;
            ldsm4(r0r,r1r,r2r,r3r, rb + SC_KH);
            bhr[2*gg][0]=r0r; bhr[2*gg][1]=r2r; bhr[2*gg+1][0]=r1r; bhr[2*gg+1][1]=r3r;
            ldsm4(r0r,r1r,r2r,r3r, rb + SC_KL);
            blr[2*gg][0]=r0r; blr[2*gg][1]=r2r; blr[2*gg+1][0]=r1r; blr[2*gg+1][1]=r3r;
        }
#pragma unroll
        for (int mt=0;mt<4;mt++)
#pragma unroll
            for (int nt=0;nt<4;nt++){
                mma16816(acc[mt][nt], ah[mt], bhr[nt][0], bhr[nt][1]);
                mma16816(acc[mt][nt], ah[mt], blr[nt][0], blr[nt][1]);
                mma16816(acc[mt][nt], al[mt], bhr[nt][0], bhr[nt][1]);
            }
    }

    // ---- phase 2: pe via T = Q DE^T (x1), 4 prefetched chunks ----
    for (int c=0;c<4;c++){
        int t0c = 64*c;
        float Tacc[4][2][4];
#pragma unroll
        for (int i=0;i<4;i++)
#pragma unroll
            for (int j=0;j<2;j++)
#pragma unroll
                for (int q=0;q<4;q++) Tacc[i][j][q]=0.f;

        CP_WAIT(0);
        __syncthreads();           // DE chunk c visible
#pragma unroll
        for (int kb=0;kb<64;kb+=16){
            u32 ah[4][4];
#pragma unroll
            for (int mt=0;mt<4;mt++)
                ldsm4(ah[mt][0],ah[mt][1],ah[mt][2],ah[mt][3],
                      sb + SC_QH + ((warpM*64+mt*16+lr)*72 + kb + lc8)*2);
            u32 r0r,r1r,r2r,r3r;
            ldsm4(r0r,r1r,r2r,r3r, sb + SC_DE + ((warpN*16+lr)*72 + kb + lc8)*2);
#pragma unroll
            for (int mt=0;mt<4;mt++){
                mma16816(Tacc[mt][0], ah[mt], r0r, r2r);
                mma16816(Tacc[mt][1], ah[mt], r1r, r3r);
            }
        }
        __syncthreads();           // sDE reads done
        if (c < 3) { load_de(c+1); CP_COMMIT(); }  // overlap with sT/gather

#pragma unroll
        for (int mt=0;mt<4;mt++)
#pragma unroll
            for (int n2=0;n2<2;n2++){
                int col = warpN*16 + n2*8 + 2*t;
                int rw = warpM*64 + mt*16 + g;
                *(float2*)&sT[rw*66 + col]     = make_float2(Tacc[mt][n2][0], Tacc[mt][n2][1]);
                *(float2*)&sT[(rw+8)*66 + col] = make_float2(Tacc[mt][n2][2], Tacc[mt][n2][3]);
            }
        __syncthreads();
#pragma unroll
        for (int mt=0;mt<4;mt++){
            int ib = warpM*64 + mt*16 + g;
#pragma unroll
            for (int nt=0;nt<4;nt++){
                int jb0 = warpN*32 + nt*8 + 2*t;
#pragma unroll
                for (int cr=0;cr<4;cr++){
                    int i = ib + (cr>>1)*8, j = jb0 + (cr&1);
                    int tt = i - j + 127 - t0c;
                    if ((unsigned)tt < 64u) acc[mt][nt][cr] += sT[i*66 + tt];
                }
            }
        }
        __syncthreads();
    }

    float* outp = g_sc + (size_t)bh*SS*SS;
#pragma unroll
    for (int mt=0;mt<4;mt++){
        int i0 = l0 + warpM*64 + mt*16 + g;
#pragma unroll
        for (int nt=0;nt<4;nt++){
            int jc = r0 + warpN*32 + nt*8 + 2*t;
            float2 mk = *(const float2*)&mask[b_*SS + jc];
            *(float2*)&outp[(size_t)i0*SS + jc] =
                make_float2(fmaf(acc[mt][nt][0],0.125f,mk.x), fmaf(acc[mt][nt][1],0.125f,mk.y));
            *(float2*)&outp[(size_t)(i0+8)*SS + jc] =
                make_float2(fmaf(acc[mt][nt][2],0.125f,mk.x), fmaf(acc[mt][nt][3],0.125f,mk.y));
        }
    }
}

// ============================================================================
// K3: stochastic double softmax, warp-per-row, hybrid fast log.
// ============================================================================
__device__ __forceinline__ float fast_neglog(float u)
{
    // w = eps - log(u + eps), eps = 1e-10
    float up = u + 1e-10f;
    float d  = up - 1.0f;
    // log1p(d), 5-term series, valid |d| < 0.03125
    float p = d*(1.f + d*(-0.5f + d*(0.33333333f + d*(-0.25f + d*0.2f))));
    float lg = __logf(up);
    float l = (d > -0.03125f) ? p : lg;
    return 1e-10f - l;
}

__global__ __launch_bounds__(256)
void softmax_warp(const float* __restrict__ gum)
{
    const int tid = threadIdx.x, lane = tid & 31, w = tid >> 5;
    const size_t row = (size_t)blockIdx.x * 8 + w;
    const float* srow = g_sc + row * SS;
    const float* urow = gum + row * SS;

    float s[32], n[32];
#pragma unroll
    for (int j = 0; j < 8; j++) {
        float4 v = *(const float4*)&srow[(j*32 + lane)*4];
        s[j*4+0]=v.x; s[j*4+1]=v.y; s[j*4+2]=v.z; s[j*4+3]=v.w;
        float4 u = *(const float4*)&urow[(j*32 + lane)*4];
        n[j*4+0] = fast_neglog(u.x);
        n[j*4+1] = fast_neglog(u.y);
        n[j*4+2] = fast_neglog(u.z);
        n[j*4+3] = fast_neglog(u.w);
    }
    float m = s[0];
#pragma unroll
    for (int i = 1; i < 32; i++) m = fmaxf(m, s[i]);
#pragma unroll
    for (int o = 16; o; o >>= 1) m = fmaxf(m, __shfl_xor_sync(0xffffffffu, m, o));

    float sm1 = 0.f;
#pragma unroll
    for (int i = 0; i < 32; i++) {
        s[i] = __expf(s[i] - m);
        n[i] = __fdividef(s[i], n[i]);
        sm1 += n[i];
    }
#pragma unroll
    for (int o = 16; o; o >>= 1) sm1 += __shfl_xor_sync(0xffffffffu, sm1, o);
    float inv1 = __fdividef(1.0f, sm1);

    float sm2 = 0.f;
#pragma unroll
    for (int i = 0; i < 32; i++) {
        n[i] = s[i] * __expf(fmaf(n[i], inv1, -1.0f));
        sm2 += n[i];
    }
#pragma unroll
    for (int o = 16; o; o >>= 1) sm2 += __shfl_xor_sync(0xffffffffu, sm2, o);
    float inv2 = __fdividef(1.0f, sm2);

#pragma unroll
    for (int j = 0; j < 8; j++) {
        float a = n[j*4+0]*inv2, b = n[j*4+1]*inv2, c = n[j*4+2]*inv2, d = n[j*4+3]*inv2;
        size_t o = row*SS + (j*32 + lane)*4;
        *(uint2*)&g_phi[o] = make_uint2(pack2hi(a,b), pack2hi(c,d));
        *(uint2*)&g_plo[o] = make_uint2(pack2lo(a,b), pack2lo(c,d));
    }
}

// ============================================================================
// K4: out = P @ V (bf16 x3 mma), cp.async 2-stage pipeline.
// stage layout (29696B): Phi(10240) Plo(10240) Vhi(4608) Vlo(4608).
// ============================================================================
#define PV_SMEM (2*29696)
__global__ __launch_bounds__(256)
void pv_mma(float* __restrict__ out)
{
    extern __shared__ __align__(16) char smem[];
    const u32 sb = sptr(smem);

    const int tid = threadIdx.x, wid = tid>>5, lane = tid&31;
    const int warpM = wid>>1, warpN = wid&1;
    const int bh = blockIdx.y, l0 = blockIdx.x*128;
    const int b_ = bh>>4, h = bh&15;
    const int lr = lane&15, lc8 = (lane>>4)*8, g = lane>>2, t = lane&3;

    const bf16* Ph = g_phi + (size_t)bh*SS*SS;
    const bf16* Pl = g_plo + (size_t)bh*SS*SS;
    const bf16* Vh = g_vhi + (size_t)bh*SS*HDD;
    const bf16* Vl = g_vlo + (size_t)bh*SS*HDD;

    auto load_stage = [&](int st, int k0){
        const u32 base = sb + st*29696;
#pragma unroll
        for (int rep=0;rep<4;rep++){          // P: 1024 transfers
            int idx = rep*256 + tid;
            int mat = idx >> 9, rem = idx & 511;
            int row = rem >> 2, s4 = rem & 3;
            const bf16* srcp = (mat==0) ? &Ph[(size_t)(l0+row)*1024 + k0 + s4*8]
                                        : &Pl[(size_t)(l0+row)*1024 + k0 + s4*8];
            CP16(base + mat*10240 + row*80 + s4*16, srcp);
        }
#pragma unroll
        for (int rep=0;rep<2;rep++){          // V: 512 transfers
            int idx = rep*256 + tid;
            int mat = idx >> 8, rem = idx & 255;
            int row = rem >> 3, s8 = rem & 7;
            const bf16* srcp = (mat==0) ? &Vh[(size_t)(k0+row)*64 + s8*8]
                                        : &Vl[(size_t)(k0+row)*64 + s8*8];
            CP16(base + 20480 + mat*4608 + row*144 + s8*16, srcp);
        }
    };

    float acc[2][4][4];
#pragma unroll
    for (int i=0;i<2;i++)
#pragma unroll
        for (int j=0;j<4;j++)
#pragma unroll
            for (int c=0;c<4;c++) acc[i][j][c]=0.f;

    load_stage(0, 0); CP_COMMIT();

    for (int c = 0; c < 32; c++) {
        if (c < 31) { load_stage((c+1)&1, (c+1)*32); CP_COMMIT(); CP_WAIT(1); }
        else        { CP_WAIT(0); }
        __syncthreads();
        const u32 st = sb + (c&1)*29696;
#pragma unroll
        for (int kb=0;kb<32;kb+=16){
            u32 ah[2][4], al[2][4], bhr[4][2], blr[4][2];
#pragma unroll
            for (int mt=0;mt<2;mt++){
                u32 ra = st + ((warpM*32+mt*16+lr)*40 + kb + lc8)*2;
                ldsm4(ah[mt][0],ah[mt][1],ah[mt][2],ah[mt][3], ra);
                ldsm4(al[mt][0],al[mt][1],al[mt][2],al[mt][3], ra + 10240);
            }
#pragma unroll
            for (int gg=0;gg<2;gg++){
                u32 rb = st + 20480 + ((kb+lr)*72 + warpN*32 + gg*16 + lc8)*2;
                u32 r0,r1,r2,r3;
                ldsm4t(r0,r1,r2,r3, rb);
                bhr[2*gg][0]=r0; bhr[2*gg][1]=r1; bhr[2*gg+1][0]=r2; bhr[2*gg+1][1]=r3;
                ldsm4t(r0,r1,r2,r3, rb + 4608);
                blr[2*gg][0]=r0; blr[2*gg][1]=r1; blr[2*gg+1][0]=r2; blr[2*gg+1][1]=r3;
            }
#pragma unroll
            for (int mt=0;mt<2;mt++)
#pragma unroll
                for (int nt=0;nt<4;nt++){
                    mma16816(acc[mt][nt], ah[mt], bhr[nt][0], bhr[nt][1]);
                    mma16816(acc[mt][nt], ah[mt], blr[nt][0], blr[nt][1]);
                    mma16816(acc[mt][nt], al[mt], bhr[nt][0], bhr[nt][1]);
                }
        }
        __syncthreads();
    }

#pragma unroll
    for (int mt=0;mt<2;mt++)
#pragma unroll
        for (int nt=0;nt<4;nt++){
            int dcol = warpN*32 + nt*8 + 2*t;
#pragma unroll
            for (int rr=0;rr<2;rr++){
                int l = l0 + warpM*32 + mt*16 + g + rr*8;
                *(float2*)&out[((size_t)(b_*SS)+l)*1024 + h*64 + dcol] =
                    make_float2(acc[mt][nt][rr*2+0], acc[mt][nt][rr*2+1]);
            }
        }
}

// ============================================================================
extern "C" void kernel_launch(void* const* d_in, const int* in_sizes, int n_in,
                              void* d_out, int out_size)
{
    const float* hidden = (const float*)d_in[0];
    const float* mask   = (const float*)d_in[1];
    const float* gum    = (const float*)d_in[2];
    const float* Wq     = (const float*)d_in[3];
    const float* bq     = (const float*)d_in[4];
    const float* Wk     = (const float*)d_in[5];
    const float* bk     = (const float*)d_in[6];
    const float* Wv     = (const float*)d_in[7];
    const float* bv     = (const float*)d_in[8];
    const float* de     = (const float*)d_in[9];
    float* out = (float*)d_out;

    static int configured = 0;
    if (!configured) {
        cudaFuncSetAttribute(qkv_mma,    cudaFuncAttributeMaxDynamicSharedMemorySize, QKV_SMEM);
        cudaFuncSetAttribute(scores_mma, cudaFuncAttributeMaxDynamicSharedMemorySize, SC_SMEM);
        cudaFuncSetAttribute(pv_mma,     cudaFuncAttributeMaxDynamicSharedMemorySize, PV_SMEM);
        configured = 1;
    }

    cvt_kernel<<<5249, 256>>>(hidden, Wq, Wk, Wv, de);
    qkv_mma<<<dim3(8, 16, 3), 256, QKV_SMEM>>>(bq, bk, bv);
    scores_mma<<<dim3(8, 8, 32), 256, SC_SMEM>>>(mask);
    softmax_warp<<<4096, 256>>>(gum);
    pv_mma<<<dim3(8, 32), 256, PV_SMEM>>>(out);
}

// round 7
// speedup vs baseline: 1.2937x; 1.0919x over previous
#include <cuda_runtime.h>
#include <cuda_bf16.h>
#include <math.h>

typedef unsigned int u32;
typedef __nv_bfloat16 bf16;

#define SS 1024
#define HH 16
#define HDD 64
#define NBH 32

// ---------------- scratch (device globals) ----------------
__device__ bf16 g_xhi[2048*1024], g_xlo[2048*1024];
__device__ bf16 g_whi[3*1024*1024], g_wlo[3*1024*1024];
__device__ bf16 g_dehi[2047*64];
__device__ bf16 g_qhi[NBH*SS*HDD], g_qlo[NBH*SS*HDD];
__device__ bf16 g_khi[NBH*SS*HDD], g_klo[NBH*SS*HDD];
__device__ bf16 g_vhi[NBH*SS*HDD], g_vlo[NBH*SS*HDD];
__device__ bf16 g_phi[(size_t)NBH*SS*SS], g_plo[(size_t)NBH*SS*SS];
__device__ float g_sc[(size_t)NBH*SS*SS];

// ---------------- helpers ----------------
__device__ __forceinline__ u32 sptr(const void* p){ return (u32)__cvta_generic_to_shared(p); }
__device__ __forceinline__ void ldsm4(u32& r0,u32& r1,u32& r2,u32& r3,u32 a){
    asm volatile("ldmatrix.sync.aligned.m8n8.x4.shared.b16 {%0,%1,%2,%3},[%4];"
                 :"=r"(r0),"=r"(r1),"=r"(r2),"=r"(r3):"r"(a));
}
__device__ __forceinline__ void ldsm4t(u32& r0,u32& r1,u32& r2,u32& r3,u32 a){
    asm volatile("ldmatrix.sync.aligned.m8n8.x4.trans.shared.b16 {%0,%1,%2,%3},[%4];"
                 :"=r"(r0),"=r"(r1),"=r"(r2),"=r"(r3):"r"(a));
}
__device__ __forceinline__ void mma16816(float (&c)[4], const u32 (&a)[4], u32 b0, u32 b1){
    asm volatile("mma.sync.aligned.m16n8k16.row.col.f32.bf16.bf16.f32 "
                 "{%0,%1,%2,%3},{%4,%5,%6,%7},{%8,%9},{%0,%1,%2,%3};"
                 :"+f"(c[0]),"+f"(c[1]),"+f"(c[2]),"+f"(c[3])
                 :"r"(a[0]),"r"(a[1]),"r"(a[2]),"r"(a[3]),"r"(b0),"r"(b1));
}
__device__ __forceinline__ void split2(float v, bf16& h, bf16& l){
    h = __float2bfloat16_rn(v);
    l = __float2bfloat16_rn(v - __bfloat162float(h));
}
__device__ __forceinline__ u32 pack2hi(float a, float b){
    __nv_bfloat162 t; t.x=__float2bfloat16_rn(a); t.y=__float2bfloat16_rn(b);
    return *(u32*)&t;
}
__device__ __forceinline__ u32 pack2lo(float a, float b){
    float ah = __bfloat162float(__float2bfloat16_rn(a));
    float bh = __bfloat162float(__float2bfloat16_rn(b));
    __nv_bfloat162 t; t.x=__float2bfloat16_rn(a-ah); t.y=__float2bfloat16_rn(b-bh);
    return *(u32*)&t;
}

#define CP16(dst, src) \
    asm volatile("cp.async.cg.shared.global [%0], [%1], 16;" :: "r"(dst), "l"(src))
#define CP_COMMIT() asm volatile("cp.async.commit_group;" ::: "memory")
#define CP_WAIT(n)  asm volatile("cp.async.wait_group %0;" :: "n"(n) : "memory")

// ============================================================================
// K0: fp32 -> bf16 (hi,lo) splits, all 5 tensors in ONE launch.
// ============================================================================
__global__ __launch_bounds__(256)
void cvt_kernel(const float* __restrict__ X, const float* __restrict__ Wq,
                const float* __restrict__ Wk, const float* __restrict__ Wv,
                const float* __restrict__ de)
{
    int i = blockIdx.x * 256 + threadIdx.x;
    const float* src; bf16 *hi, *lo = nullptr; int off;
    if (i < 524288)       { src = X;  hi = g_xhi; lo = g_xlo; off = i; }
    else if (i < 786432)  { src = Wq; hi = g_whi;            lo = g_wlo;            off = i - 524288; }
    else if (i < 1048576) { src = Wk; hi = g_whi + 1048576;  lo = g_wlo + 1048576;  off = i - 786432; }
    else if (i < 1310720) { src = Wv; hi = g_whi + 2097152;  lo = g_wlo + 2097152;  off = i - 1048576; }
    else if (i < 1343472) { src = de; hi = g_dehi;                                   off = i - 1310720; }
    else return;

    float4 v = *(const float4*)(src + (size_t)off * 4);
    float vv[4] = {v.x, v.y, v.z, v.w};
    bf16 h[4], l[4];
#pragma unroll
    for (int j = 0; j < 4; j++) split2(vv[j], h[j], l[j]);
    __nv_bfloat162 h0; h0.x=h[0]; h0.y=h[1];
    __nv_bfloat162 h1; h1.x=h[2]; h1.y=h[3];
    *(uint2*)(hi + (size_t)off*4) = make_uint2(*(u32*)&h0, *(u32*)&h1);
    if (lo) {
        __nv_bfloat162 l0; l0.x=l[0]; l0.y=l[1];
        __nv_bfloat162 l1; l1.x=l[2]; l1.y=l[3];
        *(uint2*)(lo + (size_t)off*4) = make_uint2(*(u32*)&l0, *(u32*)&l1);
    }
}

// ============================================================================
// K1: q/k/v = X @ W^T + b (bf16 x3 mma), cp.async 2-stage pipeline.
// CTA 128m x 128n, BK=32, 8 warps (2m x 4n). 2 CTAs/SM.
// ============================================================================
#define QKV_SMEM (2*40960)
__global__ __launch_bounds__(256, 2)
void qkv_mma(const float* __restrict__ bq, const float* __restrict__ bk,
             const float* __restrict__ bv)
{
    extern __shared__ __align__(16) char smem[];
    const u32 sb = sptr(smem);

    const int tid = threadIdx.x, wid = tid>>5, lane = tid&31;
    const int warpM = wid>>2, warpN = wid&3;
    const int z = blockIdx.z, n0 = blockIdx.x*128, m0 = blockIdx.y*128;
    const int lr = lane&15, lc8 = (lane>>4)*8, g = lane>>2, t = lane&3;

    const bf16* Bh = g_whi + (size_t)z*1048576;
    const bf16* Bl = g_wlo + (size_t)z*1048576;
    const float* bias = (z==0)?bq:(z==1)?bk:bv;
    bf16* dhi = (z==0)?g_qhi:(z==1)?g_khi:g_vhi;
    bf16* dlo = (z==0)?g_qlo:(z==1)?g_klo:g_vlo;

    float acc[4][4][4];
#pragma unroll
    for (int i=0;i<4;i++)
#pragma unroll
        for (int j=0;j<4;j++)
#pragma unroll
            for (int c=0;c<4;c++) acc[i][j][c]=0.f;

    auto load_stage = [&](int st, int k0){
        const u32 base = sb + st*40960;
#pragma unroll
        for (int rep=0;rep<8;rep++){
            int idx = rep*256 + tid;
            int mat = idx >> 9, rem = idx & 511;
            int row = rem >> 2, s4 = rem & 3;
            u32 dst = base + mat*10240 + row*80 + s4*16;
            const bf16* srcp =
                (mat==0) ? &g_xhi[(size_t)(m0+row)*1024 + k0 + s4*8] :
                (mat==1) ? &g_xlo[(size_t)(m0+row)*1024 + k0 + s4*8] :
                (mat==2) ? &Bh[(size_t)(n0+row)*1024 + k0 + s4*8] :
                           &Bl[(size_t)(n0+row)*1024 + k0 + s4*8];
            CP16(dst, srcp);
        }
    };

    load_stage(0, 0); CP_COMMIT();

    for (int c = 0; c < 32; c++) {
        if (c < 31) { load_stage((c+1)&1, (c+1)*32); CP_COMMIT(); CP_WAIT(1); }
        else        { CP_WAIT(0); }
        __syncthreads();
        const u32 st = sb + (c&1)*40960;
#pragma unroll
        for (int kb=0;kb<32;kb+=16){
            u32 ah[4][4], al[4][4], bhr[4][2], blr[4][2];
#pragma unroll
            for (int mt=0;mt<4;mt++){
                u32 ra = st + ((warpM*64+mt*16+lr)*40 + kb + lc8)*2;
                ldsm4(ah[mt][0],ah[mt][1],ah[mt][2],ah[mt][3], ra);
                ldsm4(al[mt][0],al[mt][1],al[mt][2],al[mt][3], ra + 10240);
            }
#pragma unroll
            for (int gg=0;gg<2;gg++){
                u32 rb = st + 20480 + ((warpN*32+gg*16+lr)*40 + kb + lc8)*2;
                u32 r0,r1,r2,r3;
                ldsm4(r0,r1,r2,r3, rb);
                bhr[2*gg][0]=r0; bhr[2*gg][1]=r2; bhr[2*gg+1][0]=r1; bhr[2*gg+1][1]=r3;
                ldsm4(r0,r1,r2,r3, rb + 10240);
                blr[2*gg][0]=r0; blr[2*gg][1]=r2; blr[2*gg+1][0]=r1; blr[2*gg+1][1]=r3;
            }
#pragma unroll
            for (int mt=0;mt<4;mt++)
#pragma unroll
                for (int nt=0;nt<4;nt++){
                    mma16816(acc[mt][nt], ah[mt], bhr[nt][0], bhr[nt][1]);
                    mma16816(acc[mt][nt], ah[mt], blr[nt][0], blr[nt][1]);
                    mma16816(acc[mt][nt], al[mt], bhr[nt][0], bhr[nt][1]);
                }
        }
        __syncthreads();
    }

#pragma unroll
    for (int mt=0;mt<4;mt++)
#pragma unroll
        for (int nt=0;nt<4;nt++){
            int ncol = n0 + warpN*32 + nt*8 + 2*t;
            float b0 = bias[ncol], b1 = bias[ncol+1];
            int h = ncol>>6, dd = ncol&63;
#pragma unroll
            for (int rr=0;rr<2;rr++){
                int m = m0 + warpM*64 + mt*16 + g + rr*8;
                int b_ = m>>10, l = m&1023;
                float v0 = acc[mt][nt][rr*2+0] + b0;
                float v1 = acc[mt][nt][rr*2+1] + b1;
                size_t o = (((size_t)(b_*HH + h))*SS + l)*HDD + dd;
                *(u32*)&dhi[o] = pack2hi(v0, v1);
                *(u32*)&dlo[o] = pack2lo(v0, v1);
            }
        }
}

// ============================================================================
// K2: scores = (q k^T)[x3] + Toeplitz(Q DE^T)[x1], *0.125 + mask -> f32
// Q/K hi/lo resident; sT OVERLAYS sKh/sKl (K dead after phase 1) -> 83KB,
// 2 CTAs/SM.
// ============================================================================
#define SC_SMEM 82944
#define SC_QH 0
#define SC_QL 18432
#define SC_KH 36864
#define SC_KL 55296
#define SC_DE 73728
#define SC_T  36864   /* overlays sKh/sKl: 128*66*4 = 33792 <= 36864 */
__global__ __launch_bounds__(256, 2)
void scores_mma(const float* __restrict__ mask)
{
    extern __shared__ __align__(16) char smem[];
    const u32 sb = sptr(smem);
    float* sT = (float*)(smem + SC_T);

    const int tid = threadIdx.x, wid = tid>>5, lane = tid&31;
    const int warpM = wid>>2, warpN = wid&3;
    const int bh = blockIdx.z, l0 = blockIdx.y*128, r0 = blockIdx.x*128;
    const int b_ = bh>>4;
    const int jb = l0 - r0 + 896;
    const int lr = lane&15, lc8 = (lane>>4)*8, g = lane>>2, t = lane&3;

    const bf16* qh = g_qhi + (size_t)bh*SS*HDD;
    const bf16* ql = g_qlo + (size_t)bh*SS*HDD;
    const bf16* kh = g_khi + (size_t)bh*SS*HDD;
    const bf16* kl = g_klo + (size_t)bh*SS*HDD;

    auto load_de = [&](int cchunk){
#pragma unroll
        for (int rep=0;rep<2;rep++){
            int idx = rep*256 + tid;
            int row = idx >> 3, s8 = idx & 7;
            int der = jb + cchunk*64 + row; if (der > 2046) der = 2046;
            CP16(sb + SC_DE + row*144 + s8*16, &g_dehi[(size_t)der*64 + s8*8]);
        }
    };

    // group 0: Q/K full K=64
#pragma unroll
    for (int rep=0;rep<16;rep++){
        int idx = rep*256 + tid;
        int mat = idx >> 10, rem = idx & 1023;
        int row = rem >> 3, s8 = rem & 7;
        u32 dst = sb + mat*18432 + row*144 + s8*16;
        const bf16* srcp =
            (mat==0) ? &qh[(size_t)(l0+row)*64 + s8*8] :
            (mat==1) ? &ql[(size_t)(l0+row)*64 + s8*8] :
            (mat==2) ? &kh[(size_t)(r0+row)*64 + s8*8] :
                       &kl[(size_t)(r0+row)*64 + s8*8];
        CP16(dst, srcp);
    }
    CP_COMMIT();
    load_de(0); CP_COMMIT();

    float acc[4][4][4];
#pragma unroll
    for (int i=0;i<4;i++)
#pragma unroll
        for (int j=0;j<4;j++)
#pragma unroll
            for (int c=0;c<4;c++) acc[i][j][c]=0.f;

    CP_WAIT(1);
    __syncthreads();

    // ---- phase 1: qk^T x3 ----
#pragma unroll
    for (int kb=0;kb<64;kb+=16){
        u32 ah[4][4], al[4][4], bhr[4][2], blr[4][2];
#pragma unroll
        for (int mt=0;mt<4;mt++){
            u32 ra = sb + ((warpM*64+mt*16+lr)*72 + kb + lc8)*2;
            ldsm4(ah[mt][0],ah[mt][1],ah[mt][2],ah[mt][3], ra + SC_QH);
            ldsm4(al[mt][0],al[mt][1],al[mt][2],al[mt][3], ra + SC_QL);
        }
#pragma unroll
        for (int gg=0;gg<2;gg++){
            u32 rb = sb + ((warpN*32+gg*16+lr)*72 + kb + lc8)*2;
            u32 r0r,r1r,r2r,r3r;
            ldsm4(r0r,r1r,r2r,r3r, rb + SC_KH);
            bhr[2*gg][0]=r0r; bhr[2*gg][1]=r2r; bhr[2*gg+1][0]=r1r; bhr[2*gg+1][1]=r3r;
            ldsm4(r0r,r1r,r2r,r3r, rb + SC_KL);
            blr[2*gg][0]=r0r; blr[2*gg][1]=r2r; blr[2*gg+1][0]=r1r; blr[2*gg+1][1]=r3r;
        }
#pragma unroll
        for (int mt=0;mt<4;mt++)
#pragma unroll
            for (int nt=0;nt<4;nt++){
                mma16816(acc[mt][nt], ah[mt], bhr[nt][0], bhr[nt][1]);
                mma16816(acc[mt][nt], ah[mt], blr[nt][0], blr[nt][1]);
                mma16816(acc[mt][nt], al[mt], bhr[nt][0], bhr[nt][1]);
            }
    }

    // ---- phase 2: pe via T = Q DE^T (x1), 4 prefetched chunks ----
    for (int c=0;c<4;c++){
        int t0c = 64*c;
        float Tacc[4][2][4];
#pragma unroll
        for (int i=0;i<4;i++)
#pragma unroll
            for (int j=0;j<2;j++)
#pragma unroll
                for (int q=0;q<4;q++) Tacc[i][j][q]=0.f;

        CP_WAIT(0);
        __syncthreads();           // DE chunk c visible; K-region reads all done
#pragma unroll
        for (int kb=0;kb<64;kb+=16){
            u32 ah[4][4];
#pragma unroll
            for (int mt=0;mt<4;mt++)
                ldsm4(ah[mt][0],ah[mt][1],ah[mt][2],ah[mt][3],
                      sb + SC_QH + ((warpM*64+mt*16+lr)*72 + kb + lc8)*2);
            u32 r0r,r1r,r2r,r3r;
            ldsm4(r0r,r1r,r2r,r3r, sb + SC_DE + ((warpN*16+lr)*72 + kb + lc8)*2);
#pragma unroll
            for (int mt=0;mt<4;mt++){
                mma16816(Tacc[mt][0], ah[mt], r0r, r2r);
                mma16816(Tacc[mt][1], ah[mt], r1r, r3r);
            }
        }
        __syncthreads();           // sDE reads done
        if (c < 3) { load_de(c+1); CP_COMMIT(); }

#pragma unroll
        for (int mt=0;mt<4;mt++)
#pragma unroll
            for (int n2=0;n2<2;n2++){
                int col = warpN*16 + n2*8 + 2*t;
                int rw = warpM*64 + mt*16 + g;
                *(float2*)&sT[rw*66 + col]     = make_float2(Tacc[mt][n2][0], Tacc[mt][n2][1]);
                *(float2*)&sT[(rw+8)*66 + col] = make_float2(Tacc[mt][n2][2], Tacc[mt][n2][3]);
            }
        __syncthreads();
#pragma unroll
        for (int mt=0;mt<4;mt++){
            int ib = warpM*64 + mt*16 + g;
#pragma unroll
            for (int nt=0;nt<4;nt++){
                int jb0 = warpN*32 + nt*8 + 2*t;
#pragma unroll
                for (int cr=0;cr<4;cr++){
                    int i = ib + (cr>>1)*8, j = jb0 + (cr&1);
                    int tt = i - j + 127 - t0c;
                    if ((unsigned)tt < 64u) acc[mt][nt][cr] += sT[i*66 + tt];
                }
            }
        }
        __syncthreads();
    }

    float* outp = g_sc + (size_t)bh*SS*SS;
#pragma unroll
    for (int mt=0;mt<4;mt++){
        int i0 = l0 + warpM*64 + mt*16 + g;
#pragma unroll
        for (int nt=0;nt<4;nt++){
            int jc = r0 + warpN*32 + nt*8 + 2*t;
            float2 mk = *(const float2*)&mask[b_*SS + jc];
            *(float2*)&outp[(size_t)i0*SS + jc] =
                make_float2(fmaf(acc[mt][nt][0],0.125f,mk.x), fmaf(acc[mt][nt][1],0.125f,mk.y));
            *(float2*)&outp[(size_t)(i0+8)*SS + jc] =
                make_float2(fmaf(acc[mt][nt][2],0.125f,mk.x), fmaf(acc[mt][nt][3],0.125f,mk.y));
        }
    }
}

// ============================================================================
// K3: stochastic double softmax, warp-per-row, hybrid fast log.
// ============================================================================
__device__ __forceinline__ float fast_neglog(float u)
{
    float up = u + 1e-10f;
    float d  = up - 1.0f;
    float p = d*(1.f + d*(-0.5f + d*(0.33333333f + d*(-0.25f + d*0.2f))));
    float lg = __logf(up);
    float l = (d > -0.03125f) ? p : lg;
    return 1e-10f - l;
}

__global__ __launch_bounds__(256)
void softmax_warp(const float* __restrict__ gum)
{
    const int tid = threadIdx.x, lane = tid & 31, w = tid >> 5;
    const size_t row = (size_t)blockIdx.x * 8 + w;
    const float* srow = g_sc + row * SS;
    const float* urow = gum + row * SS;

    float s[32], n[32];
#pragma unroll
    for (int j = 0; j < 8; j++) {
        float4 v = *(const float4*)&srow[(j*32 + lane)*4];
        s[j*4+0]=v.x; s[j*4+1]=v.y; s[j*4+2]=v.z; s[j*4+3]=v.w;
        float4 u = *(const float4*)&urow[(j*32 + lane)*4];
        n[j*4+0] = fast_neglog(u.x);
        n[j*4+1] = fast_neglog(u.y);
        n[j*4+2] = fast_neglog(u.z);
        n[j*4+3] = fast_neglog(u.w);
    }
    float m = s[0];
#pragma unroll
    for (int i = 1; i < 32; i++) m = fmaxf(m, s[i]);
#pragma unroll
    for (int o = 16; o; o >>= 1) m = fmaxf(m, __shfl_xor_sync(0xffffffffu, m, o));

    float sm1 = 0.f;
#pragma unroll
    for (int i = 0; i < 32; i++) {
        s[i] = __expf(s[i] - m);
        n[i] = __fdividef(s[i], n[i]);
        sm1 += n[i];
    }
#pragma unroll
    for (int o = 16; o; o >>= 1) sm1 += __shfl_xor_sync(0xffffffffu, sm1, o);
    float inv1 = __fdividef(1.0f, sm1);

    float sm2 = 0.f;
#pragma unroll
    for (int i = 0; i < 32; i++) {
        n[i] = s[i] * __expf(fmaf(n[i], inv1, -1.0f));
        sm2 += n[i];
    }
#pragma unroll
    for (int o = 16; o; o >>= 1) sm2 += __shfl_xor_sync(0xffffffffu, sm2, o);
    float inv2 = __fdividef(1.0f, sm2);

#pragma unroll
    for (int j = 0; j < 8; j++) {
        float a = n[j*4+0]*inv2, b = n[j*4+1]*inv2, c = n[j*4+2]*inv2, d = n[j*4+3]*inv2;
        size_t o = row*SS + (j*32 + lane)*4;
        *(uint2*)&g_phi[o] = make_uint2(pack2hi(a,b), pack2hi(c,d));
        *(uint2*)&g_plo[o] = make_uint2(pack2lo(a,b), pack2lo(c,d));
    }
}

// ============================================================================
// K4: out = P @ V (bf16 x3 mma), cp.async 2-stage pipeline. 2 CTAs/SM.
// ============================================================================
#define PV_SMEM (2*29696)
__global__ __launch_bounds__(256, 2)
void pv_mma(float* __restrict__ out)
{
    extern __shared__ __align__(16) char smem[];
    const u32 sb = sptr(smem);

    const int tid = threadIdx.x, wid = tid>>5, lane = tid&31;
    const int warpM = wid>>1, warpN = wid&1;
    const int bh = blockIdx.y, l0 = blockIdx.x*128;
    const int b_ = bh>>4, h = bh&15;
    const int lr = lane&15, lc8 = (lane>>4)*8, g = lane>>2, t = lane&3;

    const bf16* Ph = g_phi + (size_t)bh*SS*SS;
    const bf16* Pl = g_plo + (size_t)bh*SS*SS;
    const bf16* Vh = g_vhi + (size_t)bh*SS*HDD;
    const bf16* Vl = g_vlo + (size_t)bh*SS*HDD;

    auto load_stage = [&](int st, int k0){
        const u32 base = sb + st*29696;
#pragma unroll
        for (int rep=0;rep<4;rep++){
            int idx = rep*256 + tid;
            int mat = idx >> 9, rem = idx & 511;
            int row = rem >> 2, s4 = rem & 3;
            const bf16* srcp = (mat==0) ? &Ph[(size_t)(l0+row)*1024 + k0 + s4*8]
                                        : &Pl[(size_t)(l0+row)*1024 + k0 + s4*8];
            CP16(base + mat*10240 + row*80 + s4*16, srcp);
        }
#pragma unroll
        for (int rep=0;rep<2;rep++){
            int idx = rep*256 + tid;
            int mat = idx >> 8, rem = idx & 255;
            int row = rem >> 3, s8 = rem & 7;
            const bf16* srcp = (mat==0) ? &Vh[(size_t)(k0+row)*64 + s8*8]
                                        : &Vl[(size_t)(k0+row)*64 + s8*8];
            CP16(base + 20480 + mat*4608 + row*144 + s8*16, srcp);
        }
    };

    float acc[2][4][4];
#pragma unroll
    for (int i=0;i<2;i++)
#pragma unroll
        for (int j=0;j<4;j++)
#pragma unroll
            for (int c=0;c<4;c++) acc[i][j][c]=0.f;

    load_stage(0, 0); CP_COMMIT();

    for (int c = 0; c < 32; c++) {
        if (c < 31) { load_stage((c+1)&1, (c+1)*32); CP_COMMIT(); CP_WAIT(1); }
        else        { CP_WAIT(0); }
        __syncthreads();
        const u32 st = sb + (c&1)*29696;
#pragma unroll
        for (int kb=0;kb<32;kb+=16){
            u32 ah[2][4], al[2][4], bhr[4][2], blr[4][2];
#pragma unroll
            for (int mt=0;mt<2;mt++){
                u32 ra = st + ((warpM*32+mt*16+lr)*40 + kb + lc8)*2;
                ldsm4(ah[mt][0],ah[mt][1],ah[mt][2],ah[mt][3], ra);
                ldsm4(al[mt][0],al[mt][1],al[mt][2],al[mt][3], ra + 10240);
            }
#pragma unroll
            for (int gg=0;gg<2;gg++){
                u32 rb = st + 20480 + ((kb+lr)*72 + warpN*32 + gg*16 + lc8)*2;
                u32 r0,r1,r2,r3;
                ldsm4t(r0,r1,r2,r3, rb);
                bhr[2*gg][0]=r0; bhr[2*gg][1]=r1; bhr[2*gg+1][0]=r2; bhr[2*gg+1][1]=r3;
                ldsm4t(r0,r1,r2,r3, rb + 4608);
                blr[2*gg][0]=r0; blr[2*gg][1]=r1; blr[2*gg+1][0]=r2; blr[2*gg+1][1]=r3;
            }
#pragma unroll
            for (int mt=0;mt<2;mt++)
#pragma unroll
                for (int nt=0;nt<4;nt++){
                    mma16816(acc[mt][nt], ah[mt], bhr[nt][0], bhr[nt][1]);
                    mma16816(acc[mt][nt], ah[mt], blr[nt][0], blr[nt][1]);
                    mma16816(acc[mt][nt], al[mt], bhr[nt][0], bhr[nt][1]);
                }
        }
        __syncthreads();
    }

#pragma unroll
    for (int mt=0;mt<2;mt++)
#pragma unroll
        for (int nt=0;nt<4;nt++){
            int dcol = warpN*32 + nt*8 + 2*t;
#pragma unroll
            for (int rr=0;rr<2;rr++){
                int l = l0 + warpM*32 + mt*16 + g + rr*8;
                *(float2*)&out[((size_t)(b_*SS)+l)*1024 + h*64 + dcol] =
                    make_float2(acc[mt][nt][rr*2+0], acc[mt][nt][rr*2+1]);
            }
        }
}

// ============================================================================
extern "C" void kernel_launch(void* const* d_in, const int* in_sizes, int n_in,
                              void* d_out, int out_size)
{
    const float* hidden = (const float*)d_in[0];
    const float* mask   = (const float*)d_in[1];
    const float* gum    = (const float*)d_in[2];
    const float* Wq     = (const float*)d_in[3];
    const float* bq     = (const float*)d_in[4];
    const float* Wk     = (const float*)d_in[5];
    const float* bk     = (const float*)d_in[6];
    const float* Wv     = (const float*)d_in[7];
    const float* bv     = (const float*)d_in[8];
    const float* de     = (const float*)d_in[9];
    float* out = (float*)d_out;

    static int configured = 0;
    if (!configured) {
        cudaFuncSetAttribute(qkv_mma,    cudaFuncAttributeMaxDynamicSharedMemorySize, QKV_SMEM);
        cudaFuncSetAttribute(scores_mma, cudaFuncAttributeMaxDynamicSharedMemorySize, SC_SMEM);
        cudaFuncSetAttribute(pv_mma,     cudaFuncAttributeMaxDynamicSharedMemorySize, PV_SMEM);
        configured = 1;
    }

    cvt_kernel<<<5249, 256>>>(hidden, Wq, Wk, Wv, de);
    qkv_mma<<<dim3(8, 16, 3), 256, QKV_SMEM>>>(bq, bk, bv);
    scores_mma<<<dim3(8, 8, 32), 256, SC_SMEM>>>(mask);
    softmax_warp<<<4096, 256>>>(gum);
    pv_mma<<<dim3(8, 32), 256, PV_SMEM>>>(out);
}

// round 8
// speedup vs baseline: 1.5361x; 1.1874x over previous
#include <cuda_runtime.h>
#include <cuda_fp16.h>
#include <math.h>

typedef unsigned int u32;
typedef __half hf;

#define SS 1024
#define HH 16
#define HDD 64
#define NBH 32

// ---------------- scratch (device globals) ----------------
__device__ hf g_xhi[2048*1024], g_xlo[2048*1024];
__device__ hf g_w[3*1024*1024];
__device__ hf g_de[2047*64];
__device__ hf g_qhi[NBH*SS*HDD], g_qlo[NBH*SS*HDD];
__device__ hf g_k[NBH*SS*HDD];
__device__ hf g_v[NBH*SS*HDD];
__device__ hf g_phi[(size_t)NBH*SS*SS], g_plo[(size_t)NBH*SS*SS];
__device__ float g_sc[(size_t)NBH*SS*SS];

// ---------------- helpers ----------------
__device__ __forceinline__ u32 sptr(const void* p){ return (u32)__cvta_generic_to_shared(p); }
__device__ __forceinline__ void ldsm4(u32& r0,u32& r1,u32& r2,u32& r3,u32 a){
    asm volatile("ldmatrix.sync.aligned.m8n8.x4.shared.b16 {%0,%1,%2,%3},[%4];"
                 :"=r"(r0),"=r"(r1),"=r"(r2),"=r"(r3):"r"(a));
}
__device__ __forceinline__ void ldsm4t(u32& r0,u32& r1,u32& r2,u32& r3,u32 a){
    asm volatile("ldmatrix.sync.aligned.m8n8.x4.trans.shared.b16 {%0,%1,%2,%3},[%4];"
                 :"=r"(r0),"=r"(r1),"=r"(r2),"=r"(r3):"r"(a));
}
__device__ __forceinline__ void mma16816(float (&c)[4], const u32 (&a)[4], u32 b0, u32 b1){
    asm volatile("mma.sync.aligned.m16n8k16.row.col.f32.f16.f16.f32 "
                 "{%0,%1,%2,%3},{%4,%5,%6,%7},{%8,%9},{%0,%1,%2,%3};"
                 :"+f"(c[0]),"+f"(c[1]),"+f"(c[2]),"+f"(c[3])
                 :"r"(a[0]),"r"(a[1]),"r"(a[2]),"r"(a[3]),"r"(b0),"r"(b1));
}
__device__ __forceinline__ u32 pack2h(float a, float b){
    __half2 t; t.x=__float2half_rn(a); t.y=__float2half_rn(b);
    return *(u32*)&t;
}
__device__ __forceinline__ u32 pack2l(float a, float b){
    float ah = __half2float(__float2half_rn(a));
    float bh = __half2float(__float2half_rn(b));
    __half2 t; t.x=__float2half_rn(a-ah); t.y=__float2half_rn(b-bh);
    return *(u32*)&t;
}

#define CP16(dst, src) \
    asm volatile("cp.async.cg.shared.global [%0], [%1], 16;" :: "r"(dst), "l"(src))
#define CP_COMMIT() asm volatile("cp.async.commit_group;" ::: "memory")
#define CP_WAIT(n)  asm volatile("cp.async.wait_group %0;" :: "n"(n) : "memory")

// ============================================================================
// K0: fp32 -> fp16 conversion. X -> hi/lo split; W, de -> single fp16.
// ranges: X[0,524288) W[..+786432) de[..+32752)
// ============================================================================
__global__ __launch_bounds__(256)
void cvt_kernel(const float* __restrict__ X, const float* __restrict__ Wq,
                const float* __restrict__ Wk, const float* __restrict__ Wv,
                const float* __restrict__ de)
{
    int i = blockIdx.x * 256 + threadIdx.x;
    if (i >= 1343472) return;
    if (i < 524288) {
        float4 v = *(const float4*)(X + (size_t)i * 4);
        *(uint2*)(g_xhi + (size_t)i*4) = make_uint2(pack2h(v.x,v.y), pack2h(v.z,v.w));
        *(uint2*)(g_xlo + (size_t)i*4) = make_uint2(pack2l(v.x,v.y), pack2l(v.z,v.w));
        return;
    }
    const float* src; hf* dst; int off;
    if (i < 1310720) {
        off = i - 524288;                      // 0..786431 over 3 x 262144
        int wsel = off >> 18;
        src = (wsel==0)?Wq:(wsel==1)?Wk:Wv;
        dst = g_w + (size_t)(off >> 18) * 1048576;
        off &= 262143;
    } else {
        off = i - 1310720; src = de; dst = g_de;
    }
    float4 v = *(const float4*)(src + (size_t)off * 4);
    *(uint2*)(dst + (size_t)off*4) = make_uint2(pack2h(v.x,v.y), pack2h(v.z,v.w));
}

// ============================================================================
// K1: q/k/v = X @ W^T + b (fp16 x2: Xhi/Xlo split, W single).
// CTA 128m x 128n, BK=32, 8 warps (2m x 4n), cp.async 2-stage, 2 CTAs/SM.
// stage (30720B): Ah(10240) Al(10240) B(10240), row stride 80B.
// q written hi/lo; k,v written single fp16.
// ============================================================================
#define QKV_SMEM (2*30720)
__global__ __launch_bounds__(256, 2)
void qkv_mma(const float* __restrict__ bq, const float* __restrict__ bk,
             const float* __restrict__ bv)
{
    extern __shared__ __align__(16) char smem[];
    const u32 sb = sptr(smem);

    const int tid = threadIdx.x, wid = tid>>5, lane = tid&31;
    const int warpM = wid>>2, warpN = wid&3;
    const int z = blockIdx.z, n0 = blockIdx.x*128, m0 = blockIdx.y*128;
    const int lr = lane&15, lc8 = (lane>>4)*8, g = lane>>2, t = lane&3;

    const hf* B = g_w + (size_t)z*1048576;
    const float* bias = (z==0)?bq:(z==1)?bk:bv;
    hf* dhi = (z==0)?g_qhi:(z==1)?g_k:g_v;
    const bool wlo = (z==0);

    float acc[4][4][4];
#pragma unroll
    for (int i=0;i<4;i++)
#pragma unroll
        for (int j=0;j<4;j++)
#pragma unroll
            for (int c=0;c<4;c++) acc[i][j][c]=0.f;

    auto load_stage = [&](int st, int k0){
        const u32 base = sb + st*30720;
#pragma unroll
        for (int rep=0;rep<6;rep++){
            int idx = rep*256 + tid;             // 0..1535
            int mat = idx >> 9, rem = idx & 511;
            int row = rem >> 2, s4 = rem & 3;
            u32 dst = base + mat*10240 + row*80 + s4*16;
            const hf* srcp =
                (mat==0) ? &g_xhi[(size_t)(m0+row)*1024 + k0 + s4*8] :
                (mat==1) ? &g_xlo[(size_t)(m0+row)*1024 + k0 + s4*8] :
                           &B[(size_t)(n0+row)*1024 + k0 + s4*8];
            CP16(dst, srcp);
        }
    };

    load_stage(0, 0); CP_COMMIT();

    for (int c = 0; c < 32; c++) {
        if (c < 31) { load_stage((c+1)&1, (c+1)*32); CP_COMMIT(); CP_WAIT(1); }
        else        { CP_WAIT(0); }
        __syncthreads();
        const u32 st = sb + (c&1)*30720;
#pragma unroll
        for (int kb=0;kb<32;kb+=16){
            u32 ah[4][4], al[4][4], bb[4][2];
#pragma unroll
            for (int mt=0;mt<4;mt++){
                u32 ra = st + ((warpM*64+mt*16+lr)*40 + kb + lc8)*2;
                ldsm4(ah[mt][0],ah[mt][1],ah[mt][2],ah[mt][3], ra);
                ldsm4(al[mt][0],al[mt][1],al[mt][2],al[mt][3], ra + 10240);
            }
#pragma unroll
            for (int gg=0;gg<2;gg++){
                u32 rb = st + 20480 + ((warpN*32+gg*16+lr)*40 + kb + lc8)*2;
                u32 r0,r1,r2,r3;
                ldsm4(r0,r1,r2,r3, rb);
                bb[2*gg][0]=r0; bb[2*gg][1]=r2; bb[2*gg+1][0]=r1; bb[2*gg+1][1]=r3;
            }
#pragma unroll
            for (int mt=0;mt<4;mt++)
#pragma unroll
                for (int nt=0;nt<4;nt++){
                    mma16816(acc[mt][nt], ah[mt], bb[nt][0], bb[nt][1]);
                    mma16816(acc[mt][nt], al[mt], bb[nt][0], bb[nt][1]);
                }
        }
        __syncthreads();
    }

#pragma unroll
    for (int mt=0;mt<4;mt++)
#pragma unroll
        for (int nt=0;nt<4;nt++){
            int ncol = n0 + warpN*32 + nt*8 + 2*t;
            float b0 = bias[ncol], b1 = bias[ncol+1];
            int h = ncol>>6, dd = ncol&63;
#pragma unroll
            for (int rr=0;rr<2;rr++){
                int m = m0 + warpM*64 + mt*16 + g + rr*8;
                int b_ = m>>10, l = m&1023;
                float v0 = acc[mt][nt][rr*2+0] + b0;
                float v1 = acc[mt][nt][rr*2+1] + b1;
                size_t o = (((size_t)(b_*HH + h))*SS + l)*HDD + dd;
                *(u32*)&dhi[o] = pack2h(v0, v1);
                if (wlo) *(u32*)&g_qlo[o] = pack2l(v0, v1);
            }
        }
}

// ============================================================================
// K2: scores = (q k^T)[fp16 x2] + Toeplitz(Q DE^T)[x1], *0.125 + mask -> f32
// smem: sQh(18432) sQl(18432) sK(18432) sDE(9216) = 64512B; sT overlays
// sQl+sK (dead after phase 1). 2 CTAs/SM.
// ============================================================================
#define SC_SMEM 64512
#define SC_QH 0
#define SC_QL 18432
#define SC_K  36864
#define SC_DE 55296
#define SC_T  18432   /* overlays sQl+sK: 128*66*4 = 33792 <= 36864 */
__global__ __launch_bounds__(256, 2)
void scores_mma(const float* __restrict__ mask)
{
    extern __shared__ __align__(16) char smem[];
    const u32 sb = sptr(smem);
    float* sT = (float*)(smem + SC_T);

    const int tid = threadIdx.x, wid = tid>>5, lane = tid&31;
    const int warpM = wid>>2, warpN = wid&3;
    const int bh = blockIdx.z, l0 = blockIdx.y*128, r0 = blockIdx.x*128;
    const int b_ = bh>>4;
    const int jb = l0 - r0 + 896;
    const int lr = lane&15, lc8 = (lane>>4)*8, g = lane>>2, t = lane&3;

    const hf* qh = g_qhi + (size_t)bh*SS*HDD;
    const hf* ql = g_qlo + (size_t)bh*SS*HDD;
    const hf* kk = g_k   + (size_t)bh*SS*HDD;

    auto load_de = [&](int cchunk){
#pragma unroll
        for (int rep=0;rep<2;rep++){
            int idx = rep*256 + tid;
            int row = idx >> 3, s8 = idx & 7;
            int der = jb + cchunk*64 + row; if (der > 2046) der = 2046;
            CP16(sb + SC_DE + row*144 + s8*16, &g_de[(size_t)der*64 + s8*8]);
        }
    };

    // group 0: Q hi/lo + K, full K=64
#pragma unroll
    for (int rep=0;rep<12;rep++){
        int idx = rep*256 + tid;                 // 0..3071
        int mat = idx >> 10, rem = idx & 1023;
        int row = rem >> 3, s8 = rem & 7;
        u32 dst = sb + mat*18432 + row*144 + s8*16;
        const hf* srcp =
            (mat==0) ? &qh[(size_t)(l0+row)*64 + s8*8] :
            (mat==1) ? &ql[(size_t)(l0+row)*64 + s8*8] :
                       &kk[(size_t)(r0+row)*64 + s8*8];
        CP16(dst, srcp);
    }
    CP_COMMIT();
    load_de(0); CP_COMMIT();

    float acc[4][4][4];
#pragma unroll
    for (int i=0;i<4;i++)
#pragma unroll
        for (int j=0;j<4;j++)
#pragma unroll
            for (int c=0;c<4;c++) acc[i][j][c]=0.f;

    CP_WAIT(1);
    __syncthreads();

    // ---- phase 1: qk^T (x2) ----
#pragma unroll
    for (int kb=0;kb<64;kb+=16){
        u32 ah[4][4], al[4][4], bb[4][2];
#pragma unroll
        for (int mt=0;mt<4;mt++){
            u32 ra = sb + ((warpM*64+mt*16+lr)*72 + kb + lc8)*2;
            ldsm4(ah[mt][0],ah[mt][1],ah[mt][2],ah[mt][3], ra + SC_QH);
            ldsm4(al[mt][0],al[mt][1],al[mt][2],al[mt][3], ra + SC_QL);
        }
#pragma unroll
        for (int gg=0;gg<2;gg++){
            u32 rb = sb + SC_K + ((warpN*32+gg*16+lr)*72 + kb + lc8)*2;
            u32 r0r,r1r,r2r,r3r;
            ldsm4(r0r,r1r,r2r,r3r, rb);
            bb[2*gg][0]=r0r; bb[2*gg][1]=r2r; bb[2*gg+1][0]=r1r; bb[2*gg+1][1]=r3r;
        }
#pragma unroll
        for (int mt=0;mt<4;mt++)
#pragma unroll
            for (int nt=0;nt<4;nt++){
                mma16816(acc[mt][nt], ah[mt], bb[nt][0], bb[nt][1]);
                mma16816(acc[mt][nt], al[mt], bb[nt][0], bb[nt][1]);
            }
    }

    // ---- phase 2: pe via T = Q DE^T (x1), 4 prefetched chunks ----
    for (int c=0;c<4;c++){
        int t0c = 64*c;
        float Tacc[4][2][4];
#pragma unroll
        for (int i=0;i<4;i++)
#pragma unroll
            for (int j=0;j<2;j++)
#pragma unroll
                for (int q=0;q<4;q++) Tacc[i][j][q]=0.f;

        CP_WAIT(0);
        __syncthreads();           // DE chunk c visible; Ql/K reads done
#pragma unroll
        for (int kb=0;kb<64;kb+=16){
            u32 ah[4][4];
#pragma unroll
            for (int mt=0;mt<4;mt++)
                ldsm4(ah[mt][0],ah[mt][1],ah[mt][2],ah[mt][3],
                      sb + SC_QH + ((warpM*64+mt*16+lr)*72 + kb + lc8)*2);
            u32 r0r,r1r,r2r,r3r;
            ldsm4(r0r,r1r,r2r,r3r, sb + SC_DE + ((warpN*16+lr)*72 + kb + lc8)*2);
#pragma unroll
            for (int mt=0;mt<4;mt++){
                mma16816(Tacc[mt][0], ah[mt], r0r, r2r);
                mma16816(Tacc[mt][1], ah[mt], r1r, r3r);
            }
        }
        __syncthreads();           // sDE reads done
        if (c < 3) { load_de(c+1); CP_COMMIT(); }

#pragma unroll
        for (int mt=0;mt<4;mt++)
#pragma unroll
            for (int n2=0;n2<2;n2++){
                int col = warpN*16 + n2*8 + 2*t;
                int rw = warpM*64 + mt*16 + g;
                *(float2*)&sT[rw*66 + col]     = make_float2(Tacc[mt][n2][0], Tacc[mt][n2][1]);
                *(float2*)&sT[(rw+8)*66 + col] = make_float2(Tacc[mt][n2][2], Tacc[mt][n2][3]);
            }
        __syncthreads();
#pragma unroll
        for (int mt=0;mt<4;mt++){
            int ib = warpM*64 + mt*16 + g;
#pragma unroll
            for (int nt=0;nt<4;nt++){
                int jb0 = warpN*32 + nt*8 + 2*t;
#pragma unroll
                for (int cr=0;cr<4;cr++){
                    int i = ib + (cr>>1)*8, j = jb0 + (cr&1);
                    int tt = i - j + 127 - t0c;
                    if ((unsigned)tt < 64u) acc[mt][nt][cr] += sT[i*66 + tt];
                }
            }
        }
        __syncthreads();
    }

    float* outp = g_sc + (size_t)bh*SS*SS;
#pragma unroll
    for (int mt=0;mt<4;mt++){
        int i0 = l0 + warpM*64 + mt*16 + g;
#pragma unroll
        for (int nt=0;nt<4;nt++){
            int jc = r0 + warpN*32 + nt*8 + 2*t;
            float2 mk = *(const float2*)&mask[b_*SS + jc];
            *(float2*)&outp[(size_t)i0*SS + jc] =
                make_float2(fmaf(acc[mt][nt][0],0.125f,mk.x), fmaf(acc[mt][nt][1],0.125f,mk.y));
            *(float2*)&outp[(size_t)(i0+8)*SS + jc] =
                make_float2(fmaf(acc[mt][nt][2],0.125f,mk.x), fmaf(acc[mt][nt][3],0.125f,mk.y));
        }
    }
}

// ============================================================================
// K3: stochastic double softmax, warp-per-row; probs out as fp16 hi/lo.
// ============================================================================
__device__ __forceinline__ float fast_neglog(float u)
{
    float up = u + 1e-10f;
    float d  = up - 1.0f;
    float p = d*(1.f + d*(-0.5f + d*(0.33333333f + d*(-0.25f + d*0.2f))));
    float lg = __logf(up);
    float l = (d > -0.03125f) ? p : lg;
    return 1e-10f - l;
}

__global__ __launch_bounds__(256)
void softmax_warp(const float* __restrict__ gum)
{
    const int tid = threadIdx.x, lane = tid & 31, w = tid >> 5;
    const size_t row = (size_t)blockIdx.x * 8 + w;
    const float* srow = g_sc + row * SS;
    const float* urow = gum + row * SS;

    float s[32], n[32];
#pragma unroll
    for (int j = 0; j < 8; j++) {
        float4 v = *(const float4*)&srow[(j*32 + lane)*4];
        s[j*4+0]=v.x; s[j*4+1]=v.y; s[j*4+2]=v.z; s[j*4+3]=v.w;
        float4 u = *(const float4*)&urow[(j*32 + lane)*4];
        n[j*4+0] = fast_neglog(u.x);
        n[j*4+1] = fast_neglog(u.y);
        n[j*4+2] = fast_neglog(u.z);
        n[j*4+3] = fast_neglog(u.w);
    }
    float m = s[0];
#pragma unroll
    for (int i = 1; i < 32; i++) m = fmaxf(m, s[i]);
#pragma unroll
    for (int o = 16; o; o >>= 1) m = fmaxf(m, __shfl_xor_sync(0xffffffffu, m, o));

    float sm1 = 0.f;
#pragma unroll
    for (int i = 0; i < 32; i++) {
        s[i] = __expf(s[i] - m);
        n[i] = __fdividef(s[i], n[i]);
        sm1 += n[i];
    }
#pragma unroll
    for (int o = 16; o; o >>= 1) sm1 += __shfl_xor_sync(0xffffffffu, sm1, o);
    float inv1 = __fdividef(1.0f, sm1);

    float sm2 = 0.f;
#pragma unroll
    for (int i = 0; i < 32; i++) {
        n[i] = s[i] * __expf(fmaf(n[i], inv1, -1.0f));
        sm2 += n[i];
    }
#pragma unroll
    for (int o = 16; o; o >>= 1) sm2 += __shfl_xor_sync(0xffffffffu, sm2, o);
    float inv2 = __fdividef(1.0f, sm2);

#pragma unroll
    for (int j = 0; j < 8; j++) {
        float a = n[j*4+0]*inv2, b = n[j*4+1]*inv2, c = n[j*4+2]*inv2, d = n[j*4+3]*inv2;
        size_t o = row*SS + (j*32 + lane)*4;
        *(uint2*)&g_phi[o] = make_uint2(pack2h(a,b), pack2h(c,d));
        *(uint2*)&g_plo[o] = make_uint2(pack2l(a,b), pack2l(c,d));
    }
}

// ============================================================================
// K4: out = P @ V (fp16 x2: P hi/lo, V single), cp.async 2-stage, 2 CTAs/SM.
// stage (25088B): Ph(10240) Pl(10240) V(4608).
// ============================================================================
#define PV_SMEM (2*25088)
__global__ __launch_bounds__(256, 2)
void pv_mma(float* __restrict__ out)
{
    extern __shared__ __align__(16) char smem[];
    const u32 sb = sptr(smem);

    const int tid = threadIdx.x, wid = tid>>5, lane = tid&31;
    const int warpM = wid>>1, warpN = wid&1;
    const int bh = blockIdx.y, l0 = blockIdx.x*128;
    const int b_ = bh>>4, h = bh&15;
    const int lr = lane&15, lc8 = (lane>>4)*8, g = lane>>2, t = lane&3;

    const hf* Ph = g_phi + (size_t)bh*SS*SS;
    const hf* Pl = g_plo + (size_t)bh*SS*SS;
    const hf* V  = g_v   + (size_t)bh*SS*HDD;

    auto load_stage = [&](int st, int k0){
        const u32 base = sb + st*25088;
#pragma unroll
        for (int rep=0;rep<4;rep++){
            int idx = rep*256 + tid;
            int mat = idx >> 9, rem = idx & 511;
            int row = rem >> 2, s4 = rem & 3;
            const hf* srcp = (mat==0) ? &Ph[(size_t)(l0+row)*1024 + k0 + s4*8]
                                      : &Pl[(size_t)(l0+row)*1024 + k0 + s4*8];
            CP16(base + mat*10240 + row*80 + s4*16, srcp);
        }
        {   // V: 256 transfers
            int row = tid >> 3, s8 = tid & 7;
            CP16(base + 20480 + row*144 + s8*16, &V[(size_t)(k0+row)*64 + s8*8]);
        }
    };

    float acc[2][4][4];
#pragma unroll
    for (int i=0;i<2;i++)
#pragma unroll
        for (int j=0;j<4;j++)
#pragma unroll
            for (int c=0;c<4;c++) acc[i][j][c]=0.f;

    load_stage(0, 0); CP_COMMIT();

    for (int c = 0; c < 32; c++) {
        if (c < 31) { load_stage((c+1)&1, (c+1)*32); CP_COMMIT(); CP_WAIT(1); }
        else        { CP_WAIT(0); }
        __syncthreads();
        const u32 st = sb + (c&1)*25088;
#pragma unroll
        for (int kb=0;kb<32;kb+=16){
            u32 ah[2][4], al[2][4], bb[4][2];
#pragma unroll
            for (int mt=0;mt<2;mt++){
                u32 ra = st + ((warpM*32+mt*16+lr)*40 + kb + lc8)*2;
                ldsm4(ah[mt][0],ah[mt][1],ah[mt][2],ah[mt][3], ra);
                ldsm4(al[mt][0],al[mt][1],al[mt][2],al[mt][3], ra + 10240);
            }
#pragma unroll
            for (int gg=0;gg<2;gg++){
                u32 rb = st + 20480 + ((kb+lr)*72 + warpN*32 + gg*16 + lc8)*2;
                u32 r0,r1,r2,r3;
                ldsm4t(r0,r1,r2,r3, rb);
                bb[2*gg][0]=r0; bb[2*gg][1]=r1; bb[2*gg+1][0]=r2; bb[2*gg+1][1]=r3;
            }
#pragma unroll
            for (int mt=0;mt<2;mt++)
#pragma unroll
                for (int nt=0;nt<4;nt++){
                    mma16816(acc[mt][nt], ah[mt], bb[nt][0], bb[nt][1]);
                    mma16816(acc[mt][nt], al[mt], bb[nt][0], bb[nt][1]);
                }
        }
        __syncthreads();
    }

#pragma unroll
    for (int mt=0;mt<2;mt++)
#pragma unroll
        for (int nt=0;nt<4;nt++){
            int dcol = warpN*32 + nt*8 + 2*t;
#pragma unroll
            for (int rr=0;rr<2;rr++){
                int l = l0 + warpM*32 + mt*16 + g + rr*8;
                *(float2*)&out[((size_t)(b_*SS)+l)*1024 + h*64 + dcol] =
                    make_float2(acc[mt][nt][rr*2+0], acc[mt][nt][rr*2+1]);
            }
        }
}

// ============================================================================
extern "C" void kernel_launch(void* const* d_in, const int* in_sizes, int n_in,
                              void* d_out, int out_size)
{
    const float* hidden = (const float*)d_in[0];
    const float* mask   = (const float*)d_in[1];
    const float* gum    = (const float*)d_in[2];
    const float* Wq     = (const float*)d_in[3];
    const float* bq     = (const float*)d_in[4];
    const float* Wk     = (const float*)d_in[5];
    const float* bk     = (const float*)d_in[6];
    const float* Wv     = (const float*)d_in[7];
    const float* bv     = (const float*)d_in[8];
    const float* de     = (const float*)d_in[9];
    float* out = (float*)d_out;

    static int configured = 0;
    if (!configured) {
        cudaFuncSetAttribute(qkv_mma,    cudaFuncAttributeMaxDynamicSharedMemorySize, QKV_SMEM);
        cudaFuncSetAttribute(scores_mma, cudaFuncAttributeMaxDynamicSharedMemorySize, SC_SMEM);
        cudaFuncSetAttribute(pv_mma,     cudaFuncAttributeMaxDynamicSharedMemorySize, PV_SMEM);
        configured = 1;
    }

    cvt_kernel<<<5249, 256>>>(hidden, Wq, Wk, Wv, de);
    qkv_mma<<<dim3(8, 16, 3), 256, QKV_SMEM>>>(bq, bk, bv);
    scores_mma<<<dim3(8, 8, 32), 256, SC_SMEM>>>(mask);
    softmax_warp<<<4096, 256>>>(gum);
    pv_mma<<<dim3(8, 32), 256, PV_SMEM>>>(out);
}

// round 9
// speedup vs baseline: 1.6420x; 1.0689x over previous
#include <cuda_runtime.h>
#include <cuda_fp16.h>
#include <math.h>

typedef unsigned int u32;
typedef __half hf;

#define SS 1024
#define HH 16
#define HDD 64
#define NBH 32

// ---------------- scratch (device globals) ----------------
__device__ hf g_xhi[2048*1024], g_xlo[2048*1024];
__device__ hf g_w[3*1024*1024];
__device__ hf g_de[2047*64];
__device__ hf g_qhi[NBH*SS*HDD], g_qlo[NBH*SS*HDD];
__device__ hf g_k[NBH*SS*HDD];
__device__ hf g_v[NBH*SS*HDD];
__device__ hf g_p[(size_t)NBH*SS*SS];
__device__ float g_sc[(size_t)NBH*SS*SS];

// ---------------- helpers ----------------
__device__ __forceinline__ u32 sptr(const void* p){ return (u32)__cvta_generic_to_shared(p); }
__device__ __forceinline__ void ldsm4(u32& r0,u32& r1,u32& r2,u32& r3,u32 a){
    asm volatile("ldmatrix.sync.aligned.m8n8.x4.shared.b16 {%0,%1,%2,%3},[%4];"
                 :"=r"(r0),"=r"(r1),"=r"(r2),"=r"(r3):"r"(a));
}
__device__ __forceinline__ void ldsm4t(u32& r0,u32& r1,u32& r2,u32& r3,u32 a){
    asm volatile("ldmatrix.sync.aligned.m8n8.x4.trans.shared.b16 {%0,%1,%2,%3},[%4];"
                 :"=r"(r0),"=r"(r1),"=r"(r2),"=r"(r3):"r"(a));
}
__device__ __forceinline__ void mma16816(float (&c)[4], const u32 (&a)[4], u32 b0, u32 b1){
    asm volatile("mma.sync.aligned.m16n8k16.row.col.f32.f16.f16.f32 "
                 "{%0,%1,%2,%3},{%4,%5,%6,%7},{%8,%9},{%0,%1,%2,%3};"
                 :"+f"(c[0]),"+f"(c[1]),"+f"(c[2]),"+f"(c[3])
                 :"r"(a[0]),"r"(a[1]),"r"(a[2]),"r"(a[3]),"r"(b0),"r"(b1));
}
__device__ __forceinline__ u32 pack2h(float a, float b){
    __half2 t; t.x=__float2half_rn(a); t.y=__float2half_rn(b);
    return *(u32*)&t;
}
__device__ __forceinline__ u32 pack2l(float a, float b){
    float ah = __half2float(__float2half_rn(a));
    float bh = __half2float(__float2half_rn(b));
    __half2 t; t.x=__float2half_rn(a-ah); t.y=__float2half_rn(b-bh);
    return *(u32*)&t;
}

#define CP16(dst, src) \
    asm volatile("cp.async.cg.shared.global [%0], [%1], 16;" :: "r"(dst), "l"(src))
#define CP_COMMIT() asm volatile("cp.async.commit_group;" ::: "memory")
#define CP_WAIT(n)  asm volatile("cp.async.wait_group %0;" :: "n"(n) : "memory")

// ============================================================================
// K0: fp32 -> fp16 conversion. X -> hi/lo split; W, de -> single fp16.
// ============================================================================
__global__ __launch_bounds__(256)
void cvt_kernel(const float* __restrict__ X, const float* __restrict__ Wq,
                const float* __restrict__ Wk, const float* __restrict__ Wv,
                const float* __restrict__ de)
{
    int i = blockIdx.x * 256 + threadIdx.x;
    if (i >= 1343472) return;
    if (i < 524288) {
        float4 v = *(const float4*)(X + (size_t)i * 4);
        *(uint2*)(g_xhi + (size_t)i*4) = make_uint2(pack2h(v.x,v.y), pack2h(v.z,v.w));
        *(uint2*)(g_xlo + (size_t)i*4) = make_uint2(pack2l(v.x,v.y), pack2l(v.z,v.w));
        return;
    }
    const float* src; hf* dst; int off;
    if (i < 1310720) {
        off = i - 524288;
        int wsel = off >> 18;
        src = (wsel==0)?Wq:(wsel==1)?Wk:Wv;
        dst = g_w + (size_t)(off >> 18) * 1048576;
        off &= 262143;
    } else {
        off = i - 1310720; src = de; dst = g_de;
    }
    float4 v = *(const float4*)(src + (size_t)off * 4);
    *(uint2*)(dst + (size_t)off*4) = make_uint2(pack2h(v.x,v.y), pack2h(v.z,v.w));
}

// ============================================================================
// K1: q/k/v = X @ W^T + b (fp16 x2: Xhi/Xlo split, W single).
// CTA 128m x 128n, BK=32, 8 warps (2m x 4n), cp.async 2-stage, 2 CTAs/SM.
// ============================================================================
#define QKV_SMEM (2*30720)
__global__ __launch_bounds__(256, 2)
void qkv_mma(const float* __restrict__ bq, const float* __restrict__ bk,
             const float* __restrict__ bv)
{
    extern __shared__ __align__(16) char smem[];
    const u32 sb = sptr(smem);

    const int tid = threadIdx.x, wid = tid>>5, lane = tid&31;
    const int warpM = wid>>2, warpN = wid&3;
    const int z = blockIdx.z, n0 = blockIdx.x*128, m0 = blockIdx.y*128;
    const int lr = lane&15, lc8 = (lane>>4)*8, g = lane>>2, t = lane&3;

    const hf* B = g_w + (size_t)z*1048576;
    const float* bias = (z==0)?bq:(z==1)?bk:bv;
    hf* dhi = (z==0)?g_qhi:(z==1)?g_k:g_v;
    const bool wlo = (z==0);

    float acc[4][4][4];
#pragma unroll
    for (int i=0;i<4;i++)
#pragma unroll
        for (int j=0;j<4;j++)
#pragma unroll
            for (int c=0;c<4;c++) acc[i][j][c]=0.f;

    auto load_stage = [&](int st, int k0){
        const u32 base = sb + st*30720;
#pragma unroll
        for (int rep=0;rep<6;rep++){
            int idx = rep*256 + tid;
            int mat = idx >> 9, rem = idx & 511;
            int row = rem >> 2, s4 = rem & 3;
            u32 dst = base + mat*10240 + row*80 + s4*16;
            const hf* srcp =
                (mat==0) ? &g_xhi[(size_t)(m0+row)*1024 + k0 + s4*8] :
                (mat==1) ? &g_xlo[(size_t)(m0+row)*1024 + k0 + s4*8] :
                           &B[(size_t)(n0+row)*1024 + k0 + s4*8];
            CP16(dst, srcp);
        }
    };

    load_stage(0, 0); CP_COMMIT();

    for (int c = 0; c < 32; c++) {
        if (c < 31) { load_stage((c+1)&1, (c+1)*32); CP_COMMIT(); CP_WAIT(1); }
        else        { CP_WAIT(0); }
        __syncthreads();
        const u32 st = sb + (c&1)*30720;
#pragma unroll
        for (int kb=0;kb<32;kb+=16){
            u32 ah[4][4], al[4][4], bb[4][2];
#pragma unroll
            for (int mt=0;mt<4;mt++){
                u32 ra = st + ((warpM*64+mt*16+lr)*40 + kb + lc8)*2;
                ldsm4(ah[mt][0],ah[mt][1],ah[mt][2],ah[mt][3], ra);
                ldsm4(al[mt][0],al[mt][1],al[mt][2],al[mt][3], ra + 10240);
            }
#pragma unroll
            for (int gg=0;gg<2;gg++){
                u32 rb = st + 20480 + ((warpN*32+gg*16+lr)*40 + kb + lc8)*2;
                u32 r0,r1,r2,r3;
                ldsm4(r0,r1,r2,r3, rb);
                bb[2*gg][0]=r0; bb[2*gg][1]=r2; bb[2*gg+1][0]=r1; bb[2*gg+1][1]=r3;
            }
#pragma unroll
            for (int mt=0;mt<4;mt++)
#pragma unroll
                for (int nt=0;nt<4;nt++){
                    mma16816(acc[mt][nt], ah[mt], bb[nt][0], bb[nt][1]);
                    mma16816(acc[mt][nt], al[mt], bb[nt][0], bb[nt][1]);
                }
        }
        __syncthreads();
    }

#pragma unroll
    for (int mt=0;mt<4;mt++)
#pragma unroll
        for (int nt=0;nt<4;nt++){
            int ncol = n0 + warpN*32 + nt*8 + 2*t;
            float b0 = bias[ncol], b1 = bias[ncol+1];
            int h = ncol>>6, dd = ncol&63;
#pragma unroll
            for (int rr=0;rr<2;rr++){
                int m = m0 + warpM*64 + mt*16 + g + rr*8;
                int b_ = m>>10, l = m&1023;
                float v0 = acc[mt][nt][rr*2+0] + b0;
                float v1 = acc[mt][nt][rr*2+1] + b1;
                size_t o = (((size_t)(b_*HH + h))*SS + l)*HDD + dd;
                *(u32*)&dhi[o] = pack2h(v0, v1);
                if (wlo) *(u32*)&g_qlo[o] = pack2l(v0, v1);
            }
        }
}

// ============================================================================
// K2: scores = (q k^T)[fp16 x2] + Toeplitz(Q DE^T)[x1], *0.125 + mask -> f32
// ============================================================================
#define SC_SMEM 64512
#define SC_QH 0
#define SC_QL 18432
#define SC_K  36864
#define SC_DE 55296
#define SC_T  18432
__global__ __launch_bounds__(256, 2)
void scores_mma(const float* __restrict__ mask)
{
    extern __shared__ __align__(16) char smem[];
    const u32 sb = sptr(smem);
    float* sT = (float*)(smem + SC_T);

    const int tid = threadIdx.x, wid = tid>>5, lane = tid&31;
    const int warpM = wid>>2, warpN = wid&3;
    const int bh = blockIdx.z, l0 = blockIdx.y*128, r0 = blockIdx.x*128;
    const int b_ = bh>>4;
    const int jb = l0 - r0 + 896;
    const int lr = lane&15, lc8 = (lane>>4)*8, g = lane>>2, t = lane&3;

    const hf* qh = g_qhi + (size_t)bh*SS*HDD;
    const hf* ql = g_qlo + (size_t)bh*SS*HDD;
    const hf* kk = g_k   + (size_t)bh*SS*HDD;

    auto load_de = [&](int cchunk){
#pragma unroll
        for (int rep=0;rep<2;rep++){
            int idx = rep*256 + tid;
            int row = idx >> 3, s8 = idx & 7;
            int der = jb + cchunk*64 + row; if (der > 2046) der = 2046;
            CP16(sb + SC_DE + row*144 + s8*16, &g_de[(size_t)der*64 + s8*8]);
        }
    };

#pragma unroll
    for (int rep=0;rep<12;rep++){
        int idx = rep*256 + tid;
        int mat = idx >> 10, rem = idx & 1023;
        int row = rem >> 3, s8 = rem & 7;
        u32 dst = sb + mat*18432 + row*144 + s8*16;
        const hf* srcp =
            (mat==0) ? &qh[(size_t)(l0+row)*64 + s8*8] :
            (mat==1) ? &ql[(size_t)(l0+row)*64 + s8*8] :
                       &kk[(size_t)(r0+row)*64 + s8*8];
        CP16(dst, srcp);
    }
    CP_COMMIT();
    load_de(0); CP_COMMIT();

    float acc[4][4][4];
#pragma unroll
    for (int i=0;i<4;i++)
#pragma unroll
        for (int j=0;j<4;j++)
#pragma unroll
            for (int c=0;c<4;c++) acc[i][j][c]=0.f;

    CP_WAIT(1);
    __syncthreads();

    // ---- phase 1: qk^T (x2) ----
#pragma unroll
    for (int kb=0;kb<64;kb+=16){
        u32 ah[4][4], al[4][4], bb[4][2];
#pragma unroll
        for (int mt=0;mt<4;mt++){
            u32 ra = sb + ((warpM*64+mt*16+lr)*72 + kb + lc8)*2;
            ldsm4(ah[mt][0],ah[mt][1],ah[mt][2],ah[mt][3], ra + SC_QH);
            ldsm4(al[mt][0],al[mt][1],al[mt][2],al[mt][3], ra + SC_QL);
        }
#pragma unroll
        for (int gg=0;gg<2;gg++){
            u32 rb = sb + SC_K + ((warpN*32+gg*16+lr)*72 + kb + lc8)*2;
            u32 r0r,r1r,r2r,r3r;
            ldsm4(r0r,r1r,r2r,r3r, rb);
            bb[2*gg][0]=r0r; bb[2*gg][1]=r2r; bb[2*gg+1][0]=r1r; bb[2*gg+1][1]=r3r;
        }
#pragma unroll
        for (int mt=0;mt<4;mt++)
#pragma unroll
            for (int nt=0;nt<4;nt++){
                mma16816(acc[mt][nt], ah[mt], bb[nt][0], bb[nt][1]);
                mma16816(acc[mt][nt], al[mt], bb[nt][0], bb[nt][1]);
            }
    }

    // ---- phase 2: pe via T = Q DE^T (x1), 4 prefetched chunks ----
    for (int c=0;c<4;c++){
        int t0c = 64*c;
        float Tacc[4][2][4];
#pragma unroll
        for (int i=0;i<4;i++)
#pragma unroll
            for (int j=0;j<2;j++)
#pragma unroll
                for (int q=0;q<4;q++) Tacc[i][j][q]=0.f;

        CP_WAIT(0);
        __syncthreads();
#pragma unroll
        for (int kb=0;kb<64;kb+=16){
            u32 ah[4][4];
#pragma unroll
            for (int mt=0;mt<4;mt++)
                ldsm4(ah[mt][0],ah[mt][1],ah[mt][2],ah[mt][3],
                      sb + SC_QH + ((warpM*64+mt*16+lr)*72 + kb + lc8)*2);
            u32 r0r,r1r,r2r,r3r;
            ldsm4(r0r,r1r,r2r,r3r, sb + SC_DE + ((warpN*16+lr)*72 + kb + lc8)*2);
#pragma unroll
            for (int mt=0;mt<4;mt++){
                mma16816(Tacc[mt][0], ah[mt], r0r, r2r);
                mma16816(Tacc[mt][1], ah[mt], r1r, r3r);
            }
        }
        __syncthreads();
        if (c < 3) { load_de(c+1); CP_COMMIT(); }

#pragma unroll
        for (int mt=0;mt<4;mt++)
#pragma unroll
            for (int n2=0;n2<2;n2++){
                int col = warpN*16 + n2*8 + 2*t;
                int rw = warpM*64 + mt*16 + g;
                *(float2*)&sT[rw*66 + col]     = make_float2(Tacc[mt][n2][0], Tacc[mt][n2][1]);
                *(float2*)&sT[(rw+8)*66 + col] = make_float2(Tacc[mt][n2][2], Tacc[mt][n2][3]);
            }
        __syncthreads();
#pragma unroll
        for (int mt=0;mt<4;mt++){
            int ib = warpM*64 + mt*16 + g;
#pragma unroll
            for (int nt=0;nt<4;nt++){
                int jb0 = warpN*32 + nt*8 + 2*t;
#pragma unroll
                for (int cr=0;cr<4;cr++){
                    int i = ib + (cr>>1)*8, j = jb0 + (cr&1);
                    int tt = i - j + 127 - t0c;
                    if ((unsigned)tt < 64u) acc[mt][nt][cr] += sT[i*66 + tt];
                }
            }
        }
        __syncthreads();
    }

    float* outp = g_sc + (size_t)bh*SS*SS;
#pragma unroll
    for (int mt=0;mt<4;mt++){
        int i0 = l0 + warpM*64 + mt*16 + g;
#pragma unroll
        for (int nt=0;nt<4;nt++){
            int jc = r0 + warpN*32 + nt*8 + 2*t;
            float2 mk = *(const float2*)&mask[b_*SS + jc];
            *(float2*)&outp[(size_t)i0*SS + jc] =
                make_float2(fmaf(acc[mt][nt][0],0.125f,mk.x), fmaf(acc[mt][nt][1],0.125f,mk.y));
            *(float2*)&outp[(size_t)(i0+8)*SS + jc] =
                make_float2(fmaf(acc[mt][nt][2],0.125f,mk.x), fmaf(acc[mt][nt][3],0.125f,mk.y));
        }
    }
}

// ============================================================================
// K3: stochastic double softmax, warp-per-row; probs out as SINGLE fp16.
// ============================================================================
__device__ __forceinline__ float fast_neglog(float u)
{
    float up = u + 1e-10f;
    float d  = up - 1.0f;
    float p = d*(1.f + d*(-0.5f + d*(0.33333333f + d*(-0.25f + d*0.2f))));
    float lg = __logf(up);
    float l = (d > -0.03125f) ? p : lg;
    return 1e-10f - l;
}

__global__ __launch_bounds__(256)
void softmax_warp(const float* __restrict__ gum)
{
    const int tid = threadIdx.x, lane = tid & 31, w = tid >> 5;
    const size_t row = (size_t)blockIdx.x * 8 + w;
    const float* srow = g_sc + row * SS;
    const float* urow = gum + row * SS;

    float s[32], n[32];
#pragma unroll
    for (int j = 0; j < 8; j++) {
        float4 v = *(const float4*)&srow[(j*32 + lane)*4];
        s[j*4+0]=v.x; s[j*4+1]=v.y; s[j*4+2]=v.z; s[j*4+3]=v.w;
        float4 u = *(const float4*)&urow[(j*32 + lane)*4];
        n[j*4+0] = fast_neglog(u.x);
        n[j*4+1] = fast_neglog(u.y);
        n[j*4+2] = fast_neglog(u.z);
        n[j*4+3] = fast_neglog(u.w);
    }
    float m = s[0];
#pragma unroll
    for (int i = 1; i < 32; i++) m = fmaxf(m, s[i]);
#pragma unroll
    for (int o = 16; o; o >>= 1) m = fmaxf(m, __shfl_xor_sync(0xffffffffu, m, o));

    float sm1 = 0.f;
#pragma unroll
    for (int i = 0; i < 32; i++) {
        s[i] = __expf(s[i] - m);
        n[i] = __fdividef(s[i], n[i]);
        sm1 += n[i];
    }
#pragma unroll
    for (int o = 16; o; o >>= 1) sm1 += __shfl_xor_sync(0xffffffffu, sm1, o);
    float inv1 = __fdividef(1.0f, sm1);

    float sm2 = 0.f;
#pragma unroll
    for (int i = 0; i < 32; i++) {
        n[i] = s[i] * __expf(fmaf(n[i], inv1, -1.0f));
        sm2 += n[i];
    }
#pragma unroll
    for (int o = 16; o; o >>= 1) sm2 += __shfl_xor_sync(0xffffffffu, sm2, o);
    float inv2 = __fdividef(1.0f, sm2);

#pragma unroll
    for (int j = 0; j < 8; j++) {
        float a = n[j*4+0]*inv2, b = n[j*4+1]*inv2, c = n[j*4+2]*inv2, d = n[j*4+3]*inv2;
        *(uint2*)&g_p[row*SS + (j*32 + lane)*4] =
            make_uint2(pack2h(a,b), pack2h(c,d));
    }
}

// ============================================================================
// K4: out = P @ V (fp16 x1, P and V single), cp.async 2-stage, 3 CTAs/SM.
// stage (14848B): P(10240) V(4608).
// ============================================================================
#define PV_SMEM (2*14848)
__global__ __launch_bounds__(256, 3)
void pv_mma(float* __restrict__ out)
{
    extern __shared__ __align__(16) char smem[];
    const u32 sb = sptr(smem);

    const int tid = threadIdx.x, wid = tid>>5, lane = tid&31;
    const int warpM = wid>>1, warpN = wid&1;
    const int bh = blockIdx.y, l0 = blockIdx.x*128;
    const int b_ = bh>>4, h = bh&15;
    const int lr = lane&15, lc8 = (lane>>4)*8, g = lane>>2, t = lane&3;

    const hf* P = g_p + (size_t)bh*SS*SS;
    const hf* V = g_v + (size_t)bh*SS*HDD;

    auto load_stage = [&](int st, int k0){
        const u32 base = sb + st*14848;
#pragma unroll
        for (int rep=0;rep<2;rep++){
            int idx = rep*256 + tid;
            int row = idx >> 2, s4 = idx & 3;
            CP16(base + row*80 + s4*16, &P[(size_t)(l0+row)*1024 + k0 + s4*8]);
        }
        {
            int row = tid >> 3, s8 = tid & 7;
            CP16(base + 10240 + row*144 + s8*16, &V[(size_t)(k0+row)*64 + s8*8]);
        }
    };

    float acc[2][4][4];
#pragma unroll
    for (int i=0;i<2;i++)
#pragma unroll
        for (int j=0;j<4;j++)
#pragma unroll
            for (int c=0;c<4;c++) acc[i][j][c]=0.f;

    load_stage(0, 0); CP_COMMIT();

    for (int c = 0; c < 32; c++) {
        if (c < 31) { load_stage((c+1)&1, (c+1)*32); CP_COMMIT(); CP_WAIT(1); }
        else        { CP_WAIT(0); }
        __syncthreads();
        const u32 st = sb + (c&1)*14848;
#pragma unroll
        for (int kb=0;kb<32;kb+=16){
            u32 ah[2][4], bb[4][2];
#pragma unroll
            for (int mt=0;mt<2;mt++){
                u32 ra = st + ((warpM*32+mt*16+lr)*40 + kb + lc8)*2;
                ldsm4(ah[mt][0],ah[mt][1],ah[mt][2],ah[mt][3], ra);
            }
#pragma unroll
            for (int gg=0;gg<2;gg++){
                u32 rb = st + 10240 + ((kb+lr)*72 + warpN*32 + gg*16 + lc8)*2;
                u32 r0,r1,r2,r3;
                ldsm4t(r0,r1,r2,r3, rb);
                bb[2*gg][0]=r0; bb[2*gg][1]=r1; bb[2*gg+1][0]=r2; bb[2*gg+1][1]=r3;
            }
#pragma unroll
            for (int mt=0;mt<2;mt++)
#pragma unroll
                for (int nt=0;nt<4;nt++)
                    mma16816(acc[mt][nt], ah[mt], bb[nt][0], bb[nt][1]);
        }
        __syncthreads();
    }

#pragma unroll
    for (int mt=0;mt<2;mt++)
#pragma unroll
        for (int nt=0;nt<4;nt++){
            int dcol = warpN*32 + nt*8 + 2*t;
#pragma unroll
            for (int rr=0;rr<2;rr++){
                int l = l0 + warpM*32 + mt*16 + g + rr*8;
                *(float2*)&out[((size_t)(b_*SS)+l)*1024 + h*64 + dcol] =
                    make_float2(acc[mt][nt][rr*2+0], acc[mt][nt][rr*2+1]);
            }
        }
}

// ============================================================================
extern "C" void kernel_launch(void* const* d_in, const int* in_sizes, int n_in,
                              void* d_out, int out_size)
{
    const float* hidden = (const float*)d_in[0];
    const float* mask   = (const float*)d_in[1];
    const float* gum    = (const float*)d_in[2];
    const float* Wq     = (const float*)d_in[3];
    const float* bq     = (const float*)d_in[4];
    const float* Wk     = (const float*)d_in[5];
    const float* bk     = (const float*)d_in[6];
    const float* Wv     = (const float*)d_in[7];
    const float* bv     = (const float*)d_in[8];
    const float* de     = (const float*)d_in[9];
    float* out = (float*)d_out;

    static int configured = 0;
    if (!configured) {
        cudaFuncSetAttribute(qkv_mma,    cudaFuncAttributeMaxDynamicSharedMemorySize, QKV_SMEM);
        cudaFuncSetAttribute(scores_mma, cudaFuncAttributeMaxDynamicSharedMemorySize, SC_SMEM);
        cudaFuncSetAttribute(pv_mma,     cudaFuncAttributeMaxDynamicSharedMemorySize, PV_SMEM);
        configured = 1;
    }

    cvt_kernel<<<5249, 256>>>(hidden, Wq, Wk, Wv, de);
    qkv_mma<<<dim3(8, 16, 3), 256, QKV_SMEM>>>(bq, bk, bv);
    scores_mma<<<dim3(8, 8, 32), 256, SC_SMEM>>>(mask);
    softmax_warp<<<4096, 256>>>(gum);
    pv_mma<<<dim3(8, 32), 256, PV_SMEM>>>(out);
}

// round 10
// speedup vs baseline: 1.8980x; 1.1559x over previous
#include <cuda_runtime.h>
#include <cuda_fp16.h>
#include <math.h>

typedef unsigned int u32;
typedef __half hf;

#define SS 1024
#define HH 16
#define HDD 64
#define NBH 32

// ---------------- scratch (device globals) ----------------
__device__ hf g_x[2048*1024];
__device__ hf g_w[3*1024*1024];
__device__ hf g_de[2047*64];
__device__ hf g_qhi[NBH*SS*HDD], g_qlo[NBH*SS*HDD];
__device__ hf g_k[NBH*SS*HDD];
__device__ hf g_v[NBH*SS*HDD];
__device__ hf g_p[(size_t)NBH*SS*SS];
__device__ float g_sc[(size_t)NBH*SS*SS];

// ---------------- helpers ----------------
__device__ __forceinline__ u32 sptr(const void* p){ return (u32)__cvta_generic_to_shared(p); }
__device__ __forceinline__ void ldsm4(u32& r0,u32& r1,u32& r2,u32& r3,u32 a){
    asm volatile("ldmatrix.sync.aligned.m8n8.x4.shared.b16 {%0,%1,%2,%3},[%4];"
                 :"=r"(r0),"=r"(r1),"=r"(r2),"=r"(r3):"r"(a));
}
__device__ __forceinline__ void ldsm4t(u32& r0,u32& r1,u32& r2,u32& r3,u32 a){
    asm volatile("ldmatrix.sync.aligned.m8n8.x4.trans.shared.b16 {%0,%1,%2,%3},[%4];"
                 :"=r"(r0),"=r"(r1),"=r"(r2),"=r"(r3):"r"(a));
}
__device__ __forceinline__ void mma16816(float (&c)[4], const u32 (&a)[4], u32 b0, u32 b1){
    asm volatile("mma.sync.aligned.m16n8k16.row.col.f32.f16.f16.f32 "
                 "{%0,%1,%2,%3},{%4,%5,%6,%7},{%8,%9},{%0,%1,%2,%3};"
                 :"+f"(c[0]),"+f"(c[1]),"+f"(c[2]),"+f"(c[3])
                 :"r"(a[0]),"r"(a[1]),"r"(a[2]),"r"(a[3]),"r"(b0),"r"(b1));
}
__device__ __forceinline__ u32 pack2h(float a, float b){
    __half2 t; t.x=__float2half_rn(a); t.y=__float2half_rn(b);
    return *(u32*)&t;
}
__device__ __forceinline__ u32 pack2l(float a, float b){
    float ah = __half2float(__float2half_rn(a));
    float bh = __half2float(__float2half_rn(b));
    __half2 t; t.x=__float2half_rn(a-ah); t.y=__float2half_rn(b-bh);
    return *(u32*)&t;
}

#define CP16(dst, src) \
    asm volatile("cp.async.cg.shared.global [%0], [%1], 16;" :: "r"(dst), "l"(src))
#define CP_COMMIT() asm volatile("cp.async.commit_group;" ::: "memory")
#define CP_WAIT(n)  asm volatile("cp.async.wait_group %0;" :: "n"(n) : "memory")

// ============================================================================
// K0: fp32 -> fp16 (single rounding) for X, W, de.
// ranges: X[0,524288) W[..+786432) de[..+32752)
// ============================================================================
__global__ __launch_bounds__(256)
void cvt_kernel(const float* __restrict__ X, const float* __restrict__ Wq,
                const float* __restrict__ Wk, const float* __restrict__ Wv,
                const float* __restrict__ de)
{
    int i = blockIdx.x * 256 + threadIdx.x;
    if (i >= 1343472) return;
    const float* src; hf* dst; int off;
    if (i < 524288) {
        src = X; dst = g_x; off = i;
    } else if (i < 1310720) {
        off = i - 524288;
        int wsel = off >> 18;
        src = (wsel==0)?Wq:(wsel==1)?Wk:Wv;
        dst = g_w + (size_t)wsel * 1048576;
        off &= 262143;
    } else {
        off = i - 1310720; src = de; dst = g_de;
    }
    float4 v = *(const float4*)(src + (size_t)off * 4);
    *(uint2*)(dst + (size_t)off*4) = make_uint2(pack2h(v.x,v.y), pack2h(v.z,v.w));
}

// ============================================================================
// K1: q/k/v = X @ W^T + b (fp16 x1). CTA 128m x 128n, BK=32, 8 warps,
// cp.async 2-stage, 2 CTAs/SM. stage (20480B): A(10240) B(10240).
// q written hi/lo (from f32 acc); k,v single fp16.
// ============================================================================
#define QKV_SMEM (2*20480)
__global__ __launch_bounds__(256, 2)
void qkv_mma(const float* __restrict__ bq, const float* __restrict__ bk,
             const float* __restrict__ bv)
{
    extern __shared__ __align__(16) char smem[];
    const u32 sb = sptr(smem);

    const int tid = threadIdx.x, wid = tid>>5, lane = tid&31;
    const int warpM = wid>>2, warpN = wid&3;
    const int z = blockIdx.z, n0 = blockIdx.x*128, m0 = blockIdx.y*128;
    const int lr = lane&15, lc8 = (lane>>4)*8, g = lane>>2, t = lane&3;

    const hf* B = g_w + (size_t)z*1048576;
    const float* bias = (z==0)?bq:(z==1)?bk:bv;
    hf* dhi = (z==0)?g_qhi:(z==1)?g_k:g_v;
    const bool wlo = (z==0);

    float acc[4][4][4];
#pragma unroll
    for (int i=0;i<4;i++)
#pragma unroll
        for (int j=0;j<4;j++)
#pragma unroll
            for (int c=0;c<4;c++) acc[i][j][c]=0.f;

    auto load_stage = [&](int st, int k0){
        const u32 base = sb + st*20480;
#pragma unroll
        for (int rep=0;rep<4;rep++){
            int idx = rep*256 + tid;             // 0..1023
            int mat = idx >> 9, rem = idx & 511;
            int row = rem >> 2, s4 = rem & 3;
            u32 dst = base + mat*10240 + row*80 + s4*16;
            const hf* srcp =
                (mat==0) ? &g_x[(size_t)(m0+row)*1024 + k0 + s4*8]
                         : &B[(size_t)(n0+row)*1024 + k0 + s4*8];
            CP16(dst, srcp);
        }
    };

    load_stage(0, 0); CP_COMMIT();

    for (int c = 0; c < 32; c++) {
        if (c < 31) { load_stage((c+1)&1, (c+1)*32); CP_COMMIT(); CP_WAIT(1); }
        else        { CP_WAIT(0); }
        __syncthreads();
        const u32 st = sb + (c&1)*20480;
#pragma unroll
        for (int kb=0;kb<32;kb+=16){
            u32 ah[4][4], bb[4][2];
#pragma unroll
            for (int mt=0;mt<4;mt++){
                u32 ra = st + ((warpM*64+mt*16+lr)*40 + kb + lc8)*2;
                ldsm4(ah[mt][0],ah[mt][1],ah[mt][2],ah[mt][3], ra);
            }
#pragma unroll
            for (int gg=0;gg<2;gg++){
                u32 rb = st + 10240 + ((warpN*32+gg*16+lr)*40 + kb + lc8)*2;
                u32 r0,r1,r2,r3;
                ldsm4(r0,r1,r2,r3, rb);
                bb[2*gg][0]=r0; bb[2*gg][1]=r2; bb[2*gg+1][0]=r1; bb[2*gg+1][1]=r3;
            }
#pragma unroll
            for (int mt=0;mt<4;mt++)
#pragma unroll
                for (int nt=0;nt<4;nt++)
                    mma16816(acc[mt][nt], ah[mt], bb[nt][0], bb[nt][1]);
        }
        __syncthreads();
    }

#pragma unroll
    for (int mt=0;mt<4;mt++)
#pragma unroll
        for (int nt=0;nt<4;nt++){
            int ncol = n0 + warpN*32 + nt*8 + 2*t;
            float b0 = bias[ncol], b1 = bias[ncol+1];
            int h = ncol>>6, dd = ncol&63;
#pragma unroll
            for (int rr=0;rr<2;rr++){
                int m = m0 + warpM*64 + mt*16 + g + rr*8;
                int b_ = m>>10, l = m&1023;
                float v0 = acc[mt][nt][rr*2+0] + b0;
                float v1 = acc[mt][nt][rr*2+1] + b1;
                size_t o = (((size_t)(b_*HH + h))*SS + l)*HDD + dd;
                *(u32*)&dhi[o] = pack2h(v0, v1);
                if (wlo) *(u32*)&g_qlo[o] = pack2l(v0, v1);
            }
        }
}

// ============================================================================
// K2: scores = (q k^T)[fp16 x2: Q hi/lo, K single] + Toeplitz(Q DE^T)[x1],
// *0.125 + mask -> f32.  (unchanged, known good)
// ============================================================================
#define SC_SMEM 64512
#define SC_QH 0
#define SC_QL 18432
#define SC_K  36864
#define SC_DE 55296
#define SC_T  18432
__global__ __launch_bounds__(256, 2)
void scores_mma(const float* __restrict__ mask)
{
    extern __shared__ __align__(16) char smem[];
    const u32 sb = sptr(smem);
    float* sT = (float*)(smem + SC_T);

    const int tid = threadIdx.x, wid = tid>>5, lane = tid&31;
    const int warpM = wid>>2, warpN = wid&3;
    const int bh = blockIdx.z, l0 = blockIdx.y*128, r0 = blockIdx.x*128;
    const int b_ = bh>>4;
    const int jb = l0 - r0 + 896;
    const int lr = lane&15, lc8 = (lane>>4)*8, g = lane>>2, t = lane&3;

    const hf* qh = g_qhi + (size_t)bh*SS*HDD;
    const hf* ql = g_qlo + (size_t)bh*SS*HDD;
    const hf* kk = g_k   + (size_t)bh*SS*HDD;

    auto load_de = [&](int cchunk){
#pragma unroll
        for (int rep=0;rep<2;rep++){
            int idx = rep*256 + tid;
            int row = idx >> 3, s8 = idx & 7;
            int der = jb + cchunk*64 + row; if (der > 2046) der = 2046;
            CP16(sb + SC_DE + row*144 + s8*16, &g_de[(size_t)der*64 + s8*8]);
        }
    };

#pragma unroll
    for (int rep=0;rep<12;rep++){
        int idx = rep*256 + tid;
        int mat = idx >> 10, rem = idx & 1023;
        int row = rem >> 3, s8 = rem & 7;
        u32 dst = sb + mat*18432 + row*144 + s8*16;
        const hf* srcp =
            (mat==0) ? &qh[(size_t)(l0+row)*64 + s8*8] :
            (mat==1) ? &ql[(size_t)(l0+row)*64 + s8*8] :
                       &kk[(size_t)(r0+row)*64 + s8*8];
        CP16(dst, srcp);
    }
    CP_COMMIT();
    load_de(0); CP_COMMIT();

    float acc[4][4][4];
#pragma unroll
    for (int i=0;i<4;i++)
#pragma unroll
        for (int j=0;j<4;j++)
#pragma unroll
            for (int c=0;c<4;c++) acc[i][j][c]=0.f;

    CP_WAIT(1);
    __syncthreads();

    // ---- phase 1: qk^T (x2) ----
#pragma unroll
    for (int kb=0;kb<64;kb+=16){
        u32 ah[4][4], al[4][4], bb[4][2];
#pragma unroll
        for (int mt=0;mt<4;mt++){
            u32 ra = sb + ((warpM*64+mt*16+lr)*72 + kb + lc8)*2;
            ldsm4(ah[mt][0],ah[mt][1],ah[mt][2],ah[mt][3], ra + SC_QH);
            ldsm4(al[mt][0],al[mt][1],al[mt][2],al[mt][3], ra + SC_QL);
        }
#pragma unroll
        for (int gg=0;gg<2;gg++){
            u32 rb = sb + SC_K + ((warpN*32+gg*16+lr)*72 + kb + lc8)*2;
            u32 r0r,r1r,r2r,r3r;
            ldsm4(r0r,r1r,r2r,r3r, rb);
            bb[2*gg][0]=r0r; bb[2*gg][1]=r2r; bb[2*gg+1][0]=r1r; bb[2*gg+1][1]=r3r;
        }
#pragma unroll
        for (int mt=0;mt<4;mt++)
#pragma unroll
            for (int nt=0;nt<4;nt++){
                mma16816(acc[mt][nt], ah[mt], bb[nt][0], bb[nt][1]);
                mma16816(acc[mt][nt], al[mt], bb[nt][0], bb[nt][1]);
            }
    }

    // ---- phase 2: pe via T = Q DE^T (x1), 4 prefetched chunks ----
    for (int c=0;c<4;c++){
        int t0c = 64*c;
        float Tacc[4][2][4];
#pragma unroll
        for (int i=0;i<4;i++)
#pragma unroll
            for (int j=0;j<2;j++)
#pragma unroll
                for (int q=0;q<4;q++) Tacc[i][j][q]=0.f;

        CP_WAIT(0);
        __syncthreads();
#pragma unroll
        for (int kb=0;kb<64;kb+=16){
            u32 ah[4][4];
#pragma unroll
            for (int mt=0;mt<4;mt++)
                ldsm4(ah[mt][0],ah[mt][1],ah[mt][2],ah[mt][3],
                      sb + SC_QH + ((warpM*64+mt*16+lr)*72 + kb + lc8)*2);
            u32 r0r,r1r,r2r,r3r;
            ldsm4(r0r,r1r,r2r,r3r, sb + SC_DE + ((warpN*16+lr)*72 + kb + lc8)*2);
#pragma unroll
            for (int mt=0;mt<4;mt++){
                mma16816(Tacc[mt][0], ah[mt], r0r, r2r);
                mma16816(Tacc[mt][1], ah[mt], r1r, r3r);
            }
        }
        __syncthreads();
        if (c < 3) { load_de(c+1); CP_COMMIT(); }

#pragma unroll
        for (int mt=0;mt<4;mt++)
#pragma unroll
            for (int n2=0;n2<2;n2++){
                int col = warpN*16 + n2*8 + 2*t;
                int rw = warpM*64 + mt*16 + g;
                *(float2*)&sT[rw*66 + col]     = make_float2(Tacc[mt][n2][0], Tacc[mt][n2][1]);
                *(float2*)&sT[(rw+8)*66 + col] = make_float2(Tacc[mt][n2][2], Tacc[mt][n2][3]);
            }
        __syncthreads();
#pragma unroll
        for (int mt=0;mt<4;mt++){
            int ib = warpM*64 + mt*16 + g;
#pragma unroll
            for (int nt=0;nt<4;nt++){
                int jb0 = warpN*32 + nt*8 + 2*t;
#pragma unroll
                for (int cr=0;cr<4;cr++){
                    int i = ib + (cr>>1)*8, j = jb0 + (cr&1);
                    int tt = i - j + 127 - t0c;
                    if ((unsigned)tt < 64u) acc[mt][nt][cr] += sT[i*66 + tt];
                }
            }
        }
        __syncthreads();
    }

    float* outp = g_sc + (size_t)bh*SS*SS;
#pragma unroll
    for (int mt=0;mt<4;mt++){
        int i0 = l0 + warpM*64 + mt*16 + g;
#pragma unroll
        for (int nt=0;nt<4;nt++){
            int jc = r0 + warpN*32 + nt*8 + 2*t;
            float2 mk = *(const float2*)&mask[b_*SS + jc];
            *(float2*)&outp[(size_t)i0*SS + jc] =
                make_float2(fmaf(acc[mt][nt][0],0.125f,mk.x), fmaf(acc[mt][nt][1],0.125f,mk.y));
            *(float2*)&outp[(size_t)(i0+8)*SS + jc] =
                make_float2(fmaf(acc[mt][nt][2],0.125f,mk.x), fmaf(acc[mt][nt][3],0.125f,mk.y));
        }
    }
}

// ============================================================================
// K3: stochastic double softmax, warp-per-row; probs out as single fp16.
// ============================================================================
__device__ __forceinline__ float fast_neglog(float u)
{
    float up = u + 1e-10f;
    float d  = up - 1.0f;
    float p = d*(1.f + d*(-0.5f + d*(0.33333333f + d*(-0.25f + d*0.2f))));
    float lg = __logf(up);
    float l = (d > -0.03125f) ? p : lg;
    return 1e-10f - l;
}

__global__ __launch_bounds__(256)
void softmax_warp(const float* __restrict__ gum)
{
    const int tid = threadIdx.x, lane = tid & 31, w = tid >> 5;
    const size_t row = (size_t)blockIdx.x * 8 + w;
    const float* srow = g_sc + row * SS;
    const float* urow = gum + row * SS;

    float s[32], n[32];
#pragma unroll
    for (int j = 0; j < 8; j++) {
        float4 v = *(const float4*)&srow[(j*32 + lane)*4];
        s[j*4+0]=v.x; s[j*4+1]=v.y; s[j*4+2]=v.z; s[j*4+3]=v.w;
        float4 u = *(const float4*)&urow[(j*32 + lane)*4];
        n[j*4+0] = fast_neglog(u.x);
        n[j*4+1] = fast_neglog(u.y);
        n[j*4+2] = fast_neglog(u.z);
        n[j*4+3] = fast_neglog(u.w);
    }
    float m = s[0];
#pragma unroll
    for (int i = 1; i < 32; i++) m = fmaxf(m, s[i]);
#pragma unroll
    for (int o = 16; o; o >>= 1) m = fmaxf(m, __shfl_xor_sync(0xffffffffu, m, o));

    float sm1 = 0.f;
#pragma unroll
    for (int i = 0; i < 32; i++) {
        s[i] = __expf(s[i] - m);
        n[i] = __fdividef(s[i], n[i]);
        sm1 += n[i];
    }
#pragma unroll
    for (int o = 16; o; o >>= 1) sm1 += __shfl_xor_sync(0xffffffffu, sm1, o);
    float inv1 = __fdividef(1.0f, sm1);

    float sm2 = 0.f;
#pragma unroll
    for (int i = 0; i < 32; i++) {
        n[i] = s[i] * __expf(fmaf(n[i], inv1, -1.0f));
        sm2 += n[i];
    }
#pragma unroll
    for (int o = 16; o; o >>= 1) sm2 += __shfl_xor_sync(0xffffffffu, sm2, o);
    float inv2 = __fdividef(1.0f, sm2);

#pragma unroll
    for (int j = 0; j < 8; j++) {
        float a = n[j*4+0]*inv2, b = n[j*4+1]*inv2, c = n[j*4+2]*inv2, d = n[j*4+3]*inv2;
        *(uint2*)&g_p[row*SS + (j*32 + lane)*4] =
            make_uint2(pack2h(a,b), pack2h(c,d));
    }
}

// ============================================================================
// K4: out = P @ V (fp16 x1), cp.async 2-stage, 3 CTAs/SM.
// ============================================================================
#define PV_SMEM (2*14848)
__global__ __launch_bounds__(256, 3)
void pv_mma(float* __restrict__ out)
{
    extern __shared__ __align__(16) char smem[];
    const u32 sb = sptr(smem);

    const int tid = threadIdx.x, wid = tid>>5, lane = tid&31;
    const int warpM = wid>>1, warpN = wid&1;
    const int bh = blockIdx.y, l0 = blockIdx.x*128;
    const int b_ = bh>>4, h = bh&15;
    const int lr = lane&15, lc8 = (lane>>4)*8, g = lane>>2, t = lane&3;

    const hf* P = g_p + (size_t)bh*SS*SS;
    const hf* V = g_v + (size_t)bh*SS*HDD;

    auto load_stage = [&](int st, int k0){
        const u32 base = sb + st*14848;
#pragma unroll
        for (int rep=0;rep<2;rep++){
            int idx = rep*256 + tid;
            int row = idx >> 2, s4 = idx & 3;
            CP16(base + row*80 + s4*16, &P[(size_t)(l0+row)*1024 + k0 + s4*8]);
        }
        {
            int row = tid >> 3, s8 = tid & 7;
            CP16(base + 10240 + row*144 + s8*16, &V[(size_t)(k0+row)*64 + s8*8]);
        }
    };

    float acc[2][4][4];
#pragma unroll
    for (int i=0;i<2;i++)
#pragma unroll
        for (int j=0;j<4;j++)
#pragma unroll
            for (int c=0;c<4;c++) acc[i][j][c]=0.f;

    load_stage(0, 0); CP_COMMIT();

    for (int c = 0; c < 32; c++) {
        if (c < 31) { load_stage((c+1)&1, (c+1)*32); CP_COMMIT(); CP_WAIT(1); }
        else        { CP_WAIT(0); }
        __syncthreads();
        const u32 st = sb + (c&1)*14848;
#pragma unroll
        for (int kb=0;kb<32;kb+=16){
            u32 ah[2][4], bb[4][2];
#pragma unroll
            for (int mt=0;mt<2;mt++){
                u32 ra = st + ((warpM*32+mt*16+lr)*40 + kb + lc8)*2;
                ldsm4(ah[mt][0],ah[mt][1],ah[mt][2],ah[mt][3], ra);
            }
#pragma unroll
            for (int gg=0;gg<2;gg++){
                u32 rb = st + 10240 + ((kb+lr)*72 + warpN*32 + gg*16 + lc8)*2;
                u32 r0,r1,r2,r3;
                ldsm4t(r0,r1,r2,r3, rb);
                bb[2*gg][0]=r0; bb[2*gg][1]=r1; bb[2*gg+1][0]=r2; bb[2*gg+1][1]=r3;
            }
#pragma unroll
            for (int mt=0;mt<2;mt++)
#pragma unroll
                for (int nt=0;nt<4;nt++)
                    mma16816(acc[mt][nt], ah[mt], bb[nt][0], bb[nt][1]);
        }
        __syncthreads();
    }

#pragma unroll
    for (int mt=0;mt<2;mt++)
#pragma unroll
        for (int nt=0;nt<4;nt++){
            int dcol = warpN*32 + nt*8 + 2*t;
#pragma unroll
            for (int rr=0;rr<2;rr++){
                int l = l0 + warpM*32 + mt*16 + g + rr*8;
                *(float2*)&out[((size_t)(b_*SS)+l)*1024 + h*64 + dcol] =
                    make_float2(acc[mt][nt][rr*2+0], acc[mt][nt][rr*2+1]);
            }
        }
}

// ============================================================================
extern "C" void kernel_launch(void* const* d_in, const int* in_sizes, int n_in,
                              void* d_out, int out_size)
{
    const float* hidden = (const float*)d_in[0];
    const float* mask   = (const float*)d_in[1];
    const float* gum    = (const float*)d_in[2];
    const float* Wq     = (const float*)d_in[3];
    const float* bq     = (const float*)d_in[4];
    const float* Wk     = (const float*)d_in[5];
    const float* bk     = (const float*)d_in[6];
    const float* Wv     = (const float*)d_in[7];
    const float* bv     = (const float*)d_in[8];
    const float* de     = (const float*)d_in[9];
    float* out = (float*)d_out;

    static int configured = 0;
    if (!configured) {
        cudaFuncSetAttribute(qkv_mma,    cudaFuncAttributeMaxDynamicSharedMemorySize, QKV_SMEM);
        cudaFuncSetAttribute(scores_mma, cudaFuncAttributeMaxDynamicSharedMemorySize, SC_SMEM);
        cudaFuncSetAttribute(pv_mma,     cudaFuncAttributeMaxDynamicSharedMemorySize, PV_SMEM);
        configured = 1;
    }

    cvt_kernel<<<5249, 256>>>(hidden, Wq, Wk, Wv, de);
    qkv_mma<<<dim3(8, 16, 3), 256, QKV_SMEM>>>(bq, bk, bv);
    scores_mma<<<dim3(8, 8, 32), 256, SC_SMEM>>>(mask);
    softmax_warp<<<4096, 256>>>(gum);
    pv_mma<<<dim3(8, 32), 256, PV_SMEM>>>(out);
}

// round 11
// speedup vs baseline: 1.9584x; 1.0318x over previous
#include <cuda_runtime.h>
#include <cuda_fp16.h>
#include <math.h>

typedef unsigned int u32;
typedef __half hf;

#define SS 1024
#define HH 16
#define HDD 64
#define NBH 32

// ---------------- scratch (device globals) ----------------
__device__ hf g_x[2048*1024];
__device__ hf g_w[3*1024*1024];
__device__ hf g_de[2047*64];
__device__ hf g_qhi[NBH*SS*HDD], g_qlo[NBH*SS*HDD];
__device__ hf g_k[NBH*SS*HDD];
__device__ hf g_v[NBH*SS*HDD];
__device__ hf g_p[(size_t)NBH*SS*SS];
__device__ hf g_sc[(size_t)NBH*SS*SS];   // scores as fp16 (was f32)

// ---------------- helpers ----------------
__device__ __forceinline__ u32 sptr(const void* p){ return (u32)__cvta_generic_to_shared(p); }
__device__ __forceinline__ void ldsm4(u32& r0,u32& r1,u32& r2,u32& r3,u32 a){
    asm volatile("ldmatrix.sync.aligned.m8n8.x4.shared.b16 {%0,%1,%2,%3},[%4];"
                 :"=r"(r0),"=r"(r1),"=r"(r2),"=r"(r3):"r"(a));
}
__device__ __forceinline__ void ldsm4t(u32& r0,u32& r1,u32& r2,u32& r3,u32 a){
    asm volatile("ldmatrix.sync.aligned.m8n8.x4.trans.shared.b16 {%0,%1,%2,%3},[%4];"
                 :"=r"(r0),"=r"(r1),"=r"(r2),"=r"(r3):"r"(a));
}
__device__ __forceinline__ void mma16816(float (&c)[4], const u32 (&a)[4], u32 b0, u32 b1){
    asm volatile("mma.sync.aligned.m16n8k16.row.col.f32.f16.f16.f32 "
                 "{%0,%1,%2,%3},{%4,%5,%6,%7},{%8,%9},{%0,%1,%2,%3};"
                 :"+f"(c[0]),"+f"(c[1]),"+f"(c[2]),"+f"(c[3])
                 :"r"(a[0]),"r"(a[1]),"r"(a[2]),"r"(a[3]),"r"(b0),"r"(b1));
}
__device__ __forceinline__ u32 pack2h(float a, float b){
    __half2 t; t.x=__float2half_rn(a); t.y=__float2half_rn(b);
    return *(u32*)&t;
}
__device__ __forceinline__ u32 pack2l(float a, float b){
    float ah = __half2float(__float2half_rn(a));
    float bh = __half2float(__float2half_rn(b));
    __half2 t; t.x=__float2half_rn(a-ah); t.y=__float2half_rn(b-bh);
    return *(u32*)&t;
}

#define CP16(dst, src) \
    asm volatile("cp.async.cg.shared.global [%0], [%1], 16;" :: "r"(dst), "l"(src))
#define CP_COMMIT() asm volatile("cp.async.commit_group;" ::: "memory")
#define CP_WAIT(n)  asm volatile("cp.async.wait_group %0;" :: "n"(n) : "memory")

// ============================================================================
// K0: fp32 -> fp16 (single rounding) for X, W, de.
// ============================================================================
__global__ __launch_bounds__(256)
void cvt_kernel(const float* __restrict__ X, const float* __restrict__ Wq,
                const float* __restrict__ Wk, const float* __restrict__ Wv,
                const float* __restrict__ de)
{
    int i = blockIdx.x * 256 + threadIdx.x;
    if (i >= 1343472) return;
    const float* src; hf* dst; int off;
    if (i < 524288) {
        src = X; dst = g_x; off = i;
    } else if (i < 1310720) {
        off = i - 524288;
        int wsel = off >> 18;
        src = (wsel==0)?Wq:(wsel==1)?Wk:Wv;
        dst = g_w + (size_t)wsel * 1048576;
        off &= 262143;
    } else {
        off = i - 1310720; src = de; dst = g_de;
    }
    float4 v = *(const float4*)(src + (size_t)off * 4);
    *(uint2*)(dst + (size_t)off*4) = make_uint2(pack2h(v.x,v.y), pack2h(v.z,v.w));
}

// ============================================================================
// K1: q/k/v = X @ W^T + b (fp16 x1). CTA 128m x 128n, BK=32, 8 warps,
// cp.async 2-stage, 2 CTAs/SM. q written hi/lo; k,v single fp16.
// ============================================================================
#define QKV_SMEM (2*20480)
__global__ __launch_bounds__(256, 2)
void qkv_mma(const float* __restrict__ bq, const float* __restrict__ bk,
             const float* __restrict__ bv)
{
    extern __shared__ __align__(16) char smem[];
    const u32 sb = sptr(smem);

    const int tid = threadIdx.x, wid = tid>>5, lane = tid&31;
    const int warpM = wid>>2, warpN = wid&3;
    const int z = blockIdx.z, n0 = blockIdx.x*128, m0 = blockIdx.y*128;
    const int lr = lane&15, lc8 = (lane>>4)*8, g = lane>>2, t = lane&3;

    const hf* B = g_w + (size_t)z*1048576;
    const float* bias = (z==0)?bq:(z==1)?bk:bv;
    hf* dhi = (z==0)?g_qhi:(z==1)?g_k:g_v;
    const bool wlo = (z==0);

    float acc[4][4][4];
#pragma unroll
    for (int i=0;i<4;i++)
#pragma unroll
        for (int j=0;j<4;j++)
#pragma unroll
            for (int c=0;c<4;c++) acc[i][j][c]=0.f;

    auto load_stage = [&](int st, int k0){
        const u32 base = sb + st*20480;
#pragma unroll
        for (int rep=0;rep<4;rep++){
            int idx = rep*256 + tid;
            int mat = idx >> 9, rem = idx & 511;
            int row = rem >> 2, s4 = rem & 3;
            u32 dst = base + mat*10240 + row*80 + s4*16;
            const hf* srcp =
                (mat==0) ? &g_x[(size_t)(m0+row)*1024 + k0 + s4*8]
                         : &B[(size_t)(n0+row)*1024 + k0 + s4*8];
            CP16(dst, srcp);
        }
    };

    load_stage(0, 0); CP_COMMIT();

    for (int c = 0; c < 32; c++) {
        if (c < 31) { load_stage((c+1)&1, (c+1)*32); CP_COMMIT(); CP_WAIT(1); }
        else        { CP_WAIT(0); }
        __syncthreads();
        const u32 st = sb + (c&1)*20480;
#pragma unroll
        for (int kb=0;kb<32;kb+=16){
            u32 ah[4][4], bb[4][2];
#pragma unroll
            for (int mt=0;mt<4;mt++){
                u32 ra = st + ((warpM*64+mt*16+lr)*40 + kb + lc8)*2;
                ldsm4(ah[mt][0],ah[mt][1],ah[mt][2],ah[mt][3], ra);
            }
#pragma unroll
            for (int gg=0;gg<2;gg++){
                u32 rb = st + 10240 + ((warpN*32+gg*16+lr)*40 + kb + lc8)*2;
                u32 r0,r1,r2,r3;
                ldsm4(r0,r1,r2,r3, rb);
                bb[2*gg][0]=r0; bb[2*gg][1]=r2; bb[2*gg+1][0]=r1; bb[2*gg+1][1]=r3;
            }
#pragma unroll
            for (int mt=0;mt<4;mt++)
#pragma unroll
                for (int nt=0;nt<4;nt++)
                    mma16816(acc[mt][nt], ah[mt], bb[nt][0], bb[nt][1]);
        }
        __syncthreads();
    }

#pragma unroll
    for (int mt=0;mt<4;mt++)
#pragma unroll
        for (int nt=0;nt<4;nt++){
            int ncol = n0 + warpN*32 + nt*8 + 2*t;
            float b0 = bias[ncol], b1 = bias[ncol+1];
            int h = ncol>>6, dd = ncol&63;
#pragma unroll
            for (int rr=0;rr<2;rr++){
                int m = m0 + warpM*64 + mt*16 + g + rr*8;
                int b_ = m>>10, l = m&1023;
                float v0 = acc[mt][nt][rr*2+0] + b0;
                float v1 = acc[mt][nt][rr*2+1] + b1;
                size_t o = (((size_t)(b_*HH + h))*SS + l)*HDD + dd;
                *(u32*)&dhi[o] = pack2h(v0, v1);
                if (wlo) *(u32*)&g_qlo[o] = pack2l(v0, v1);
            }
        }
}

// ============================================================================
// K2: scores = (q k^T)[fp16 x2: Q hi/lo, K single] + Toeplitz(Q DE^T)[x1],
// *0.125 + mask -> fp16 out.
// ============================================================================
#define SC_SMEM 64512
#define SC_QH 0
#define SC_QL 18432
#define SC_K  36864
#define SC_DE 55296
#define SC_T  18432
__global__ __launch_bounds__(256, 2)
void scores_mma(const float* __restrict__ mask)
{
    extern __shared__ __align__(16) char smem[];
    const u32 sb = sptr(smem);
    float* sT = (float*)(smem + SC_T);

    const int tid = threadIdx.x, wid = tid>>5, lane = tid&31;
    const int warpM = wid>>2, warpN = wid&3;
    const int bh = blockIdx.z, l0 = blockIdx.y*128, r0 = blockIdx.x*128;
    const int b_ = bh>>4;
    const int jb = l0 - r0 + 896;
    const int lr = lane&15, lc8 = (lane>>4)*8, g = lane>>2, t = lane&3;

    const hf* qh = g_qhi + (size_t)bh*SS*HDD;
    const hf* ql = g_qlo + (size_t)bh*SS*HDD;
    const hf* kk = g_k   + (size_t)bh*SS*HDD;

    auto load_de = [&](int cchunk){
#pragma unroll
        for (int rep=0;rep<2;rep++){
            int idx = rep*256 + tid;
            int row = idx >> 3, s8 = idx & 7;
            int der = jb + cchunk*64 + row; if (der > 2046) der = 2046;
            CP16(sb + SC_DE + row*144 + s8*16, &g_de[(size_t)der*64 + s8*8]);
        }
    };

#pragma unroll
    for (int rep=0;rep<12;rep++){
        int idx = rep*256 + tid;
        int mat = idx >> 10, rem = idx & 1023;
        int row = rem >> 3, s8 = rem & 7;
        u32 dst = sb + mat*18432 + row*144 + s8*16;
        const hf* srcp =
            (mat==0) ? &qh[(size_t)(l0+row)*64 + s8*8] :
            (mat==1) ? &ql[(size_t)(l0+row)*64 + s8*8] :
                       &kk[(size_t)(r0+row)*64 + s8*8];
        CP16(dst, srcp);
    }
    CP_COMMIT();
    load_de(0); CP_COMMIT();

    float acc[4][4][4];
#pragma unroll
    for (int i=0;i<4;i++)
#pragma unroll
        for (int j=0;j<4;j++)
#pragma unroll
            for (int c=0;c<4;c++) acc[i][j][c]=0.f;

    CP_WAIT(1);
    __syncthreads();

    // ---- phase 1: qk^T (x2) ----
#pragma unroll
    for (int kb=0;kb<64;kb+=16){
        u32 ah[4][4], al[4][4], bb[4][2];
#pragma unroll
        for (int mt=0;mt<4;mt++){
            u32 ra = sb + ((warpM*64+mt*16+lr)*72 + kb + lc8)*2;
            ldsm4(ah[mt][0],ah[mt][1],ah[mt][2],ah[mt][3], ra + SC_QH);
            ldsm4(al[mt][0],al[mt][1],al[mt][2],al[mt][3], ra + SC_QL);
        }
#pragma unroll
        for (int gg=0;gg<2;gg++){
            u32 rb = sb + SC_K + ((warpN*32+gg*16+lr)*72 + kb + lc8)*2;
            u32 r0r,r1r,r2r,r3r;
            ldsm4(r0r,r1r,r2r,r3r, rb);
            bb[2*gg][0]=r0r; bb[2*gg][1]=r2r; bb[2*gg+1][0]=r1r; bb[2*gg+1][1]=r3r;
        }
#pragma unroll
        for (int mt=0;mt<4;mt++)
#pragma unroll
            for (int nt=0;nt<4;nt++){
                mma16816(acc[mt][nt], ah[mt], bb[nt][0], bb[nt][1]);
                mma16816(acc[mt][nt], al[mt], bb[nt][0], bb[nt][1]);
            }
    }

    // ---- phase 2: pe via T = Q DE^T (x1), 4 prefetched chunks ----
    for (int c=0;c<4;c++){
        int t0c = 64*c;
        float Tacc[4][2][4];
#pragma unroll
        for (int i=0;i<4;i++)
#pragma unroll
            for (int j=0;j<2;j++)
#pragma unroll
                for (int q=0;q<4;q++) Tacc[i][j][q]=0.f;

        CP_WAIT(0);
        __syncthreads();
#pragma unroll
        for (int kb=0;kb<64;kb+=16){
            u32 ah[4][4];
#pragma unroll
            for (int mt=0;mt<4;mt++)
                ldsm4(ah[mt][0],ah[mt][1],ah[mt][2],ah[mt][3],
                      sb + SC_QH + ((warpM*64+mt*16+lr)*72 + kb + lc8)*2);
            u32 r0r,r1r,r2r,r3r;
            ldsm4(r0r,r1r,r2r,r3r, sb + SC_DE + ((warpN*16+lr)*72 + kb + lc8)*2);
#pragma unroll
            for (int mt=0;mt<4;mt++){
                mma16816(Tacc[mt][0], ah[mt], r0r, r2r);
                mma16816(Tacc[mt][1], ah[mt], r1r, r3r);
            }
        }
        __syncthreads();
        if (c < 3) { load_de(c+1); CP_COMMIT(); }

#pragma unroll
        for (int mt=0;mt<4;mt++)
#pragma unroll
            for (int n2=0;n2<2;n2++){
                int col = warpN*16 + n2*8 + 2*t;
                int rw = warpM*64 + mt*16 + g;
                *(float2*)&sT[rw*66 + col]     = make_float2(Tacc[mt][n2][0], Tacc[mt][n2][1]);
                *(float2*)&sT[(rw+8)*66 + col] = make_float2(Tacc[mt][n2][2], Tacc[mt][n2][3]);
            }
        __syncthreads();
#pragma unroll
        for (int mt=0;mt<4;mt++){
            int ib = warpM*64 + mt*16 + g;
#pragma unroll
            for (int nt=0;nt<4;nt++){
                int jb0 = warpN*32 + nt*8 + 2*t;
#pragma unroll
                for (int cr=0;cr<4;cr++){
                    int i = ib + (cr>>1)*8, j = jb0 + (cr&1);
                    int tt = i - j + 127 - t0c;
                    if ((unsigned)tt < 64u) acc[mt][nt][cr] += sT[i*66 + tt];
                }
            }
        }
        __syncthreads();
    }

    hf* outp = g_sc + (size_t)bh*SS*SS;
#pragma unroll
    for (int mt=0;mt<4;mt++){
        int i0 = l0 + warpM*64 + mt*16 + g;
#pragma unroll
        for (int nt=0;nt<4;nt++){
            int jc = r0 + warpN*32 + nt*8 + 2*t;
            float2 mk = *(const float2*)&mask[b_*SS + jc];
            *(u32*)&outp[(size_t)i0*SS + jc] =
                pack2h(fmaf(acc[mt][nt][0],0.125f,mk.x), fmaf(acc[mt][nt][1],0.125f,mk.y));
            *(u32*)&outp[(size_t)(i0+8)*SS + jc] =
                pack2h(fmaf(acc[mt][nt][2],0.125f,mk.x), fmaf(acc[mt][nt][3],0.125f,mk.y));
        }
    }
}

// ============================================================================
// K3: stochastic double softmax, warp-per-row; fp16 scores in, fp16 probs out.
// ============================================================================
__device__ __forceinline__ float fast_neglog(float u)
{
    float up = u + 1e-10f;
    float d  = up - 1.0f;
    float p = d*(1.f + d*(-0.5f + d*(0.33333333f + d*(-0.25f + d*0.2f))));
    float lg = __logf(up);
    float l = (d > -0.03125f) ? p : lg;
    return 1e-10f - l;
}

__global__ __launch_bounds__(256)
void softmax_warp(const float* __restrict__ gum)
{
    const int tid = threadIdx.x, lane = tid & 31, w = tid >> 5;
    const size_t row = (size_t)blockIdx.x * 8 + w;
    const hf* srow = g_sc + row * SS;
    const float* urow = gum + row * SS;

    float s[32], n[32];
#pragma unroll
    for (int j = 0; j < 8; j++) {
        uint2 sv = *(const uint2*)&srow[(j*32 + lane)*4];
        float2 f0 = __half22float2(*(__half2*)&sv.x);
        float2 f1 = __half22float2(*(__half2*)&sv.y);
        s[j*4+0]=f0.x; s[j*4+1]=f0.y; s[j*4+2]=f1.x; s[j*4+3]=f1.y;
        float4 u = *(const float4*)&urow[(j*32 + lane)*4];
        n[j*4+0] = fast_neglog(u.x);
        n[j*4+1] = fast_neglog(u.y);
        n[j*4+2] = fast_neglog(u.z);
        n[j*4+3] = fast_neglog(u.w);
    }
    float m = s[0];
#pragma unroll
    for (int i = 1; i < 32; i++) m = fmaxf(m, s[i]);
#pragma unroll
    for (int o = 16; o; o >>= 1) m = fmaxf(m, __shfl_xor_sync(0xffffffffu, m, o));

    float sm1 = 0.f;
#pragma unroll
    for (int i = 0; i < 32; i++) {
        s[i] = __expf(s[i] - m);
        n[i] = __fdividef(s[i], n[i]);
        sm1 += n[i];
    }
#pragma unroll
    for (int o = 16; o; o >>= 1) sm1 += __shfl_xor_sync(0xffffffffu, sm1, o);
    float inv1 = __fdividef(1.0f, sm1);

    float sm2 = 0.f;
#pragma unroll
    for (int i = 0; i < 32; i++) {
        n[i] = s[i] * __expf(fmaf(n[i], inv1, -1.0f));
        sm2 += n[i];
    }
#pragma unroll
    for (int o = 16; o; o >>= 1) sm2 += __shfl_xor_sync(0xffffffffu, sm2, o);
    float inv2 = __fdividef(1.0f, sm2);

#pragma unroll
    for (int j = 0; j < 8; j++) {
        float a = n[j*4+0]*inv2, b = n[j*4+1]*inv2, c = n[j*4+2]*inv2, d = n[j*4+3]*inv2;
        *(uint2*)&g_p[row*SS + (j*32 + lane)*4] =
            make_uint2(pack2h(a,b), pack2h(c,d));
    }
}

// ============================================================================
// K4: out = P @ V (fp16 x1), cp.async 2-stage, 3 CTAs/SM.
// ============================================================================
#define PV_SMEM (2*14848)
__global__ __launch_bounds__(256, 3)
void pv_mma(float* __restrict__ out)
{
    extern __shared__ __align__(16) char smem[];
    const u32 sb = sptr(smem);

    const int tid = threadIdx.x, wid = tid>>5, lane = tid&31;
    const int warpM = wid>>1, warpN = wid&1;
    const int bh = blockIdx.y, l0 = blockIdx.x*128;
    const int b_ = bh>>4, h = bh&15;
    const int lr = lane&15, lc8 = (lane>>4)*8, g = lane>>2, t = lane&3;

    const hf* P = g_p + (size_t)bh*SS*SS;
    const hf* V = g_v + (size_t)bh*SS*HDD;

    auto load_stage = [&](int st, int k0){
        const u32 base = sb + st*14848;
#pragma unroll
        for (int rep=0;rep<2;rep++){
            int idx = rep*256 + tid;
            int row = idx >> 2, s4 = idx & 3;
            CP16(base + row*80 + s4*16, &P[(size_t)(l0+row)*1024 + k0 + s4*8]);
        }
        {
            int row = tid >> 3, s8 = tid & 7;
            CP16(base + 10240 + row*144 + s8*16, &V[(size_t)(k0+row)*64 + s8*8]);
        }
    };

    float acc[2][4][4];
#pragma unroll
    for (int i=0;i<2;i++)
#pragma unroll
        for (int j=0;j<4;j++)
#pragma unroll
            for (int c=0;c<4;c++) acc[i][j][c]=0.f;

    load_stage(0, 0); CP_COMMIT();

    for (int c = 0; c < 32; c++) {
        if (c < 31) { load_stage((c+1)&1, (c+1)*32); CP_COMMIT(); CP_WAIT(1); }
        else        { CP_WAIT(0); }
        __syncthreads();
        const u32 st = sb + (c&1)*14848;
#pragma unroll
        for (int kb=0;kb<32;kb+=16){
            u32 ah[2][4], bb[4][2];
#pragma unroll
            for (int mt=0;mt<2;mt++){
                u32 ra = st + ((warpM*32+mt*16+lr)*40 + kb + lc8)*2;
                ldsm4(ah[mt][0],ah[mt][1],ah[mt][2],ah[mt][3], ra);
            }
#pragma unroll
            for (int gg=0;gg<2;gg++){
                u32 rb = st + 10240 + ((kb+lr)*72 + warpN*32 + gg*16 + lc8)*2;
                u32 r0,r1,r2,r3;
                ldsm4t(r0,r1,r2,r3, rb);
                bb[2*gg][0]=r0; bb[2*gg][1]=r1; bb[2*gg+1][0]=r2; bb[2*gg+1][1]=r3;
            }
#pragma unroll
            for (int mt=0;mt<2;mt++)
#pragma unroll
                for (int nt=0;nt<4;nt++)
                    mma16816(acc[mt][nt], ah[mt], bb[nt][0], bb[nt][1]);
        }
        __syncthreads();
    }

#pragma unroll
    for (int mt=0;mt<2;mt++)
#pragma unroll
        for (int nt=0;nt<4;nt++){
            int dcol = warpN*32 + nt*8 + 2*t;
#pragma unroll
            for (int rr=0;rr<2;rr++){
                int l = l0 + warpM*32 + mt*16 + g + rr*8;
                *(float2*)&out[((size_t)(b_*SS)+l)*1024 + h*64 + dcol] =
                    make_float2(acc[mt][nt][rr*2+0], acc[mt][nt][rr*2+1]);
            }
        }
}

// ============================================================================
extern "C" void kernel_launch(void* const* d_in, const int* in_sizes, int n_in,
                              void* d_out, int out_size)
{
    const float* hidden = (const float*)d_in[0];
    const float* mask   = (const float*)d_in[1];
    const float* gum    = (const float*)d_in[2];
    const float* Wq     = (const float*)d_in[3];
    const float* bq     = (const float*)d_in[4];
    const float* Wk     = (const float*)d_in[5];
    const float* bk     = (const float*)d_in[6];
    const float* Wv     = (const float*)d_in[7];
    const float* bv     = (const float*)d_in[8];
    const float* de     = (const float*)d_in[9];
    float* out = (float*)d_out;

    static int configured = 0;
    if (!configured) {
        cudaFuncSetAttribute(qkv_mma,    cudaFuncAttributeMaxDynamicSharedMemorySize, QKV_SMEM);
        cudaFuncSetAttribute(scores_mma, cudaFuncAttributeMaxDynamicSharedMemorySize, SC_SMEM);
        cudaFuncSetAttribute(pv_mma,     cudaFuncAttributeMaxDynamicSharedMemorySize, PV_SMEM);
        configured = 1;
    }

    cvt_kernel<<<5249, 256>>>(hidden, Wq, Wk, Wv, de);
    qkv_mma<<<dim3(8, 16, 3), 256, QKV_SMEM>>>(bq, bk, bv);
    scores_mma<<<dim3(8, 8, 32), 256, SC_SMEM>>>(mask);
    softmax_warp<<<4096, 256>>>(gum);
    pv_mma<<<dim3(8, 32), 256, PV_SMEM>>>(out);
}

// round 12
// speedup vs baseline: 2.1076x; 1.0762x over previous
#include <cuda_runtime.h>
#include <cuda_fp16.h>
#include <math.h>

typedef unsigned int u32;
typedef __half hf;

#define SS 1024
#define HH 16
#define HDD 64
#define NBH 32

// ---------------- scratch (device globals) ----------------
__device__ hf g_x[2048*1024];
__device__ hf g_w[3*1024*1024];
__device__ hf g_de[2047*64];
__device__ hf g_q[NBH*SS*HDD];
__device__ hf g_k[NBH*SS*HDD];
__device__ hf g_v[NBH*SS*HDD];
__device__ hf g_p[(size_t)NBH*SS*SS];
__device__ hf g_sc[(size_t)NBH*SS*SS];

// ---------------- helpers ----------------
__device__ __forceinline__ u32 sptr(const void* p){ return (u32)__cvta_generic_to_shared(p); }
__device__ __forceinline__ void ldsm4(u32& r0,u32& r1,u32& r2,u32& r3,u32 a){
    asm volatile("ldmatrix.sync.aligned.m8n8.x4.shared.b16 {%0,%1,%2,%3},[%4];"
                 :"=r"(r0),"=r"(r1),"=r"(r2),"=r"(r3):"r"(a));
}
__device__ __forceinline__ void ldsm4t(u32& r0,u32& r1,u32& r2,u32& r3,u32 a){
    asm volatile("ldmatrix.sync.aligned.m8n8.x4.trans.shared.b16 {%0,%1,%2,%3},[%4];"
                 :"=r"(r0),"=r"(r1),"=r"(r2),"=r"(r3):"r"(a));
}
__device__ __forceinline__ void mma16816(float (&c)[4], const u32 (&a)[4], u32 b0, u32 b1){
    asm volatile("mma.sync.aligned.m16n8k16.row.col.f32.f16.f16.f32 "
                 "{%0,%1,%2,%3},{%4,%5,%6,%7},{%8,%9},{%0,%1,%2,%3};"
                 :"+f"(c[0]),"+f"(c[1]),"+f"(c[2]),"+f"(c[3])
                 :"r"(a[0]),"r"(a[1]),"r"(a[2]),"r"(a[3]),"r"(b0),"r"(b1));
}
__device__ __forceinline__ u32 pack2h(float a, float b){
    __half2 t; t.x=__float2half_rn(a); t.y=__float2half_rn(b);
    return *(u32*)&t;
}

#define CP16(dst, src) \
    asm volatile("cp.async.cg.shared.global [%0], [%1], 16;" :: "r"(dst), "l"(src))
#define CP_COMMIT() asm volatile("cp.async.commit_group;" ::: "memory")
#define CP_WAIT(n)  asm volatile("cp.async.wait_group %0;" :: "n"(n) : "memory")

// ============================================================================
// K0: fp32 -> fp16 (single rounding) for X, W, de.
// ============================================================================
__global__ __launch_bounds__(256)
void cvt_kernel(const float* __restrict__ X, const float* __restrict__ Wq,
                const float* __restrict__ Wk, const float* __restrict__ Wv,
                const float* __restrict__ de)
{
    int i = blockIdx.x * 256 + threadIdx.x;
    if (i >= 1343472) return;
    const float* src; hf* dst; int off;
    if (i < 524288) {
        src = X; dst = g_x; off = i;
    } else if (i < 1310720) {
        off = i - 524288;
        int wsel = off >> 18;
        src = (wsel==0)?Wq:(wsel==1)?Wk:Wv;
        dst = g_w + (size_t)wsel * 1048576;
        off &= 262143;
    } else {
        off = i - 1310720; src = de; dst = g_de;
    }
    float4 v = *(const float4*)(src + (size_t)off * 4);
    *(uint2*)(dst + (size_t)off*4) = make_uint2(pack2h(v.x,v.y), pack2h(v.z,v.w));
}

// ============================================================================
// K1: q/k/v = X @ W^T + b (fp16 x1). CTA 128m x 128n, BK=64, 8 warps,
// cp.async 2-stage, 2 CTAs/SM. stage (36864B): A(18432) B(18432), stride 144B.
// ============================================================================
#define QKV_SMEM (2*36864)
__global__ __launch_bounds__(256, 2)
void qkv_mma(const float* __restrict__ bq, const float* __restrict__ bk,
             const float* __restrict__ bv)
{
    extern __shared__ __align__(16) char smem[];
    const u32 sb = sptr(smem);

    const int tid = threadIdx.x, wid = tid>>5, lane = tid&31;
    const int warpM = wid>>2, warpN = wid&3;
    const int z = blockIdx.z, n0 = blockIdx.x*128, m0 = blockIdx.y*128;
    const int lr = lane&15, lc8 = (lane>>4)*8, g = lane>>2, t = lane&3;

    const hf* B = g_w + (size_t)z*1048576;
    const float* bias = (z==0)?bq:(z==1)?bk:bv;
    hf* dq = (z==0)?g_q:(z==1)?g_k:g_v;

    float acc[4][4][4];
#pragma unroll
    for (int i=0;i<4;i++)
#pragma unroll
        for (int j=0;j<4;j++)
#pragma unroll
            for (int c=0;c<4;c++) acc[i][j][c]=0.f;

    auto load_stage = [&](int st, int k0){
        const u32 base = sb + st*36864;
#pragma unroll
        for (int rep=0;rep<8;rep++){
            int idx = rep*256 + tid;             // 0..2047
            int mat = idx >> 10, rem = idx & 1023;
            int row = rem >> 3, s8 = rem & 7;
            u32 dst = base + mat*18432 + row*144 + s8*16;
            const hf* srcp =
                (mat==0) ? &g_x[(size_t)(m0+row)*1024 + k0 + s8*8]
                         : &B[(size_t)(n0+row)*1024 + k0 + s8*8];
            CP16(dst, srcp);
        }
    };

    load_stage(0, 0); CP_COMMIT();

    for (int c = 0; c < 16; c++) {
        if (c < 15) { load_stage((c+1)&1, (c+1)*64); CP_COMMIT(); CP_WAIT(1); }
        else        { CP_WAIT(0); }
        __syncthreads();
        const u32 st = sb + (c&1)*36864;
#pragma unroll
        for (int kb=0;kb<64;kb+=16){
            u32 ah[4][4], bb[4][2];
#pragma unroll
            for (int mt=0;mt<4;mt++){
                u32 ra = st + ((warpM*64+mt*16+lr)*72 + kb + lc8)*2;
                ldsm4(ah[mt][0],ah[mt][1],ah[mt][2],ah[mt][3], ra);
            }
#pragma unroll
            for (int gg=0;gg<2;gg++){
                u32 rb = st + 18432 + ((warpN*32+gg*16+lr)*72 + kb + lc8)*2;
                u32 r0,r1,r2,r3;
                ldsm4(r0,r1,r2,r3, rb);
                bb[2*gg][0]=r0; bb[2*gg][1]=r2; bb[2*gg+1][0]=r1; bb[2*gg+1][1]=r3;
            }
#pragma unroll
            for (int mt=0;mt<4;mt++)
#pragma unroll
                for (int nt=0;nt<4;nt++)
                    mma16816(acc[mt][nt], ah[mt], bb[nt][0], bb[nt][1]);
        }
        __syncthreads();
    }

#pragma unroll
    for (int mt=0;mt<4;mt++)
#pragma unroll
        for (int nt=0;nt<4;nt++){
            int ncol = n0 + warpN*32 + nt*8 + 2*t;
            float b0 = bias[ncol], b1 = bias[ncol+1];
            int h = ncol>>6, dd = ncol&63;
#pragma unroll
            for (int rr=0;rr<2;rr++){
                int m = m0 + warpM*64 + mt*16 + g + rr*8;
                int b_ = m>>10, l = m&1023;
                float v0 = acc[mt][nt][rr*2+0] + b0;
                float v1 = acc[mt][nt][rr*2+1] + b1;
                size_t o = (((size_t)(b_*HH + h))*SS + l)*HDD + dd;
                *(u32*)&dq[o] = pack2h(v0, v1);
            }
        }
}

// ============================================================================
// K2: scores = (q k^T)[fp16 x1] + Toeplitz(Q DE^T)[x1], *0.125 + mask -> fp16
// smem: Q(0,18432) K(18432,18432) | sT overlays K (33792) | DE(52224,9216)
// ============================================================================
#define SC_SMEM 61440
#define SC_Q  0
#define SC_K  18432
#define SC_T  18432
#define SC_DE 52224
__global__ __launch_bounds__(256, 2)
void scores_mma(const float* __restrict__ mask)
{
    extern __shared__ __align__(16) char smem[];
    const u32 sb = sptr(smem);
    float* sT = (float*)(smem + SC_T);

    const int tid = threadIdx.x, wid = tid>>5, lane = tid&31;
    const int warpM = wid>>2, warpN = wid&3;
    const int bh = blockIdx.z, l0 = blockIdx.y*128, r0 = blockIdx.x*128;
    const int b_ = bh>>4;
    const int jb = l0 - r0 + 896;
    const int lr = lane&15, lc8 = (lane>>4)*8, g = lane>>2, t = lane&3;

    const hf* qq = g_q + (size_t)bh*SS*HDD;
    const hf* kk = g_k + (size_t)bh*SS*HDD;

    auto load_de = [&](int cchunk){
#pragma unroll
        for (int rep=0;rep<2;rep++){
            int idx = rep*256 + tid;
            int row = idx >> 3, s8 = idx & 7;
            int der = jb + cchunk*64 + row; if (der > 2046) der = 2046;
            CP16(sb + SC_DE + row*144 + s8*16, &g_de[(size_t)der*64 + s8*8]);
        }
    };

    // group 0: Q + K, full K=64
#pragma unroll
    for (int rep=0;rep<8;rep++){
        int idx = rep*256 + tid;                 // 0..2047
        int mat = idx >> 10, rem = idx & 1023;
        int row = rem >> 3, s8 = rem & 7;
        u32 dst = sb + mat*18432 + row*144 + s8*16;
        const hf* srcp =
            (mat==0) ? &qq[(size_t)(l0+row)*64 + s8*8]
                     : &kk[(size_t)(r0+row)*64 + s8*8];
        CP16(dst, srcp);
    }
    CP_COMMIT();
    load_de(0); CP_COMMIT();

    float acc[4][4][4];
#pragma unroll
    for (int i=0;i<4;i++)
#pragma unroll
        for (int j=0;j<4;j++)
#pragma unroll
            for (int c=0;c<4;c++) acc[i][j][c]=0.f;

    CP_WAIT(1);
    __syncthreads();

    // ---- phase 1: qk^T (x1) ----
#pragma unroll
    for (int kb=0;kb<64;kb+=16){
        u32 ah[4][4], bb[4][2];
#pragma unroll
        for (int mt=0;mt<4;mt++){
            u32 ra = sb + SC_Q + ((warpM*64+mt*16+lr)*72 + kb + lc8)*2;
            ldsm4(ah[mt][0],ah[mt][1],ah[mt][2],ah[mt][3], ra);
        }
#pragma unroll
        for (int gg=0;gg<2;gg++){
            u32 rb = sb + SC_K + ((warpN*32+gg*16+lr)*72 + kb + lc8)*2;
            u32 r0r,r1r,r2r,r3r;
            ldsm4(r0r,r1r,r2r,r3r, rb);
            bb[2*gg][0]=r0r; bb[2*gg][1]=r2r; bb[2*gg+1][0]=r1r; bb[2*gg+1][1]=r3r;
        }
#pragma unroll
        for (int mt=0;mt<4;mt++)
#pragma unroll
            for (int nt=0;nt<4;nt++)
                mma16816(acc[mt][nt], ah[mt], bb[nt][0], bb[nt][1]);
    }

    // ---- phase 2: pe via T = Q DE^T (x1), 4 prefetched chunks ----
    // sT overlays K region, which is dead after phase 1.
    for (int c=0;c<4;c++){
        int t0c = 64*c;
        float Tacc[4][2][4];
#pragma unroll
        for (int i=0;i<4;i++)
#pragma unroll
            for (int j=0;j<2;j++)
#pragma unroll
                for (int q=0;q<4;q++) Tacc[i][j][q]=0.f;

        CP_WAIT(0);
        __syncthreads();           // DE chunk c visible; K reads done
#pragma unroll
        for (int kb=0;kb<64;kb+=16){
            u32 ah[4][4];
#pragma unroll
            for (int mt=0;mt<4;mt++)
                ldsm4(ah[mt][0],ah[mt][1],ah[mt][2],ah[mt][3],
                      sb + SC_Q + ((warpM*64+mt*16+lr)*72 + kb + lc8)*2);
            u32 r0r,r1r,r2r,r3r;
            ldsm4(r0r,r1r,r2r,r3r, sb + SC_DE + ((warpN*16+lr)*72 + kb + lc8)*2);
#pragma unroll
            for (int mt=0;mt<4;mt++){
                mma16816(Tacc[mt][0], ah[mt], r0r, r2r);
                mma16816(Tacc[mt][1], ah[mt], r1r, r3r);
            }
        }
        __syncthreads();           // sDE reads done
        if (c < 3) { load_de(c+1); CP_COMMIT(); }

#pragma unroll
        for (int mt=0;mt<4;mt++)
#pragma unroll
            for (int n2=0;n2<2;n2++){
                int col = warpN*16 + n2*8 + 2*t;
                int rw = warpM*64 + mt*16 + g;
                *(float2*)&sT[rw*66 + col]     = make_float2(Tacc[mt][n2][0], Tacc[mt][n2][1]);
                *(float2*)&sT[(rw+8)*66 + col] = make_float2(Tacc[mt][n2][2], Tacc[mt][n2][3]);
            }
        __syncthreads();
#pragma unroll
        for (int mt=0;mt<4;mt++){
            int ib = warpM*64 + mt*16 + g;
#pragma unroll
            for (int nt=0;nt<4;nt++){
                int jb0 = warpN*32 + nt*8 + 2*t;
#pragma unroll
                for (int cr=0;cr<4;cr++){
                    int i = ib + (cr>>1)*8, j = jb0 + (cr&1);
                    int tt = i - j + 127 - t0c;
                    if ((unsigned)tt < 64u) acc[mt][nt][cr] += sT[i*66 + tt];
                }
            }
        }
        __syncthreads();
    }

    hf* outp = g_sc + (size_t)bh*SS*SS;
#pragma unroll
    for (int mt=0;mt<4;mt++){
        int i0 = l0 + warpM*64 + mt*16 + g;
#pragma unroll
        for (int nt=0;nt<4;nt++){
            int jc = r0 + warpN*32 + nt*8 + 2*t;
            float2 mk = *(const float2*)&mask[b_*SS + jc];
            *(u32*)&outp[(size_t)i0*SS + jc] =
                pack2h(fmaf(acc[mt][nt][0],0.125f,mk.x), fmaf(acc[mt][nt][1],0.125f,mk.y));
            *(u32*)&outp[(size_t)(i0+8)*SS + jc] =
                pack2h(fmaf(acc[mt][nt][2],0.125f,mk.x), fmaf(acc[mt][nt][3],0.125f,mk.y));
        }
    }
}

// ============================================================================
// K3: stochastic double softmax, warp-per-row; fp16 scores in, fp16 probs out.
// ============================================================================
__device__ __forceinline__ float fast_neglog(float u)
{
    float up = u + 1e-10f;
    float d  = up - 1.0f;
    float p = d*(1.f + d*(-0.5f + d*(0.33333333f + d*(-0.25f + d*0.2f))));
    float lg = __logf(up);
    float l = (d > -0.03125f) ? p : lg;
    return 1e-10f - l;
}

__global__ __launch_bounds__(256)
void softmax_warp(const float* __restrict__ gum)
{
    const int tid = threadIdx.x, lane = tid & 31, w = tid >> 5;
    const size_t row = (size_t)blockIdx.x * 8 + w;
    const hf* srow = g_sc + row * SS;
    const float* urow = gum + row * SS;

    float s[32], n[32];
#pragma unroll
    for (int j = 0; j < 8; j++) {
        uint2 sv = *(const uint2*)&srow[(j*32 + lane)*4];
        float2 f0 = __half22float2(*(__half2*)&sv.x);
        float2 f1 = __half22float2(*(__half2*)&sv.y);
        s[j*4+0]=f0.x; s[j*4+1]=f0.y; s[j*4+2]=f1.x; s[j*4+3]=f1.y;
        float4 u = *(const float4*)&urow[(j*32 + lane)*4];
        n[j*4+0] = fast_neglog(u.x);
        n[j*4+1] = fast_neglog(u.y);
        n[j*4+2] = fast_neglog(u.z);
        n[j*4+3] = fast_neglog(u.w);
    }
    float m = s[0];
#pragma unroll
    for (int i = 1; i < 32; i++) m = fmaxf(m, s[i]);
#pragma unroll
    for (int o = 16; o; o >>= 1) m = fmaxf(m, __shfl_xor_sync(0xffffffffu, m, o));

    float sm1 = 0.f;
#pragma unroll
    for (int i = 0; i < 32; i++) {
        s[i] = __expf(s[i] - m);
        n[i] = __fdividef(s[i], n[i]);
        sm1 += n[i];
    }
#pragma unroll
    for (int o = 16; o; o >>= 1) sm1 += __shfl_xor_sync(0xffffffffu, sm1, o);
    float inv1 = __fdividef(1.0f, sm1);

    float sm2 = 0.f;
#pragma unroll
    for (int i = 0; i < 32; i++) {
        n[i] = s[i] * __expf(fmaf(n[i], inv1, -1.0f));
        sm2 += n[i];
    }
#pragma unroll
    for (int o = 16; o; o >>= 1) sm2 += __shfl_xor_sync(0xffffffffu, sm2, o);
    float inv2 = __fdividef(1.0f, sm2);

#pragma unroll
    for (int j = 0; j < 8; j++) {
        float a = n[j*4+0]*inv2, b = n[j*4+1]*inv2, c = n[j*4+2]*inv2, d = n[j*4+3]*inv2;
        *(uint2*)&g_p[row*SS + (j*32 + lane)*4] =
            make_uint2(pack2h(a,b), pack2h(c,d));
    }
}

// ============================================================================
// K4: out = P @ V (fp16 x1), BK=64, cp.async 2-stage, 3 CTAs/SM.
// stage (27648B): P(18432) V(9216), stride 144B.
// ============================================================================
#define PV_SMEM (2*27648)
__global__ __launch_bounds__(256, 3)
void pv_mma(float* __restrict__ out)
{
    extern __shared__ __align__(16) char smem[];
    const u32 sb = sptr(smem);

    const int tid = threadIdx.x, wid = tid>>5, lane = tid&31;
    const int warpM = wid>>1, warpN = wid&1;
    const int bh = blockIdx.y, l0 = blockIdx.x*128;
    const int b_ = bh>>4, h = bh&15;
    const int lr = lane&15, lc8 = (lane>>4)*8, g = lane>>2, t = lane&3;

    const hf* P = g_p + (size_t)bh*SS*SS;
    const hf* V = g_v + (size_t)bh*SS*HDD;

    auto load_stage = [&](int st, int k0){
        const u32 base = sb + st*27648;
#pragma unroll
        for (int rep=0;rep<4;rep++){          // P: 128 rows x 8 seg
            int idx = rep*256 + tid;
            int row = idx >> 3, s8 = idx & 7;
            CP16(base + row*144 + s8*16, &P[(size_t)(l0+row)*1024 + k0 + s8*8]);
        }
#pragma unroll
        for (int rep=0;rep<2;rep++){          // V: 64 rows x 8 seg
            int idx = rep*256 + tid;
            int row = idx >> 3, s8 = idx & 7;
            CP16(base + 18432 + row*144 + s8*16, &V[(size_t)(k0+row)*64 + s8*8]);
        }
    };

    float acc[2][4][4];
#pragma unroll
    for (int i=0;i<2;i++)
#pragma unroll
        for (int j=0;j<4;j++)
#pragma unroll
            for (int c=0;c<4;c++) acc[i][j][c]=0.f;

    load_stage(0, 0); CP_COMMIT();

    for (int c = 0; c < 16; c++) {
        if (c < 15) { load_stage((c+1)&1, (c+1)*64); CP_COMMIT(); CP_WAIT(1); }
        else        { CP_WAIT(0); }
        __syncthreads();
        const u32 st = sb + (c&1)*27648;
#pragma unroll
        for (int kb=0;kb<64;kb+=16){
            u32 ah[2][4], bb[4][2];
#pragma unroll
            for (int mt=0;mt<2;mt++){
                u32 ra = st + ((warpM*32+mt*16+lr)*72 + kb + lc8)*2;
                ldsm4(ah[mt][0],ah[mt][1],ah[mt][2],ah[mt][3], ra);
            }
#pragma unroll
            for (int gg=0;gg<2;gg++){
                u32 rb = st + 18432 + ((kb+lr)*72 + warpN*32 + gg*16 + lc8)*2;
                u32 r0,r1,r2,r3;
                ldsm4t(r0,r1,r2,r3, rb);
                bb[2*gg][0]=r0; bb[2*gg][1]=r1; bb[2*gg+1][0]=r2; bb[2*gg+1][1]=r3;
            }
#pragma unroll
            for (int mt=0;mt<2;mt++)
#pragma unroll
                for (int nt=0;nt<4;nt++)
                    mma16816(acc[mt][nt], ah[mt], bb[nt][0], bb[nt][1]);
        }
        __syncthreads();
    }

#pragma unroll
    for (int mt=0;mt<2;mt++)
#pragma unroll
        for (int nt=0;nt<4;nt++){
            int dcol = warpN*32 + nt*8 + 2*t;
#pragma unroll
            for (int rr=0;rr<2;rr++){
                int l = l0 + warpM*32 + mt*16 + g + rr*8;
                *(float2*)&out[((size_t)(b_*SS)+l)*1024 + h*64 + dcol] =
                    make_float2(acc[mt][nt][rr*2+0], acc[mt][nt][rr*2+1]);
            }
        }
}

// ============================================================================
extern "C" void kernel_launch(void* const* d_in, const int* in_sizes, int n_in,
                              void* d_out, int out_size)
{
    const float* hidden = (const float*)d_in[0];
    const float* mask   = (const float*)d_in[1];
    const float* gum    = (const float*)d_in[2];
    const float* Wq     = (const float*)d_in[3];
    const float* bq     = (const float*)d_in[4];
    const float* Wk     = (const float*)d_in[5];
    const float* bk     = (const float*)d_in[6];
    const float* Wv     = (const float*)d_in[7];
    const float* bv     = (const float*)d_in[8];
    const float* de     = (const float*)d_in[9];
    float* out = (float*)d_out;

    static int configured = 0;
    if (!configured) {
        cudaFuncSetAttribute(qkv_mma,    cudaFuncAttributeMaxDynamicSharedMemorySize, QKV_SMEM);
        cudaFuncSetAttribute(scores_mma, cudaFuncAttributeMaxDynamicSharedMemorySize, SC_SMEM);
        cudaFuncSetAttribute(pv_mma,     cudaFuncAttributeMaxDynamicSharedMemorySize, PV_SMEM);
        configured = 1;
    }

    cvt_kernel<<<5249, 256>>>(hidden, Wq, Wk, Wv, de);
    qkv_mma<<<dim3(8, 16, 3), 256, QKV_SMEM>>>(bq, bk, bv);
    scores_mma<<<dim3(8, 8, 32), 256, SC_SMEM>>>(mask);
    softmax_warp<<<4096, 256>>>(gum);
    pv_mma<<<dim3(8, 32), 256, PV_SMEM>>>(out);
}

// round 14
// speedup vs baseline: 2.1421x; 1.0164x over previous
#include <cuda_runtime.h>
#include <cuda_fp16.h>
#include <math.h>

typedef unsigned int u32;
typedef __half hf;

#define SS 1024
#define HH 16
#define HDD 64
#define NBH 32

// ---------------- scratch (device globals) ----------------
__device__ hf g_x[2048*1024];
__device__ hf g_w[3*1024*1024];
__device__ hf g_de[2047*64];
__device__ hf g_q[NBH*SS*HDD];
__device__ hf g_k[NBH*SS*HDD];
__device__ hf g_v[NBH*SS*HDD];
__device__ hf g_sc[(size_t)NBH*SS*SS];

// ---------------- helpers ----------------
__device__ __forceinline__ u32 sptr(const void* p){ return (u32)__cvta_generic_to_shared(p); }
__device__ __forceinline__ void ldsm4(u32& r0,u32& r1,u32& r2,u32& r3,u32 a){
    asm volatile("ldmatrix.sync.aligned.m8n8.x4.shared.b16 {%0,%1,%2,%3},[%4];"
                 :"=r"(r0),"=r"(r1),"=r"(r2),"=r"(r3):"r"(a));
}
__device__ __forceinline__ void ldsm4t(u32& r0,u32& r1,u32& r2,u32& r3,u32 a){
    asm volatile("ldmatrix.sync.aligned.m8n8.x4.trans.shared.b16 {%0,%1,%2,%3},[%4];"
                 :"=r"(r0),"=r"(r1),"=r"(r2),"=r"(r3):"r"(a));
}
__device__ __forceinline__ void mma16816(float (&c)[4], const u32 (&a)[4], u32 b0, u32 b1){
    asm volatile("mma.sync.aligned.m16n8k16.row.col.f32.f16.f16.f32 "
                 "{%0,%1,%2,%3},{%4,%5,%6,%7},{%8,%9},{%0,%1,%2,%3};"
                 :"+f"(c[0]),"+f"(c[1]),"+f"(c[2]),"+f"(c[3])
                 :"r"(a[0]),"r"(a[1]),"r"(a[2]),"r"(a[3]),"r"(b0),"r"(b1));
}
__device__ __forceinline__ u32 pack2h(float a, float b){
    __half2 t; t.x=__float2half_rn(a); t.y=__float2half_rn(b);
    return *(u32*)&t;
}

#define CP16(dst, src) \
    asm volatile("cp.async.cg.shared.global [%0], [%1], 16;" :: "r"(dst), "l"(src))
#define CP_COMMIT() asm volatile("cp.async.commit_group;" ::: "memory")
#define CP_WAIT(n)  asm volatile("cp.async.wait_group %0;" :: "n"(n) : "memory")

// ============================================================================
// K0: fp32 -> fp16 (single rounding) for X, W, de.
// ============================================================================
__global__ __launch_bounds__(256)
void cvt_kernel(const float* __restrict__ X, const float* __restrict__ Wq,
                const float* __restrict__ Wk, const float* __restrict__ Wv,
                const float* __restrict__ de)
{
    int i = blockIdx.x * 256 + threadIdx.x;
    if (i >= 1343472) return;
    const float* src; hf* dst; int off;
    if (i < 524288) {
        src = X; dst = g_x; off = i;
    } else if (i < 1310720) {
        off = i - 524288;
        int wsel = off >> 18;
        src = (wsel==0)?Wq:(wsel==1)?Wk:Wv;
        dst = g_w + (size_t)wsel * 1048576;
        off &= 262143;
    } else {
        off = i - 1310720; src = de; dst = g_de;
    }
    float4 v = *(const float4*)(src + (size_t)off * 4);
    *(uint2*)(dst + (size_t)off*4) = make_uint2(pack2h(v.x,v.y), pack2h(v.z,v.w));
}

// ============================================================================
// K1: q/k/v = X @ W^T + b (fp16 x1). CTA 128x128, BK=64, cp.async 2-stage,
// 2 CTAs/SM.
// ============================================================================
#define QKV_SMEM (2*36864)
__global__ __launch_bounds__(256, 2)
void qkv_mma(const float* __restrict__ bq, const float* __restrict__ bk,
             const float* __restrict__ bv)
{
    extern __shared__ __align__(16) char smem[];
    const u32 sb = sptr(smem);

    const int tid = threadIdx.x, wid = tid>>5, lane = tid&31;
    const int warpM = wid>>2, warpN = wid&3;
    const int z = blockIdx.z, n0 = blockIdx.x*128, m0 = blockIdx.y*128;
    const int lr = lane&15, lc8 = (lane>>4)*8, g = lane>>2, t = lane&3;

    const hf* B = g_w + (size_t)z*1048576;
    const float* bias = (z==0)?bq:(z==1)?bk:bv;
    hf* dq = (z==0)?g_q:(z==1)?g_k:g_v;

    float acc[4][4][4];
#pragma unroll
    for (int i=0;i<4;i++)
#pragma unroll
        for (int j=0;j<4;j++)
#pragma unroll
            for (int c=0;c<4;c++) acc[i][j][c]=0.f;

    auto load_stage = [&](int st, int k0){
        const u32 base = sb + st*36864;
#pragma unroll
        for (int rep=0;rep<8;rep++){
            int idx = rep*256 + tid;
            int mat = idx >> 10, rem = idx & 1023;
            int row = rem >> 3, s8 = rem & 7;
            u32 dst = base + mat*18432 + row*144 + s8*16;
            const hf* srcp =
                (mat==0) ? &g_x[(size_t)(m0+row)*1024 + k0 + s8*8]
                         : &B[(size_t)(n0+row)*1024 + k0 + s8*8];
            CP16(dst, srcp);
        }
    };

    load_stage(0, 0); CP_COMMIT();

    for (int c = 0; c < 16; c++) {
        if (c < 15) { load_stage((c+1)&1, (c+1)*64); CP_COMMIT(); CP_WAIT(1); }
        else        { CP_WAIT(0); }
        __syncthreads();
        const u32 st = sb + (c&1)*36864;
#pragma unroll
        for (int kb=0;kb<64;kb+=16){
            u32 ah[4][4], bb[4][2];
#pragma unroll
            for (int mt=0;mt<4;mt++){
                u32 ra = st + ((warpM*64+mt*16+lr)*72 + kb + lc8)*2;
                ldsm4(ah[mt][0],ah[mt][1],ah[mt][2],ah[mt][3], ra);
            }
#pragma unroll
            for (int gg=0;gg<2;gg++){
                u32 rb = st + 18432 + ((warpN*32+gg*16+lr)*72 + kb + lc8)*2;
                u32 r0,r1,r2,r3;
                ldsm4(r0,r1,r2,r3, rb);
                bb[2*gg][0]=r0; bb[2*gg][1]=r2; bb[2*gg+1][0]=r1; bb[2*gg+1][1]=r3;
            }
#pragma unroll
            for (int mt=0;mt<4;mt++)
#pragma unroll
                for (int nt=0;nt<4;nt++)
                    mma16816(acc[mt][nt], ah[mt], bb[nt][0], bb[nt][1]);
        }
        __syncthreads();
    }

#pragma unroll
    for (int mt=0;mt<4;mt++)
#pragma unroll
        for (int nt=0;nt<4;nt++){
            int ncol = n0 + warpN*32 + nt*8 + 2*t;
            float b0 = bias[ncol], b1 = bias[ncol+1];
            int h = ncol>>6, dd = ncol&63;
#pragma unroll
            for (int rr=0;rr<2;rr++){
                int m = m0 + warpM*64 + mt*16 + g + rr*8;
                int b_ = m>>10, l = m&1023;
                float v0 = acc[mt][nt][rr*2+0] + b0;
                float v1 = acc[mt][nt][rr*2+1] + b1;
                size_t o = (((size_t)(b_*HH + h))*SS + l)*HDD + dd;
                *(u32*)&dq[o] = pack2h(v0, v1);
            }
        }
}

// ============================================================================
// K2: scores = (q k^T)[fp16 x1] + Toeplitz(Q DE^T)[x1], *0.125 + mask -> fp16
// ============================================================================
#define SC_SMEM 61440
#define SC_Q  0
#define SC_K  18432
#define SC_T  18432
#define SC_DE 52224
__global__ __launch_bounds__(256, 2)
void scores_mma(const float* __restrict__ mask)
{
    extern __shared__ __align__(16) char smem[];
    const u32 sb = sptr(smem);
    float* sT = (float*)(smem + SC_T);

    const int tid = threadIdx.x, wid = tid>>5, lane = tid&31;
    const int warpM = wid>>2, warpN = wid&3;
    const int bh = blockIdx.z, l0 = blockIdx.y*128, r0 = blockIdx.x*128;
    const int b_ = bh>>4;
    const int jb = l0 - r0 + 896;
    const int lr = lane&15, lc8 = (lane>>4)*8, g = lane>>2, t = lane&3;

    const hf* qq = g_q + (size_t)bh*SS*HDD;
    const hf* kk = g_k + (size_t)bh*SS*HDD;

    auto load_de = [&](int cchunk){
#pragma unroll
        for (int rep=0;rep<2;rep++){
            int idx = rep*256 + tid;
            int row = idx >> 3, s8 = idx & 7;
            int der = jb + cchunk*64 + row; if (der > 2046) der = 2046;
            CP16(sb + SC_DE + row*144 + s8*16, &g_de[(size_t)der*64 + s8*8]);
        }
    };

#pragma unroll
    for (int rep=0;rep<8;rep++){
        int idx = rep*256 + tid;
        int mat = idx >> 10, rem = idx & 1023;
        int row = rem >> 3, s8 = rem & 7;
        u32 dst = sb + mat*18432 + row*144 + s8*16;
        const hf* srcp =
            (mat==0) ? &qq[(size_t)(l0+row)*64 + s8*8]
                     : &kk[(size_t)(r0+row)*64 + s8*8];
        CP16(dst, srcp);
    }
    CP_COMMIT();
    load_de(0); CP_COMMIT();

    float acc[4][4][4];
#pragma unroll
    for (int i=0;i<4;i++)
#pragma unroll
        for (int j=0;j<4;j++)
#pragma unroll
            for (int c=0;c<4;c++) acc[i][j][c]=0.f;

    CP_WAIT(1);
    __syncthreads();

    // ---- phase 1: qk^T (x1) ----
#pragma unroll
    for (int kb=0;kb<64;kb+=16){
        u32 ah[4][4], bb[4][2];
#pragma unroll
        for (int mt=0;mt<4;mt++){
            u32 ra = sb + SC_Q + ((warpM*64+mt*16+lr)*72 + kb + lc8)*2;
            ldsm4(ah[mt][0],ah[mt][1],ah[mt][2],ah[mt][3], ra);
        }
#pragma unroll
        for (int gg=0;gg<2;gg++){
            u32 rb = sb + SC_K + ((warpN*32+gg*16+lr)*72 + kb + lc8)*2;
            u32 r0r,r1r,r2r,r3r;
            ldsm4(r0r,r1r,r2r,r3r, rb);
            bb[2*gg][0]=r0r; bb[2*gg][1]=r2r; bb[2*gg+1][0]=r1r; bb[2*gg+1][1]=r3r;
        }
#pragma unroll
        for (int mt=0;mt<4;mt++)
#pragma unroll
            for (int nt=0;nt<4;nt++)
                mma16816(acc[mt][nt], ah[mt], bb[nt][0], bb[nt][1]);
    }

    // ---- phase 2: pe via T = Q DE^T, 4 prefetched chunks; sT overlays K ----
    for (int c=0;c<4;c++){
        int t0c = 64*c;
        float Tacc[4][2][4];
#pragma unroll
        for (int i=0;i<4;i++)
#pragma unroll
            for (int j=0;j<2;j++)
#pragma unroll
                for (int q=0;q<4;q++) Tacc[i][j][q]=0.f;

        CP_WAIT(0);
        __syncthreads();
#pragma unroll
        for (int kb=0;kb<64;kb+=16){
            u32 ah[4][4];
#pragma unroll
            for (int mt=0;mt<4;mt++)
                ldsm4(ah[mt][0],ah[mt][1],ah[mt][2],ah[mt][3],
                      sb + SC_Q + ((warpM*64+mt*16+lr)*72 + kb + lc8)*2);
            u32 r0r,r1r,r2r,r3r;
            ldsm4(r0r,r1r,r2r,r3r, sb + SC_DE + ((warpN*16+lr)*72 + kb + lc8)*2);
#pragma unroll
            for (int mt=0;mt<4;mt++){
                mma16816(Tacc[mt][0], ah[mt], r0r, r2r);
                mma16816(Tacc[mt][1], ah[mt], r1r, r3r);
            }
        }
        __syncthreads();
        if (c < 3) { load_de(c+1); CP_COMMIT(); }

#pragma unroll
        for (int mt=0;mt<4;mt++)
#pragma unroll
            for (int n2=0;n2<2;n2++){
                int col = warpN*16 + n2*8 + 2*t;
                int rw = warpM*64 + mt*16 + g;
                *(float2*)&sT[rw*66 + col]     = make_float2(Tacc[mt][n2][0], Tacc[mt][n2][1]);
                *(float2*)&sT[(rw+8)*66 + col] = make_float2(Tacc[mt][n2][2], Tacc[mt][n2][3]);
            }
        __syncthreads();
#pragma unroll
        for (int mt=0;mt<4;mt++){
            int ib = warpM*64 + mt*16 + g;
#pragma unroll
            for (int nt=0;nt<4;nt++){
                int jb0 = warpN*32 + nt*8 + 2*t;
#pragma unroll
                for (int cr=0;cr<4;cr++){
                    int i = ib + (cr>>1)*8, j = jb0 + (cr&1);
                    int tt = i - j + 127 - t0c;
                    if ((unsigned)tt < 64u) acc[mt][nt][cr] += sT[i*66 + tt];
                }
            }
        }
        __syncthreads();
    }

    hf* outp = g_sc + (size_t)bh*SS*SS;
#pragma unroll
    for (int mt=0;mt<4;mt++){
        int i0 = l0 + warpM*64 + mt*16 + g;
#pragma unroll
        for (int nt=0;nt<4;nt++){
            int jc = r0 + warpN*32 + nt*8 + 2*t;
            float2 mk = *(const float2*)&mask[b_*SS + jc];
            *(u32*)&outp[(size_t)i0*SS + jc] =
                pack2h(fmaf(acc[mt][nt][0],0.125f,mk.x), fmaf(acc[mt][nt][1],0.125f,mk.y));
            *(u32*)&outp[(size_t)(i0+8)*SS + jc] =
                pack2h(fmaf(acc[mt][nt][2],0.125f,mk.x), fmaf(acc[mt][nt][3],0.125f,mk.y));
        }
    }
}

// ============================================================================
// K3: FUSED softmax + PV. CTA = (bh, 32 l-rows), 2 CTAs/SM.
// smem: P 32 x 1032 halves (66048B, 2064B row stride) | V 2 x 18432B.
// Phase A: cp.async scores -> smem; warp-per-row double softmax in place.
// Phase B: out = P @ V with P from smem, V double-buffered.
// ============================================================================
#define FS_SMEM (66048 + 2*18432)
__device__ __forceinline__ float fast_neglog(float u)
{
    float up = u + 1e-10f;
    float d  = up - 1.0f;
    float p = d*(1.f + d*(-0.5f + d*(0.33333333f + d*(-0.25f + d*0.2f))));
    float lg = __logf(up);
    float l = (d > -0.03125f) ? p : lg;
    return 1e-10f - l;
}

__global__ __launch_bounds__(256, 2)
void softpv(const float* __restrict__ gum, float* __restrict__ out)
{
    extern __shared__ __align__(16) char smem[];
    hf* P = (hf*)smem;                     // 32 rows x 1032 halves
    const u32 sbP = sptr(smem);
    const u32 sbV = sbP + 66048;

    const int tid = threadIdx.x, wid = tid>>5, lane = tid&31;
    const int bh = blockIdx.y, l0 = blockIdx.x*32;
    const int b_ = bh>>4, h = bh&15;

    const hf* S = g_sc + (size_t)bh*SS*SS + (size_t)l0*SS;
    const hf* V = g_v + (size_t)bh*SS*HDD;

    auto load_v = [&](int st, int k0){
#pragma unroll
        for (int rep=0;rep<4;rep++){
            int idx = rep*256 + tid;
            int row = idx >> 3, s8 = idx & 7;
            CP16(sbV + st*18432 + row*144 + s8*16, &V[(size_t)(k0+row)*64 + s8*8]);
        }
    };

    // load scores 32x1024 (4096 x 16B transfers)
#pragma unroll
    for (int rep=0; rep<16; rep++){
        int idx = rep*256 + tid;
        int row = idx >> 7, c16 = idx & 127;
        CP16(sbP + row*2064 + c16*16, &S[(size_t)row*1024 + c16*8]);
    }
    CP_COMMIT();
    load_v(0, 0); CP_COMMIT();
    CP_WAIT(0);
    __syncthreads();

    // ---- phase A: double softmax, warp w owns rows w*4..w*4+3 ----
    for (int rr = 0; rr < 4; rr++) {
        int row = wid*4 + rr;
        const float* urow = gum + ((size_t)(bh*1024 + l0 + row))*1024;
        hf* prow = P + row*1032;

        float s[32], n[32];
#pragma unroll
        for (int j = 0; j < 8; j++) {
            uint2 sv = *(const uint2*)&prow[j*128 + lane*4];
            float2 f0 = __half22float2(*(__half2*)&sv.x);
            float2 f1 = __half22float2(*(__half2*)&sv.y);
            s[j*4+0]=f0.x; s[j*4+1]=f0.y; s[j*4+2]=f1.x; s[j*4+3]=f1.y;
            float4 u = *(const float4*)&urow[(j*32 + lane)*4];
            n[j*4+0] = fast_neglog(u.x);
            n[j*4+1] = fast_neglog(u.y);
            n[j*4+2] = fast_neglog(u.z);
            n[j*4+3] = fast_neglog(u.w);
        }
        float m = s[0];
#pragma unroll
        for (int i = 1; i < 32; i++) m = fmaxf(m, s[i]);
#pragma unroll
        for (int o = 16; o; o >>= 1) m = fmaxf(m, __shfl_xor_sync(0xffffffffu, m, o));

        float sm1 = 0.f;
#pragma unroll
        for (int i = 0; i < 32; i++) {
            s[i] = __expf(s[i] - m);
            n[i] = __fdividef(s[i], n[i]);
            sm1 += n[i];
        }
#pragma unroll
        for (int o = 16; o; o >>= 1) sm1 += __shfl_xor_sync(0xffffffffu, sm1, o);
        float inv1 = __fdividef(1.0f, sm1);

        float sm2 = 0.f;
#pragma unroll
        for (int i = 0; i < 32; i++) {
            n[i] = s[i] * __expf(fmaf(n[i], inv1, -1.0f));
            sm2 += n[i];
        }
#pragma unroll
        for (int o = 16; o; o >>= 1) sm2 += __shfl_xor_sync(0xffffffffu, sm2, o);
        float inv2 = __fdividef(1.0f, sm2);

#pragma unroll
        for (int j = 0; j < 8; j++) {
            float a = n[j*4+0]*inv2, b = n[j*4+1]*inv2;
            float c = n[j*4+2]*inv2, d = n[j*4+3]*inv2;
            *(uint2*)&prow[j*128 + lane*4] = make_uint2(pack2h(a,b), pack2h(c,d));
        }
    }
    __syncthreads();

    // ---- phase B: out(32x64) = P(32x1024) @ V(1024x64) ----
    const int warpM = wid>>2, warpN = wid&3;     // 2m x 4n, warp tile 16x16
    const int lr = lane&15, lc8 = (lane>>4)*8, g = lane>>2, t = lane&3;

    float acc[2][4];
#pragma unroll
    for (int i=0;i<2;i++)
#pragma unroll
        for (int c=0;c<4;c++) acc[i][c]=0.f;

    for (int c = 0; c < 8; c++) {
        if (c < 7) { load_v((c+1)&1, (c+1)*128); CP_COMMIT(); CP_WAIT(1); }
        else       { CP_WAIT(0); }
        __syncthreads();
        const u32 st = sbV + (c&1)*18432;
#pragma unroll
        for (int kb=0;kb<128;kb+=16){
            u32 ah[4];
            ldsm4(ah[0],ah[1],ah[2],ah[3],
                  sbP + (warpM*16+lr)*2064 + (c*128 + kb + lc8)*2);
            u32 r0,r1,r2,r3;
            ldsm4t(r0,r1,r2,r3, st + ((kb+lr)*72 + warpN*16 + lc8)*2);
            mma16816(acc[0], ah, r0, r1);
            mma16816(acc[1], ah, r2, r3);
        }
        __syncthreads();   // all reads of stage c done before it is overwritten
    }

#pragma unroll
    for (int nt=0; nt<2; nt++){
        int dcol = warpN*16 + nt*8 + 2*t;
#pragma unroll
        for (int rr=0; rr<2; rr++){
            int l = l0 + warpM*16 + g + rr*8;
            *(float2*)&out[((size_t)(b_*SS)+l)*1024 + h*64 + dcol] =
                make_float2(acc[nt][rr*2+0], acc[nt][rr*2+1]);
        }
    }
}

// ============================================================================
extern "C" void kernel_launch(void* const* d_in, const int* in_sizes, int n_in,
                              void* d_out, int out_size)
{
    const float* hidden = (const float*)d_in[0];
    const float* mask   = (const float*)d_in[1];
    const float* gum    = (const float*)d_in[2];
    const float* Wq     = (const float*)d_in[3];
    const float* bq     = (const float*)d_in[4];
    const float* Wk     = (const float*)d_in[5];
    const float* bk     = (const float*)d_in[6];
    const float* Wv     = (const float*)d_in[7];
    const float* bv     = (const float*)d_in[8];
    const float* de     = (const float*)d_in[9];
    float* out = (float*)d_out;

    static int configured = 0;
    if (!configured) {
        cudaFuncSetAttribute(qkv_mma,    cudaFuncAttributeMaxDynamicSharedMemorySize, QKV_SMEM);
        cudaFuncSetAttribute(scores_mma, cudaFuncAttributeMaxDynamicSharedMemorySize, SC_SMEM);
        cudaFuncSetAttribute(softpv,     cudaFuncAttributeMaxDynamicSharedMemorySize, FS_SMEM);
        configured = 1;
    }

    cvt_kernel<<<5249, 256>>>(hidden, Wq, Wk, Wv, de);
    qkv_mma<<<dim3(8, 16, 3), 256, QKV_SMEM>>>(bq, bk, bv);
    scores_mma<<<dim3(8, 8, 32), 256, SC_SMEM>>>(mask);
    softpv<<<dim3(32, 32), 256, FS_SMEM>>>(gum, out);
}